// round 1
// baseline (speedup 1.0000x reference)
#include <cuda_runtime.h>
#include <math.h>

#define L_    2048
#define HID_  1024
#define H_    16
#define DH_   64
#define QS_   1024
#define T3_   3072
#define EPS_  1.1920929e-07f

// ---------------- scratch (device globals; no allocation allowed) ----------------
__device__ float g_qkv[L_ * T3_];          // (L, 3072)
__device__ float g_q[H_ * L_ * DH_];       // (H, L, DH)
__device__ float g_k[H_ * L_ * DH_];
__device__ float g_v[H_ * L_ * DH_];       // pre-scaled by dt
__device__ float g_dt[H_ * L_];
__device__ float g_Adec[H_ * L_];
__device__ float g_ca[H_ * L_];            // cumsum of A per head
__device__ float g_attn[L_ * QS_];         // (L, H*DH) post-RMSNorm

// ---------------- generic TN SGEMM: C[m,n] = sum_k A[m*K+k] * B[n*K+k] -----------
// BM=BN=128, BK=16, 256 threads, 8x8 per thread. M,N,K all multiples of 128/16.
template <int M, int N, int K>
__device__ __forceinline__ void sgemm_body(const float* __restrict__ A,
                                           const float* __restrict__ B,
                                           float* __restrict__ C)
{
    __shared__ __align__(16) float As[16 * 132];
    __shared__ __align__(16) float Bs[16 * 132];

    const int tid = threadIdx.x;
    const int tx = tid & 15;
    const int ty = tid >> 4;
    const int m0 = blockIdx.y * 128;
    const int n0 = blockIdx.x * 128;

    float acc[8][8];
#pragma unroll
    for (int i = 0; i < 8; i++)
#pragma unroll
        for (int j = 0; j < 8; j++) acc[i][j] = 0.f;

    for (int k0 = 0; k0 < K; k0 += 16) {
#pragma unroll
        for (int r = 0; r < 2; r++) {
            int vec = tid + 256 * r;        // 512 float4 per operand
            int row = vec >> 2;             // 0..127
            int kc  = (vec & 3) << 2;       // 0,4,8,12
            float4 a = *reinterpret_cast<const float4*>(&A[(size_t)(m0 + row) * K + k0 + kc]);
            As[(kc + 0) * 132 + row] = a.x;
            As[(kc + 1) * 132 + row] = a.y;
            As[(kc + 2) * 132 + row] = a.z;
            As[(kc + 3) * 132 + row] = a.w;
            float4 b = *reinterpret_cast<const float4*>(&B[(size_t)(n0 + row) * K + k0 + kc]);
            Bs[(kc + 0) * 132 + row] = b.x;
            Bs[(kc + 1) * 132 + row] = b.y;
            Bs[(kc + 2) * 132 + row] = b.z;
            Bs[(kc + 3) * 132 + row] = b.w;
        }
        __syncthreads();
#pragma unroll
        for (int k = 0; k < 16; k++) {
            float af[8], bf[8];
            *reinterpret_cast<float4*>(&af[0]) = *reinterpret_cast<const float4*>(&As[k * 132 + ty * 8]);
            *reinterpret_cast<float4*>(&af[4]) = *reinterpret_cast<const float4*>(&As[k * 132 + ty * 8 + 4]);
            *reinterpret_cast<float4*>(&bf[0]) = *reinterpret_cast<const float4*>(&Bs[k * 132 + tx * 8]);
            *reinterpret_cast<float4*>(&bf[4]) = *reinterpret_cast<const float4*>(&Bs[k * 132 + tx * 8 + 4]);
#pragma unroll
            for (int i = 0; i < 8; i++)
#pragma unroll
                for (int j = 0; j < 8; j++)
                    acc[i][j] = fmaf(af[i], bf[j], acc[i][j]);
        }
        __syncthreads();
    }

#pragma unroll
    for (int i = 0; i < 8; i++) {
        float* cp = &C[(size_t)(m0 + ty * 8 + i) * N + n0 + tx * 8];
        *reinterpret_cast<float4*>(cp)     = make_float4(acc[i][0], acc[i][1], acc[i][2], acc[i][3]);
        *reinterpret_cast<float4*>(cp + 4) = make_float4(acc[i][4], acc[i][5], acc[i][6], acc[i][7]);
    }
}

__global__ __launch_bounds__(256) void sgemm_qkv_kernel(const float* __restrict__ X,
                                                        const float* __restrict__ W)
{
    sgemm_body<L_, T3_, HID_>(X, W, g_qkv);
}

__global__ __launch_bounds__(256) void sgemm_o_kernel(const float* __restrict__ W,
                                                      float* __restrict__ out)
{
    sgemm_body<L_, HID_, QS_>(g_attn, W, out);
}

// ---------------- dt = softplus(X @ Wdt^T + b + dt_bias); A = -exp(A_log)*dt -----
__global__ __launch_bounds__(512) void dt_kernel(const float* __restrict__ X,
                                                 const float* __restrict__ W,
                                                 const float* __restrict__ b,
                                                 const float* __restrict__ dt_bias,
                                                 const float* __restrict__ A_log)
{
    const int l = blockIdx.x;
    const int warp = threadIdx.x >> 5;   // head
    const int lane = threadIdx.x & 31;
    const float* x = X + (size_t)l * HID_;
    const float* w = W + (size_t)warp * HID_;
    float s = 0.f;
#pragma unroll 8
    for (int k = lane; k < HID_; k += 32) s = fmaf(x[k], w[k], s);
#pragma unroll
    for (int o = 16; o; o >>= 1) s += __shfl_xor_sync(0xffffffffu, s, o);
    if (lane == 0) {
        float xv = s + b[warp] + dt_bias[warp];
        float dt = (xv > 20.f) ? xv : log1pf(expf(xv));
        g_dt[warp * L_ + l]   = dt;
        g_Adec[warp * L_ + l] = -expf(A_log[warp]) * dt;
    }
}

// ---------------- per-head inclusive cumsum over L -------------------------------
__global__ __launch_bounds__(256) void cumsum_kernel()
{
    const int h = blockIdx.x;
    __shared__ float wsum[8];
    __shared__ float carry_s;
    const int tid = threadIdx.x, lane = tid & 31, warp = tid >> 5;
    if (tid == 0) carry_s = 0.f;
    __syncthreads();
    for (int base = 0; base < L_; base += 256) {
        float x = g_Adec[h * L_ + base + tid];
#pragma unroll
        for (int o = 1; o < 32; o <<= 1) {
            float t = __shfl_up_sync(0xffffffffu, x, o);
            if (lane >= o) x += t;
        }
        if (lane == 31) wsum[warp] = x;
        __syncthreads();
        if (tid < 8) {
            float w = wsum[tid];
#pragma unroll
            for (int o = 1; o < 8; o <<= 1) {
                float t = __shfl_up_sync(0xffu, w, o);
                if (tid >= o) w += t;
            }
            wsum[tid] = w;
        }
        __syncthreads();
        float pre = (warp > 0 ? wsum[warp - 1] : 0.f) + carry_s;
        float outv = x + pre;
        g_ca[h * L_ + base + tid] = outv;
        __syncthreads();
        if (tid == 255) carry_s = outv;
        __syncthreads();
    }
}

// ---------------- causal depthwise conv (K=2) + head split + v*dt ----------------
__global__ __launch_bounds__(256) void conv_kernel(const float* __restrict__ qcw,
                                                   const float* __restrict__ qcb,
                                                   const float* __restrict__ kcw,
                                                   const float* __restrict__ kcb,
                                                   const float* __restrict__ vcw,
                                                   const float* __restrict__ vcb)
{
    const int idx = blockIdx.x * 256 + threadIdx.x;   // L_*QS_ total
    const int l = idx >> 10;
    const int c = idx & 1023;
    const int h = c >> 6;
    const int d = c & 63;
    const float* row  = g_qkv + (size_t)l * T3_;
    const float* prow = g_qkv + (size_t)(l - 1) * T3_;
    const bool hasp = (l > 0);
    float qc = row[c];            float qp = hasp ? prow[c] : 0.f;
    float kc = row[QS_ + c];      float kp = hasp ? prow[QS_ + c] : 0.f;
    float vc = row[2 * QS_ + c];  float vp = hasp ? prow[2 * QS_ + c] : 0.f;
    float qv = fmaf(qc, qcw[2 * c + 1], fmaf(qp, qcw[2 * c], qcb[c]));
    float kv = fmaf(kc, kcw[2 * c + 1], fmaf(kp, kcw[2 * c], kcb[c]));
    float vv = fmaf(vc, vcw[2 * c + 1], fmaf(vp, vcw[2 * c], vcb[c]));
    vv *= g_dt[h * L_ + l];
    const size_t o = ((size_t)h * L_ + l) * DH_ + d;
    g_q[o] = qv;
    g_k[o] = kv;
    g_v[o] = vv;
}

// ---------------- attention: per (head, 64-row tile), decay-pruned ---------------
// Shared: Qs (XOR-swizzled transposed), KSs (K transposed, later reused for S),
//         Vs (natural). Exactly 48KB static.
// Swizzle: element (d, i) lives at d*64 + (i ^ d). Then a float4 at
// d*64 + ((base) ^ (d & 60)) holds logical elements base+0..3 permuted by (d&3).
__global__ __launch_bounds__(256) void attn_kernel(const float* __restrict__ norm_w,
                                                   const float* __restrict__ order_coeff)
{
    __shared__ __align__(16) float Qs[4096];
    __shared__ __align__(16) float KSs[4096];
    __shared__ __align__(16) float Vs[4096];

    const int h  = blockIdx.y;
    const int lt = blockIdx.x;
    const int l0 = lt * 64;
    const int tid = threadIdx.x;
    const int tx = tid & 15;
    const int ty = tid >> 4;

    const float* qh = g_q + (size_t)h * L_ * DH_;
    const float* kh = g_k + (size_t)h * L_ * DH_;
    const float* vh = g_v + (size_t)h * L_ * DH_;
    const float* ca = g_ca + h * L_;
    const float inv_oc = 1.f / order_coeff[h];

    for (int e = tid; e < 4096; e += 256) {
        int i = e >> 6, d = e & 63;
        Qs[d * 64 + (i ^ d)] = qh[(size_t)(l0 + i) * DH_ + d];
    }
    float caL[4];
#pragma unroll
    for (int ii = 0; ii < 4; ii++) caL[ii] = ca[l0 + ty * 4 + ii];
    const float ca_top = ca[l0];

    float accO[4][4];
#pragma unroll
    for (int ii = 0; ii < 4; ii++)
#pragma unroll
        for (int jj = 0; jj < 4; jj++) accO[ii][jj] = 0.f;
    __syncthreads();

    for (int mt = lt; mt >= 0; mt--) {
        const int m0 = mt * 64;
        // decay prune: max weight in tile (and all earlier tiles) below fp32 noise
        if (mt < lt && (ca_top - ca[m0 + 63]) < -45.f) break;

        for (int e = tid; e < 4096; e += 256) {
            int j = e >> 6, d = e & 63;
            KSs[d * 64 + (j ^ d)] = kh[(size_t)(m0 + j) * DH_ + d];
            Vs[j * 64 + d]        = vh[(size_t)(m0 + j) * DH_ + d];
        }
        float caM[4];
#pragma unroll
        for (int jj = 0; jj < 4; jj++) caM[jj] = ca[m0 + tx * 4 + jj];
        __syncthreads();

        // S = Q K^T  (over d)
        float s[4][4];
#pragma unroll
        for (int ii = 0; ii < 4; ii++)
#pragma unroll
            for (int jj = 0; jj < 4; jj++) s[ii][jj] = 0.f;

        for (int d0 = 0; d0 < 64; d0 += 4) {
            const float* qa = &Qs[d0 * 64 + ((ty * 4) ^ d0)];
            const float* kb = &KSs[d0 * 64 + ((tx * 4) ^ d0)];
#pragma unroll
            for (int u = 0; u < 4; u++) {
                float4 av = *reinterpret_cast<const float4*>(qa + u * 64);
                float4 bv = *reinterpret_cast<const float4*>(kb + u * 64);
                const float a[4] = {av.x, av.y, av.z, av.w};
                const float b[4] = {bv.x, bv.y, bv.z, bv.w};
#pragma unroll
                for (int ii = 0; ii < 4; ii++)
#pragma unroll
                    for (int jj = 0; jj < 4; jj++)
                        s[ii][jj] = fmaf(a[ii ^ u], b[jj ^ u], s[ii][jj]);
            }
        }
        __syncthreads();   // done reading K; reuse KSs for S

        // apply decay weight + causal mask, store S transposed [m][i] (swizzled)
#pragma unroll
        for (int jj = 0; jj < 4; jj++) {
            const int m  = tx * 4 + jj;
            const int gm = m0 + m;
#pragma unroll
            for (int ii = 0; ii < 4; ii++) {
                const int gl = l0 + ty * 4 + ii;
                float wgt = (gm <= gl) ? __expf(caL[ii] - caM[jj]) * inv_oc : 0.f;
                KSs[m * 64 + ((ty * 4 + ii) ^ m)] = s[ii][jj] * wgt;
            }
        }
        __syncthreads();

        // O += S @ V  (over m)
        for (int mb = 0; mb < 64; mb += 4) {
            const float* sa = &KSs[mb * 64 + ((ty * 4) ^ mb)];
            const float* vb = &Vs[mb * 64 + tx * 4];
#pragma unroll
            for (int u = 0; u < 4; u++) {
                float4 av = *reinterpret_cast<const float4*>(sa + u * 64);
                float4 bv = *reinterpret_cast<const float4*>(vb + u * 64);
                const float a[4] = {av.x, av.y, av.z, av.w};
                const float b[4] = {bv.x, bv.y, bv.z, bv.w};
#pragma unroll
                for (int ii = 0; ii < 4; ii++)
#pragma unroll
                    for (int jj = 0; jj < 4; jj++)
                        accO[ii][jj] = fmaf(a[ii ^ u], b[jj], accO[ii][jj]);
            }
        }
        __syncthreads();
    }

    // RMSNorm over DH: row sums of squares via shuffle across the 16 tx lanes
    float p[4];
#pragma unroll
    for (int ii = 0; ii < 4; ii++) {
        float t = 0.f;
#pragma unroll
        for (int jj = 0; jj < 4; jj++) t = fmaf(accO[ii][jj], accO[ii][jj], t);
        p[ii] = t;
    }
#pragma unroll
    for (int o = 1; o < 16; o <<= 1)
#pragma unroll
        for (int ii = 0; ii < 4; ii++) p[ii] += __shfl_xor_sync(0xffffffffu, p[ii], o);

    if (tx == 0) {
#pragma unroll
        for (int ii = 0; ii < 4; ii++)
            Vs[ty * 4 + ii] = rsqrtf(p[ii] * (1.f / 64.f) + EPS_);   // Vs dead: reuse
    }
    __syncthreads();

    float nw[4];
#pragma unroll
    for (int jj = 0; jj < 4; jj++) nw[jj] = norm_w[tx * 4 + jj];
#pragma unroll
    for (int ii = 0; ii < 4; ii++) {
        const int i = ty * 4 + ii;
        const float r = Vs[i];
        float4 o4;
        o4.x = accO[ii][0] * r * nw[0];
        o4.y = accO[ii][1] * r * nw[1];
        o4.z = accO[ii][2] * r * nw[2];
        o4.w = accO[ii][3] * r * nw[3];
        *reinterpret_cast<float4*>(&g_attn[(size_t)(l0 + i) * QS_ + h * DH_ + tx * 4]) = o4;
    }
}

// ---------------- launch ---------------------------------------------------------
extern "C" void kernel_launch(void* const* d_in, const int* in_sizes, int n_in,
                              void* d_out, int out_size)
{
    const float* hidden    = (const float*)d_in[0];
    // d_in[1] = attention_mask (causal triu) — structurally known, unused
    const float* qkv_w     = (const float*)d_in[2];
    const float* q_conv_w  = (const float*)d_in[3];
    const float* q_conv_b  = (const float*)d_in[4];
    const float* k_conv_w  = (const float*)d_in[5];
    const float* k_conv_b  = (const float*)d_in[6];
    const float* v_conv_w  = (const float*)d_in[7];
    const float* v_conv_b  = (const float*)d_in[8];
    const float* norm_w    = (const float*)d_in[9];
    const float* A_log     = (const float*)d_in[10];
    const float* dt_bias   = (const float*)d_in[11];
    const float* dt_proj_w = (const float*)d_in[12];
    const float* dt_proj_b = (const float*)d_in[13];
    const float* o_w       = (const float*)d_in[14];
    const float* order_c   = (const float*)d_in[15];
    float* out = (float*)d_out;

    sgemm_qkv_kernel<<<dim3(T3_ / 128, L_ / 128), 256>>>(hidden, qkv_w);
    dt_kernel<<<L_, 512>>>(hidden, dt_proj_w, dt_proj_b, dt_bias, A_log);
    cumsum_kernel<<<H_, 256>>>();
    conv_kernel<<<(L_ * QS_) / 256, 256>>>(q_conv_w, q_conv_b, k_conv_w, k_conv_b,
                                           v_conv_w, v_conv_b);
    attn_kernel<<<dim3(L_ / 64, H_), 256>>>(norm_w, order_c);
    sgemm_o_kernel<<<dim3(HID_ / 128, L_ / 128), 256>>>(o_w, out);
}

// round 3
// speedup vs baseline: 1.5310x; 1.5310x over previous
#include <cuda_runtime.h>
#include <stdint.h>
#include <math.h>

#define L_    2048
#define HID_  1024
#define H_    16
#define DH_   64
#define QS_   1024
#define T3_   3072
#define EPS_  1.1920929e-07f

// ---------------- scratch (device globals; no allocation allowed) ----------------
__device__ float g_qkv[L_ * T3_];          // (L, 3072)
__device__ float g_q[H_ * L_ * DH_];       // (H, L, DH)
__device__ float g_k[H_ * L_ * DH_];
__device__ float g_v[H_ * L_ * DH_];       // pre-scaled by dt
__device__ float g_dt[H_ * L_];
__device__ float g_Adec[H_ * L_];
__device__ float g_ca[H_ * L_];            // cumsum of A per head
__device__ float g_attn[L_ * QS_];         // (L, H*DH) post-RMSNorm

// =================================================================================
// TN GEMM on tensor pipe: C[m,n] = sum_k A[m*K+k] * B[n*K+k], tf32 mma.sync
// CTA tile 128x128, K-step 16, 256 threads = 8 warps (4m x 2n), warp tile 32x64.
// Smem row stride 20 floats -> bank = 4*(5r mod 8) + c : conflict-free frag loads.
// =================================================================================

#define MMA_TF32(D, Ar, Br)                                                        \
    asm volatile("mma.sync.aligned.m16n8k8.row.col.f32.tf32.tf32.f32 "             \
                 "{%0,%1,%2,%3}, {%4,%5,%6,%7}, {%8,%9}, {%0,%1,%2,%3};"           \
                 : "+f"((D)[0]), "+f"((D)[1]), "+f"((D)[2]), "+f"((D)[3])          \
                 : "r"((Ar)[0]), "r"((Ar)[1]), "r"((Ar)[2]), "r"((Ar)[3]),         \
                   "r"((Br)[0]), "r"((Br)[1]))

__device__ __forceinline__ uint32_t f2tf32(float x) {
    uint32_t u;
    asm("cvt.rna.tf32.f32 %0, %1;" : "=r"(u) : "f"(x));
    return u;
}

__device__ __forceinline__ void cvt_store(float* dst, int row, int cg, float4 x) {
    float4 y;
    y.x = __uint_as_float(f2tf32(x.x));
    y.y = __uint_as_float(f2tf32(x.y));
    y.z = __uint_as_float(f2tf32(x.z));
    y.w = __uint_as_float(f2tf32(x.w));
    *reinterpret_cast<float4*>(&dst[row * 20 + cg]) = y;   // 16B aligned: 20r+cg % 4 == 0
}

template <int M, int N, int K>
__device__ __forceinline__ void mma_gemm_body(const float* __restrict__ A,
                                              const float* __restrict__ B,
                                              float* __restrict__ C)
{
    __shared__ __align__(16) float As[2][128 * 20];
    __shared__ __align__(16) float Bs[2][128 * 20];

    const int tid  = threadIdx.x;
    const int lane = tid & 31;
    const int wid  = tid >> 5;
    const int g    = lane >> 2;       // groupID
    const int t4   = lane & 3;        // threadID in group
    const int m0   = blockIdx.y * 128;
    const int n0   = blockIdx.x * 128;
    const int wm   = (wid >> 1) * 32; // warp m offset (2 mtiles of 16)
    const int wn   = (wid & 1) * 64;  // warp n offset (8 ntiles of 8)

    // loader coords: 512 float4 per operand tile, 2 per thread
    const int r0 = tid >> 2,           c0 = (tid & 3) << 2;
    const int r1 = (tid + 256) >> 2,   c1 = ((tid + 256) & 3) << 2;

    float acc[2][8][4];
#pragma unroll
    for (int mt = 0; mt < 2; mt++)
#pragma unroll
        for (int nt = 0; nt < 8; nt++)
#pragma unroll
            for (int e = 0; e < 4; e++) acc[mt][nt][e] = 0.f;

    // prologue: fill buffer 0
    cvt_store(As[0], r0, c0, *reinterpret_cast<const float4*>(&A[(size_t)(m0 + r0) * K + c0]));
    cvt_store(As[0], r1, c1, *reinterpret_cast<const float4*>(&A[(size_t)(m0 + r1) * K + c1]));
    cvt_store(Bs[0], r0, c0, *reinterpret_cast<const float4*>(&B[(size_t)(n0 + r0) * K + c0]));
    cvt_store(Bs[0], r1, c1, *reinterpret_cast<const float4*>(&B[(size_t)(n0 + r1) * K + c1]));
    __syncthreads();

    int buf = 0;
    for (int k0 = 0; k0 < K; k0 += 16) {
        const bool has_next = (k0 + 16) < K;
        float4 pa0, pa1, pb0, pb1;
        if (has_next) {
            const int kn = k0 + 16;
            pa0 = *reinterpret_cast<const float4*>(&A[(size_t)(m0 + r0) * K + kn + c0]);
            pa1 = *reinterpret_cast<const float4*>(&A[(size_t)(m0 + r1) * K + kn + c1]);
            pb0 = *reinterpret_cast<const float4*>(&B[(size_t)(n0 + r0) * K + kn + c0]);
            pb1 = *reinterpret_cast<const float4*>(&B[(size_t)(n0 + r1) * K + kn + c1]);
        }

        const uint32_t* Au = reinterpret_cast<const uint32_t*>(As[buf]);
        const uint32_t* Bu = reinterpret_cast<const uint32_t*>(Bs[buf]);
#pragma unroll
        for (int ks = 0; ks < 16; ks += 8) {
            uint32_t a[2][4], b[8][2];
#pragma unroll
            for (int mt = 0; mt < 2; mt++) {
                const int r = wm + mt * 16 + g;
                a[mt][0] = Au[r * 20 + ks + t4];
                a[mt][1] = Au[(r + 8) * 20 + ks + t4];
                a[mt][2] = Au[r * 20 + ks + t4 + 4];
                a[mt][3] = Au[(r + 8) * 20 + ks + t4 + 4];
            }
#pragma unroll
            for (int nt = 0; nt < 8; nt++) {
                const int r = wn + nt * 8 + g;
                b[nt][0] = Bu[r * 20 + ks + t4];
                b[nt][1] = Bu[r * 20 + ks + t4 + 4];
            }
#pragma unroll
            for (int mt = 0; mt < 2; mt++)
#pragma unroll
                for (int nt = 0; nt < 8; nt++)
                    MMA_TF32(acc[mt][nt], a[mt], b[nt]);
        }

        if (has_next) {
            cvt_store(As[buf ^ 1], r0, c0, pa0);
            cvt_store(As[buf ^ 1], r1, c1, pa1);
            cvt_store(Bs[buf ^ 1], r0, c0, pb0);
            cvt_store(Bs[buf ^ 1], r1, c1, pb1);
            __syncthreads();
            buf ^= 1;
        }
    }

    // epilogue
#pragma unroll
    for (int mt = 0; mt < 2; mt++) {
#pragma unroll
        for (int nt = 0; nt < 8; nt++) {
            const int row = m0 + wm + mt * 16 + g;
            const int col = n0 + wn + nt * 8 + t4 * 2;
            *reinterpret_cast<float2*>(&C[(size_t)row * N + col]) =
                make_float2(acc[mt][nt][0], acc[mt][nt][1]);
            *reinterpret_cast<float2*>(&C[(size_t)(row + 8) * N + col]) =
                make_float2(acc[mt][nt][2], acc[mt][nt][3]);
        }
    }
}

__global__ __launch_bounds__(256) void mma_qkv_kernel(const float* __restrict__ X,
                                                      const float* __restrict__ W)
{
    mma_gemm_body<L_, T3_, HID_>(X, W, g_qkv);
}

__global__ __launch_bounds__(256) void mma_o_kernel(const float* __restrict__ W,
                                                    float* __restrict__ out)
{
    mma_gemm_body<L_, HID_, QS_>(g_attn, W, out);
}

// ---------------- dt = softplus(X @ Wdt^T + b + dt_bias); A = -exp(A_log)*dt -----
__global__ __launch_bounds__(512) void dt_kernel(const float* __restrict__ X,
                                                 const float* __restrict__ W,
                                                 const float* __restrict__ b,
                                                 const float* __restrict__ dt_bias,
                                                 const float* __restrict__ A_log)
{
    const int l = blockIdx.x;
    const int warp = threadIdx.x >> 5;   // head
    const int lane = threadIdx.x & 31;
    const float* x = X + (size_t)l * HID_;
    const float* w = W + (size_t)warp * HID_;
    float s = 0.f;
#pragma unroll 8
    for (int k = lane; k < HID_; k += 32) s = fmaf(x[k], w[k], s);
#pragma unroll
    for (int o = 16; o; o >>= 1) s += __shfl_xor_sync(0xffffffffu, s, o);
    if (lane == 0) {
        float xv = s + b[warp] + dt_bias[warp];
        float dt = (xv > 20.f) ? xv : log1pf(expf(xv));
        g_dt[warp * L_ + l]   = dt;
        g_Adec[warp * L_ + l] = -expf(A_log[warp]) * dt;
    }
}

// ---------------- per-head inclusive cumsum over L -------------------------------
__global__ __launch_bounds__(256) void cumsum_kernel()
{
    const int h = blockIdx.x;
    __shared__ float wsum[8];
    __shared__ float carry_s;
    const int tid = threadIdx.x, lane = tid & 31, warp = tid >> 5;
    if (tid == 0) carry_s = 0.f;
    __syncthreads();
    for (int base = 0; base < L_; base += 256) {
        float x = g_Adec[h * L_ + base + tid];
#pragma unroll
        for (int o = 1; o < 32; o <<= 1) {
            float t = __shfl_up_sync(0xffffffffu, x, o);
            if (lane >= o) x += t;
        }
        if (lane == 31) wsum[warp] = x;
        __syncthreads();
        if (tid < 8) {
            float w = wsum[tid];
#pragma unroll
            for (int o = 1; o < 8; o <<= 1) {
                float t = __shfl_up_sync(0xffu, w, o);
                if (tid >= o) w += t;
            }
            wsum[tid] = w;
        }
        __syncthreads();
        float pre = (warp > 0 ? wsum[warp - 1] : 0.f) + carry_s;
        float outv = x + pre;
        g_ca[h * L_ + base + tid] = outv;
        __syncthreads();
        if (tid == 255) carry_s = outv;
        __syncthreads();
    }
}

// ---------------- causal depthwise conv (K=2) + head split + v*dt ----------------
__global__ __launch_bounds__(256) void conv_kernel(const float* __restrict__ qcw,
                                                   const float* __restrict__ qcb,
                                                   const float* __restrict__ kcw,
                                                   const float* __restrict__ kcb,
                                                   const float* __restrict__ vcw,
                                                   const float* __restrict__ vcb)
{
    const int idx = blockIdx.x * 256 + threadIdx.x;   // L_*QS_ total
    const int l = idx >> 10;
    const int c = idx & 1023;
    const int h = c >> 6;
    const int d = c & 63;
    const float* row  = g_qkv + (size_t)l * T3_;
    const float* prow = g_qkv + (size_t)(l - 1) * T3_;
    const bool hasp = (l > 0);
    float qc = row[c];            float qp = hasp ? prow[c] : 0.f;
    float kc = row[QS_ + c];      float kp = hasp ? prow[QS_ + c] : 0.f;
    float vc = row[2 * QS_ + c];  float vp = hasp ? prow[2 * QS_ + c] : 0.f;
    float qv = fmaf(qc, qcw[2 * c + 1], fmaf(qp, qcw[2 * c], qcb[c]));
    float kv = fmaf(kc, kcw[2 * c + 1], fmaf(kp, kcw[2 * c], kcb[c]));
    float vv = fmaf(vc, vcw[2 * c + 1], fmaf(vp, vcw[2 * c], vcb[c]));
    vv *= g_dt[h * L_ + l];
    const size_t o = ((size_t)h * L_ + l) * DH_ + d;
    g_q[o] = qv;
    g_k[o] = kv;
    g_v[o] = vv;
}

// ---------------- attention: per (head, 64-row tile), decay-pruned ---------------
__global__ __launch_bounds__(256) void attn_kernel(const float* __restrict__ norm_w,
                                                   const float* __restrict__ order_coeff)
{
    __shared__ __align__(16) float Qs[4096];
    __shared__ __align__(16) float KSs[4096];
    __shared__ __align__(16) float Vs[4096];

    const int h  = blockIdx.y;
    const int lt = blockIdx.x;
    const int l0 = lt * 64;
    const int tid = threadIdx.x;
    const int tx = tid & 15;
    const int ty = tid >> 4;

    const float* qh = g_q + (size_t)h * L_ * DH_;
    const float* kh = g_k + (size_t)h * L_ * DH_;
    const float* vh = g_v + (size_t)h * L_ * DH_;
    const float* ca = g_ca + h * L_;
    const float inv_oc = 1.f / order_coeff[h];

    for (int e = tid; e < 4096; e += 256) {
        int i = e >> 6, d = e & 63;
        Qs[d * 64 + (i ^ d)] = qh[(size_t)(l0 + i) * DH_ + d];
    }
    float caL[4];
#pragma unroll
    for (int ii = 0; ii < 4; ii++) caL[ii] = ca[l0 + ty * 4 + ii];
    const float ca_top = ca[l0];

    float accO[4][4];
#pragma unroll
    for (int ii = 0; ii < 4; ii++)
#pragma unroll
        for (int jj = 0; jj < 4; jj++) accO[ii][jj] = 0.f;
    __syncthreads();

    for (int mt = lt; mt >= 0; mt--) {
        const int m0 = mt * 64;
        if (mt < lt && (ca_top - ca[m0 + 63]) < -45.f) break;

        for (int e = tid; e < 4096; e += 256) {
            int j = e >> 6, d = e & 63;
            KSs[d * 64 + (j ^ d)] = kh[(size_t)(m0 + j) * DH_ + d];
            Vs[j * 64 + d]        = vh[(size_t)(m0 + j) * DH_ + d];
        }
        float caM[4];
#pragma unroll
        for (int jj = 0; jj < 4; jj++) caM[jj] = ca[m0 + tx * 4 + jj];
        __syncthreads();

        float s[4][4];
#pragma unroll
        for (int ii = 0; ii < 4; ii++)
#pragma unroll
            for (int jj = 0; jj < 4; jj++) s[ii][jj] = 0.f;

        for (int d0 = 0; d0 < 64; d0 += 4) {
            const float* qa = &Qs[d0 * 64 + ((ty * 4) ^ d0)];
            const float* kb = &KSs[d0 * 64 + ((tx * 4) ^ d0)];
#pragma unroll
            for (int u = 0; u < 4; u++) {
                float4 av = *reinterpret_cast<const float4*>(qa + u * 64);
                float4 bv = *reinterpret_cast<const float4*>(kb + u * 64);
                const float a[4] = {av.x, av.y, av.z, av.w};
                const float b[4] = {bv.x, bv.y, bv.z, bv.w};
#pragma unroll
                for (int ii = 0; ii < 4; ii++)
#pragma unroll
                    for (int jj = 0; jj < 4; jj++)
                        s[ii][jj] = fmaf(a[ii ^ u], b[jj ^ u], s[ii][jj]);
            }
        }
        __syncthreads();   // done reading K; reuse KSs for S

#pragma unroll
        for (int jj = 0; jj < 4; jj++) {
            const int m  = tx * 4 + jj;
            const int gm = m0 + m;
#pragma unroll
            for (int ii = 0; ii < 4; ii++) {
                const int gl = l0 + ty * 4 + ii;
                float wgt = (gm <= gl) ? __expf(caL[ii] - caM[jj]) * inv_oc : 0.f;
                KSs[m * 64 + ((ty * 4 + ii) ^ m)] = s[ii][jj] * wgt;
            }
        }
        __syncthreads();

        for (int mb = 0; mb < 64; mb += 4) {
            const float* sa = &KSs[mb * 64 + ((ty * 4) ^ mb)];
            const float* vb = &Vs[mb * 64 + tx * 4];
#pragma unroll
            for (int u = 0; u < 4; u++) {
                float4 av = *reinterpret_cast<const float4*>(sa + u * 64);
                float4 bv = *reinterpret_cast<const float4*>(vb + u * 64);
                const float a[4] = {av.x, av.y, av.z, av.w};
                const float b[4] = {bv.x, bv.y, bv.z, bv.w};
#pragma unroll
                for (int ii = 0; ii < 4; ii++)
#pragma unroll
                    for (int jj = 0; jj < 4; jj++)
                        accO[ii][jj] = fmaf(a[ii ^ u], b[jj], accO[ii][jj]);
            }
        }
        __syncthreads();
    }

    float p[4];
#pragma unroll
    for (int ii = 0; ii < 4; ii++) {
        float t = 0.f;
#pragma unroll
        for (int jj = 0; jj < 4; jj++) t = fmaf(accO[ii][jj], accO[ii][jj], t);
        p[ii] = t;
    }
#pragma unroll
    for (int o = 1; o < 16; o <<= 1)
#pragma unroll
        for (int ii = 0; ii < 4; ii++) p[ii] += __shfl_xor_sync(0xffffffffu, p[ii], o);

    if (tx == 0) {
#pragma unroll
        for (int ii = 0; ii < 4; ii++)
            Vs[ty * 4 + ii] = rsqrtf(p[ii] * (1.f / 64.f) + EPS_);
    }
    __syncthreads();

    float nw[4];
#pragma unroll
    for (int jj = 0; jj < 4; jj++) nw[jj] = norm_w[tx * 4 + jj];
#pragma unroll
    for (int ii = 0; ii < 4; ii++) {
        const int i = ty * 4 + ii;
        const float r = Vs[i];
        float4 o4;
        o4.x = accO[ii][0] * r * nw[0];
        o4.y = accO[ii][1] * r * nw[1];
        o4.z = accO[ii][2] * r * nw[2];
        o4.w = accO[ii][3] * r * nw[3];
        *reinterpret_cast<float4*>(&g_attn[(size_t)(l0 + i) * QS_ + h * DH_ + tx * 4]) = o4;
    }
}

// ---------------- launch ---------------------------------------------------------
extern "C" void kernel_launch(void* const* d_in, const int* in_sizes, int n_in,
                              void* d_out, int out_size)
{
    const float* hidden    = (const float*)d_in[0];
    // d_in[1] = attention_mask (causal triu) — structurally known, unused
    const float* qkv_w     = (const float*)d_in[2];
    const float* q_conv_w  = (const float*)d_in[3];
    const float* q_conv_b  = (const float*)d_in[4];
    const float* k_conv_w  = (const float*)d_in[5];
    const float* k_conv_b  = (const float*)d_in[6];
    const float* v_conv_w  = (const float*)d_in[7];
    const float* v_conv_b  = (const float*)d_in[8];
    const float* norm_w    = (const float*)d_in[9];
    const float* A_log     = (const float*)d_in[10];
    const float* dt_bias   = (const float*)d_in[11];
    const float* dt_proj_w = (const float*)d_in[12];
    const float* dt_proj_b = (const float*)d_in[13];
    const float* o_w       = (const float*)d_in[14];
    const float* order_c   = (const float*)d_in[15];
    float* out = (float*)d_out;

    mma_qkv_kernel<<<dim3(T3_ / 128, L_ / 128), 256>>>(hidden, qkv_w);
    dt_kernel<<<L_, 512>>>(hidden, dt_proj_w, dt_proj_b, dt_bias, A_log);
    cumsum_kernel<<<H_, 256>>>();
    conv_kernel<<<(L_ * QS_) / 256, 256>>>(q_conv_w, q_conv_b, k_conv_w, k_conv_b,
                                           v_conv_w, v_conv_b);
    attn_kernel<<<dim3(L_ / 64, H_), 256>>>(norm_w, order_c);
    mma_o_kernel<<<dim3(HID_ / 128, L_ / 128), 256>>>(o_w, out);
}

// round 4
// speedup vs baseline: 2.1511x; 1.4050x over previous
#include <cuda_runtime.h>
#include <stdint.h>
#include <math.h>

#define L_    2048
#define HID_  1024
#define H_    16
#define DH_   64
#define QS_   1024
#define T3_   3072
#define EPS_  1.1920929e-07f

// ---------------- scratch (device globals; no allocation allowed) ----------------
__device__ float g_qkv[L_ * T3_];          // (L, 3072)
__device__ float g_q[H_ * L_ * DH_];       // (H, L, DH)
__device__ float g_k[H_ * L_ * DH_];
__device__ float g_v[H_ * L_ * DH_];       // pre-scaled by dt
__device__ float g_dt[H_ * L_];
__device__ float g_Adec[H_ * L_];
__device__ float g_ca[H_ * L_];            // cumsum of A per head
__device__ float g_attn[L_ * QS_];         // (L, H*DH) post-RMSNorm

// =================================================================================
// tf32 mma.sync helpers
// =================================================================================
#define MMA_TF32(D, Ar, Br)                                                        \
    asm volatile("mma.sync.aligned.m16n8k8.row.col.f32.tf32.tf32.f32 "             \
                 "{%0,%1,%2,%3}, {%4,%5,%6,%7}, {%8,%9}, {%0,%1,%2,%3};"           \
                 : "+f"((D)[0]), "+f"((D)[1]), "+f"((D)[2]), "+f"((D)[3])          \
                 : "r"((Ar)[0]), "r"((Ar)[1]), "r"((Ar)[2]), "r"((Ar)[3]),         \
                   "r"((Br)[0]), "r"((Br)[1]))

__device__ __forceinline__ uint32_t f2tf32(float x) {
    uint32_t u;
    asm("cvt.rna.tf32.f32 %0, %1;" : "=r"(u) : "f"(x));
    return u;
}
__device__ __forceinline__ float f2tf32f(float x) { return __uint_as_float(f2tf32(x)); }

template <int STRIDE>
__device__ __forceinline__ void cvt_store(float* dst, int row, int cg, float4 x) {
    float4 y;
    y.x = f2tf32f(x.x);
    y.y = f2tf32f(x.y);
    y.z = f2tf32f(x.z);
    y.w = f2tf32f(x.w);
    *reinterpret_cast<float4*>(&dst[row * STRIDE + cg]) = y;
}

// =================================================================================
// TN GEMM on tensor pipe: C[m,n] = sum_k A[m*K+k] * B[n*K+k], tf32 mma.sync
// CTA tile 128x128, K-step 16, 256 threads = 8 warps (4m x 2n), warp tile 32x64.
// =================================================================================
template <int M, int N, int K>
__device__ __forceinline__ void mma_gemm_body(const float* __restrict__ A,
                                              const float* __restrict__ B,
                                              float* __restrict__ C)
{
    __shared__ __align__(16) float As[2][128 * 20];
    __shared__ __align__(16) float Bs[2][128 * 20];

    const int tid  = threadIdx.x;
    const int lane = tid & 31;
    const int wid  = tid >> 5;
    const int g    = lane >> 2;
    const int t4   = lane & 3;
    const int m0   = blockIdx.y * 128;
    const int n0   = blockIdx.x * 128;
    const int wm   = (wid >> 1) * 32;
    const int wn   = (wid & 1) * 64;

    const int r0 = tid >> 2,           c0 = (tid & 3) << 2;
    const int r1 = (tid + 256) >> 2,   c1 = ((tid + 256) & 3) << 2;

    float acc[2][8][4];
#pragma unroll
    for (int mt = 0; mt < 2; mt++)
#pragma unroll
        for (int nt = 0; nt < 8; nt++)
#pragma unroll
            for (int e = 0; e < 4; e++) acc[mt][nt][e] = 0.f;

    cvt_store<20>(As[0], r0, c0, *reinterpret_cast<const float4*>(&A[(size_t)(m0 + r0) * K + c0]));
    cvt_store<20>(As[0], r1, c1, *reinterpret_cast<const float4*>(&A[(size_t)(m0 + r1) * K + c1]));
    cvt_store<20>(Bs[0], r0, c0, *reinterpret_cast<const float4*>(&B[(size_t)(n0 + r0) * K + c0]));
    cvt_store<20>(Bs[0], r1, c1, *reinterpret_cast<const float4*>(&B[(size_t)(n0 + r1) * K + c1]));
    __syncthreads();

    int buf = 0;
    for (int k0 = 0; k0 < K; k0 += 16) {
        const bool has_next = (k0 + 16) < K;
        float4 pa0, pa1, pb0, pb1;
        if (has_next) {
            const int kn = k0 + 16;
            pa0 = *reinterpret_cast<const float4*>(&A[(size_t)(m0 + r0) * K + kn + c0]);
            pa1 = *reinterpret_cast<const float4*>(&A[(size_t)(m0 + r1) * K + kn + c1]);
            pb0 = *reinterpret_cast<const float4*>(&B[(size_t)(n0 + r0) * K + kn + c0]);
            pb1 = *reinterpret_cast<const float4*>(&B[(size_t)(n0 + r1) * K + kn + c1]);
        }

        const uint32_t* Au = reinterpret_cast<const uint32_t*>(As[buf]);
        const uint32_t* Bu = reinterpret_cast<const uint32_t*>(Bs[buf]);
#pragma unroll
        for (int ks = 0; ks < 16; ks += 8) {
            uint32_t a[2][4], b[8][2];
#pragma unroll
            for (int mt = 0; mt < 2; mt++) {
                const int r = wm + mt * 16 + g;
                a[mt][0] = Au[r * 20 + ks + t4];
                a[mt][1] = Au[(r + 8) * 20 + ks + t4];
                a[mt][2] = Au[r * 20 + ks + t4 + 4];
                a[mt][3] = Au[(r + 8) * 20 + ks + t4 + 4];
            }
#pragma unroll
            for (int nt = 0; nt < 8; nt++) {
                const int r = wn + nt * 8 + g;
                b[nt][0] = Bu[r * 20 + ks + t4];
                b[nt][1] = Bu[r * 20 + ks + t4 + 4];
            }
#pragma unroll
            for (int mt = 0; mt < 2; mt++)
#pragma unroll
                for (int nt = 0; nt < 8; nt++)
                    MMA_TF32(acc[mt][nt], a[mt], b[nt]);
        }

        if (has_next) {
            cvt_store<20>(As[buf ^ 1], r0, c0, pa0);
            cvt_store<20>(As[buf ^ 1], r1, c1, pa1);
            cvt_store<20>(Bs[buf ^ 1], r0, c0, pb0);
            cvt_store<20>(Bs[buf ^ 1], r1, c1, pb1);
            __syncthreads();
            buf ^= 1;
        }
    }

#pragma unroll
    for (int mt = 0; mt < 2; mt++) {
#pragma unroll
        for (int nt = 0; nt < 8; nt++) {
            const int row = m0 + wm + mt * 16 + g;
            const int col = n0 + wn + nt * 8 + t4 * 2;
            *reinterpret_cast<float2*>(&C[(size_t)row * N + col]) =
                make_float2(acc[mt][nt][0], acc[mt][nt][1]);
            *reinterpret_cast<float2*>(&C[(size_t)(row + 8) * N + col]) =
                make_float2(acc[mt][nt][2], acc[mt][nt][3]);
        }
    }
}

__global__ __launch_bounds__(256) void mma_qkv_kernel(const float* __restrict__ X,
                                                      const float* __restrict__ W)
{
    mma_gemm_body<L_, T3_, HID_>(X, W, g_qkv);
}

__global__ __launch_bounds__(256) void mma_o_kernel(const float* __restrict__ W,
                                                    float* __restrict__ out)
{
    mma_gemm_body<L_, HID_, QS_>(g_attn, W, out);
}

// ---------------- dt = softplus(X @ Wdt^T + b + dt_bias); A = -exp(A_log)*dt -----
__global__ __launch_bounds__(512) void dt_kernel(const float* __restrict__ X,
                                                 const float* __restrict__ W,
                                                 const float* __restrict__ b,
                                                 const float* __restrict__ dt_bias,
                                                 const float* __restrict__ A_log)
{
    const int l = blockIdx.x;
    const int warp = threadIdx.x >> 5;
    const int lane = threadIdx.x & 31;
    const float* x = X + (size_t)l * HID_;
    const float* w = W + (size_t)warp * HID_;
    float s = 0.f;
#pragma unroll 8
    for (int k = lane; k < HID_; k += 32) s = fmaf(x[k], w[k], s);
#pragma unroll
    for (int o = 16; o; o >>= 1) s += __shfl_xor_sync(0xffffffffu, s, o);
    if (lane == 0) {
        float xv = s + b[warp] + dt_bias[warp];
        float dt = (xv > 20.f) ? xv : log1pf(expf(xv));
        g_dt[warp * L_ + l]   = dt;
        g_Adec[warp * L_ + l] = -expf(A_log[warp]) * dt;
    }
}

// ---------------- per-head inclusive cumsum over L -------------------------------
__global__ __launch_bounds__(256) void cumsum_kernel()
{
    const int h = blockIdx.x;
    __shared__ float wsum[8];
    __shared__ float carry_s;
    const int tid = threadIdx.x, lane = tid & 31, warp = tid >> 5;
    if (tid == 0) carry_s = 0.f;
    __syncthreads();
    for (int base = 0; base < L_; base += 256) {
        float x = g_Adec[h * L_ + base + tid];
#pragma unroll
        for (int o = 1; o < 32; o <<= 1) {
            float t = __shfl_up_sync(0xffffffffu, x, o);
            if (lane >= o) x += t;
        }
        if (lane == 31) wsum[warp] = x;
        __syncthreads();
        if (tid < 8) {
            float w = wsum[tid];
#pragma unroll
            for (int o = 1; o < 8; o <<= 1) {
                float t = __shfl_up_sync(0xffu, w, o);
                if (tid >= o) w += t;
            }
            wsum[tid] = w;
        }
        __syncthreads();
        float pre = (warp > 0 ? wsum[warp - 1] : 0.f) + carry_s;
        float outv = x + pre;
        g_ca[h * L_ + base + tid] = outv;
        __syncthreads();
        if (tid == 255) carry_s = outv;
        __syncthreads();
    }
}

// ---------------- causal depthwise conv (K=2) + head split + v*dt ----------------
__global__ __launch_bounds__(256) void conv_kernel(const float* __restrict__ qcw,
                                                   const float* __restrict__ qcb,
                                                   const float* __restrict__ kcw,
                                                   const float* __restrict__ kcb,
                                                   const float* __restrict__ vcw,
                                                   const float* __restrict__ vcb)
{
    const int idx = blockIdx.x * 256 + threadIdx.x;
    const int l = idx >> 10;
    const int c = idx & 1023;
    const int h = c >> 6;
    const int d = c & 63;
    const float* row  = g_qkv + (size_t)l * T3_;
    const float* prow = g_qkv + (size_t)(l - 1) * T3_;
    const bool hasp = (l > 0);
    float qc = row[c];            float qp = hasp ? prow[c] : 0.f;
    float kc = row[QS_ + c];      float kp = hasp ? prow[QS_ + c] : 0.f;
    float vc = row[2 * QS_ + c];  float vp = hasp ? prow[2 * QS_ + c] : 0.f;
    float qv = fmaf(qc, qcw[2 * c + 1], fmaf(qp, qcw[2 * c], qcb[c]));
    float kv = fmaf(kc, kcw[2 * c + 1], fmaf(kp, kcw[2 * c], kcb[c]));
    float vv = fmaf(vc, vcw[2 * c + 1], fmaf(vp, vcw[2 * c], vcb[c]));
    vv *= g_dt[h * L_ + l];
    const size_t o = ((size_t)h * L_ + l) * DH_ + d;
    g_q[o] = qv;
    g_k[o] = kv;
    g_v[o] = vv;
}

// =================================================================================
// attention on tensor pipe: per (head, 64-row l-tile), 4 warps (each owns 16 rows)
// S = Q K^T (tf32 mma) -> exp-decay weighting in registers -> O += S V (tf32 mma)
// Weighted S round-trips through the dead K smem region (warp-private, __syncwarp).
// =================================================================================
#define AT_NW 68    // padded row stride: bank = (4*row + col) % 32 -> conflict-free frags

__global__ __launch_bounds__(128) void attn_mma_kernel(const float* __restrict__ norm_w,
                                                       const float* __restrict__ order_coeff)
{
    __shared__ __align__(16) float KSs[64 * AT_NW];   // Q staging -> K chunk -> weighted S
    __shared__ __align__(16) float Vt[64 * AT_NW];    // V chunk transposed (d-major)

    const int h    = blockIdx.y;
    const int lt   = blockIdx.x;
    const int l0   = lt * 64;
    const int tid  = threadIdx.x;
    const int lane = tid & 31;
    const int w    = tid >> 5;      // warp 0..3
    const int g    = lane >> 2;     // group row
    const int t4   = lane & 3;      // thread-in-group
    const int wl   = w * 16;        // warp's l-row offset inside tile

    const float* qh = g_q + (size_t)h * L_ * DH_;
    const float* kh = g_k + (size_t)h * L_ * DH_;
    const float* vh = g_v + (size_t)h * L_ * DH_;
    const float* ca = g_ca + h * L_;
    const float lc  = __logf(1.f / order_coeff[h]);   // fold 1/order_coeff into exponent

    // ---- stage Q tile (tf32) into KSs, hoist per-warp A-fragments to registers ----
    for (int f = tid; f < 1024; f += 128) {
        int row = f >> 4, c4 = (f & 15) << 2;
        cvt_store<AT_NW>(KSs, row, c4,
            *reinterpret_cast<const float4*>(&qh[(size_t)(l0 + row) * DH_ + c4]));
    }
    __syncthreads();

    uint32_t qa[8][4];
    {
        const uint32_t* Qu = reinterpret_cast<const uint32_t*>(KSs);
#pragma unroll
        for (int ko = 0; ko < 8; ko++) {
            qa[ko][0] = Qu[(wl + g) * AT_NW + ko * 8 + t4];
            qa[ko][1] = Qu[(wl + g + 8) * AT_NW + ko * 8 + t4];
            qa[ko][2] = Qu[(wl + g) * AT_NW + ko * 8 + t4 + 4];
            qa[ko][3] = Qu[(wl + g + 8) * AT_NW + ko * 8 + t4 + 4];
        }
    }
    const float cl0 = ca[l0 + wl + g] + lc;
    const float cl1 = ca[l0 + wl + g + 8] + lc;
    const float ca_top = ca[l0];

    float accO[8][4];
#pragma unroll
    for (int nt = 0; nt < 8; nt++)
#pragma unroll
        for (int e = 0; e < 4; e++) accO[nt][e] = 0.f;

    for (int mt = lt; mt >= 0; mt--) {
        const int m0 = mt * 64;
        if (mt < lt && (ca_top - ca[m0 + 63]) < -45.f) break;

        __syncthreads();   // previous chunk's smem reads (and Q frag loads) complete

        // load K chunk (tf32) into KSs — coalesced, conflict-free float4 stores
        for (int f = tid; f < 1024; f += 128) {
            int row = f >> 4, c4 = (f & 15) << 2;
            cvt_store<AT_NW>(KSs, row, c4,
                *reinterpret_cast<const float4*>(&kh[(size_t)(m0 + row) * DH_ + c4]));
        }
        // load V chunk transposed into Vt: lane = m -> STS banks (const + m), conflict-free
        {
            const int d0 = w * 16;
            int m = lane;
#pragma unroll
            for (int half = 0; half < 2; half++, m += 32) {
#pragma unroll
                for (int i = 0; i < 4; i++) {
                    float4 x = *reinterpret_cast<const float4*>(
                        &vh[(size_t)(m0 + m) * DH_ + d0 + i * 4]);
                    Vt[(d0 + i * 4 + 0) * AT_NW + m] = f2tf32f(x.x);
                    Vt[(d0 + i * 4 + 1) * AT_NW + m] = f2tf32f(x.y);
                    Vt[(d0 + i * 4 + 2) * AT_NW + m] = f2tf32f(x.z);
                    Vt[(d0 + i * 4 + 3) * AT_NW + m] = f2tf32f(x.w);
                }
            }
        }
        __syncthreads();

        // ---- S-phase: sfr = Q(16x64) . K^T(64x64) ----
        float sfr[8][4];
#pragma unroll
        for (int nt = 0; nt < 8; nt++)
#pragma unroll
            for (int e = 0; e < 4; e++) sfr[nt][e] = 0.f;

        const uint32_t* Ku = reinterpret_cast<const uint32_t*>(KSs);
#pragma unroll
        for (int ko = 0; ko < 8; ko++) {
            uint32_t b[8][2];
#pragma unroll
            for (int nt = 0; nt < 8; nt++) {
                b[nt][0] = Ku[(nt * 8 + g) * AT_NW + ko * 8 + t4];
                b[nt][1] = Ku[(nt * 8 + g) * AT_NW + ko * 8 + t4 + 4];
            }
#pragma unroll
            for (int nt = 0; nt < 8; nt++)
                MMA_TF32(sfr[nt], qa[ko], b[nt]);
        }

        // ---- decay weighting + causal mask on C-fragments ----
        const bool diag = (mt == lt);
        const int gl0 = l0 + wl + g, gl1 = gl0 + 8;
#pragma unroll
        for (int nt = 0; nt < 8; nt++) {
            const int gm0 = m0 + nt * 8 + 2 * t4;
            const int gm1 = gm0 + 1;
            const float cm0 = ca[gm0], cm1 = ca[gm1];
            float w00 = (!diag || gm0 <= gl0) ? __expf(cl0 - cm0) : 0.f;
            float w01 = (!diag || gm1 <= gl0) ? __expf(cl0 - cm1) : 0.f;
            float w10 = (!diag || gm0 <= gl1) ? __expf(cl1 - cm0) : 0.f;
            float w11 = (!diag || gm1 <= gl1) ? __expf(cl1 - cm1) : 0.f;
            sfr[nt][0] *= w00;
            sfr[nt][1] *= w01;
            sfr[nt][2] *= w10;
            sfr[nt][3] *= w11;
        }
        __syncthreads();   // all warps done reading K from KSs

        // ---- store weighted S (tf32) into warp-private KSs rows ----
#pragma unroll
        for (int nt = 0; nt < 8; nt++) {
            const int cc = nt * 8 + 2 * t4;
            *reinterpret_cast<float2*>(&KSs[(wl + g) * AT_NW + cc]) =
                make_float2(f2tf32f(sfr[nt][0]), f2tf32f(sfr[nt][1]));
            *reinterpret_cast<float2*>(&KSs[(wl + g + 8) * AT_NW + cc]) =
                make_float2(f2tf32f(sfr[nt][2]), f2tf32f(sfr[nt][3]));
        }
        __syncwarp();

        // ---- O-phase: accO += S(16x64) . V(64x64) with V^T in smem ----
        const uint32_t* Su = reinterpret_cast<const uint32_t*>(KSs);
        const uint32_t* Vu = reinterpret_cast<const uint32_t*>(Vt);
#pragma unroll
        for (int ko = 0; ko < 8; ko++) {
            uint32_t a[4];
            a[0] = Su[(wl + g) * AT_NW + ko * 8 + t4];
            a[1] = Su[(wl + g + 8) * AT_NW + ko * 8 + t4];
            a[2] = Su[(wl + g) * AT_NW + ko * 8 + t4 + 4];
            a[3] = Su[(wl + g + 8) * AT_NW + ko * 8 + t4 + 4];
#pragma unroll
            for (int nt = 0; nt < 8; nt++) {
                uint32_t b[2];
                b[0] = Vu[(nt * 8 + g) * AT_NW + ko * 8 + t4];
                b[1] = Vu[(nt * 8 + g) * AT_NW + ko * 8 + t4 + 4];
                MMA_TF32(accO[nt], a, b);
            }
        }
    }

    // ---- fused RMSNorm epilogue on C-fragments ----
    float ss0 = 0.f, ss1 = 0.f;
#pragma unroll
    for (int nt = 0; nt < 8; nt++) {
        ss0 = fmaf(accO[nt][0], accO[nt][0], ss0);
        ss0 = fmaf(accO[nt][1], accO[nt][1], ss0);
        ss1 = fmaf(accO[nt][2], accO[nt][2], ss1);
        ss1 = fmaf(accO[nt][3], accO[nt][3], ss1);
    }
    ss0 += __shfl_xor_sync(0xffffffffu, ss0, 1);
    ss0 += __shfl_xor_sync(0xffffffffu, ss0, 2);
    ss1 += __shfl_xor_sync(0xffffffffu, ss1, 1);
    ss1 += __shfl_xor_sync(0xffffffffu, ss1, 2);
    const float r0 = rsqrtf(ss0 * (1.f / 64.f) + EPS_);
    const float r1 = rsqrtf(ss1 * (1.f / 64.f) + EPS_);

#pragma unroll
    for (int nt = 0; nt < 8; nt++) {
        const int dc = nt * 8 + 2 * t4;
        const float2 nw = *reinterpret_cast<const float2*>(&norm_w[dc]);
        const int col = h * DH_ + dc;
        *reinterpret_cast<float2*>(&g_attn[(size_t)(l0 + wl + g) * QS_ + col]) =
            make_float2(accO[nt][0] * r0 * nw.x, accO[nt][1] * r0 * nw.y);
        *reinterpret_cast<float2*>(&g_attn[(size_t)(l0 + wl + g + 8) * QS_ + col]) =
            make_float2(accO[nt][2] * r1 * nw.x, accO[nt][3] * r1 * nw.y);
    }
}

// ---------------- launch ---------------------------------------------------------
extern "C" void kernel_launch(void* const* d_in, const int* in_sizes, int n_in,
                              void* d_out, int out_size)
{
    const float* hidden    = (const float*)d_in[0];
    // d_in[1] = attention_mask (causal triu) — structurally known, unused
    const float* qkv_w     = (const float*)d_in[2];
    const float* q_conv_w  = (const float*)d_in[3];
    const float* q_conv_b  = (const float*)d_in[4];
    const float* k_conv_w  = (const float*)d_in[5];
    const float* k_conv_b  = (const float*)d_in[6];
    const float* v_conv_w  = (const float*)d_in[7];
    const float* v_conv_b  = (const float*)d_in[8];
    const float* norm_w    = (const float*)d_in[9];
    const float* A_log     = (const float*)d_in[10];
    const float* dt_bias   = (const float*)d_in[11];
    const float* dt_proj_w = (const float*)d_in[12];
    const float* dt_proj_b = (const float*)d_in[13];
    const float* o_w       = (const float*)d_in[14];
    const float* order_c   = (const float*)d_in[15];
    float* out = (float*)d_out;

    mma_qkv_kernel<<<dim3(T3_ / 128, L_ / 128), 256>>>(hidden, qkv_w);
    dt_kernel<<<L_, 512>>>(hidden, dt_proj_w, dt_proj_b, dt_bias, A_log);
    cumsum_kernel<<<H_, 256>>>();
    conv_kernel<<<(L_ * QS_) / 256, 256>>>(q_conv_w, q_conv_b, k_conv_w, k_conv_b,
                                           v_conv_w, v_conv_b);
    attn_mma_kernel<<<dim3(L_ / 64, H_), 128>>>(norm_w, order_c);
    mma_o_kernel<<<dim3(HID_ / 128, L_ / 128), 256>>>(o_w, out);
}

// round 5
// speedup vs baseline: 2.8017x; 1.3024x over previous
#include <cuda_runtime.h>
#include <stdint.h>
#include <math.h>

#define L_    2048
#define HID_  1024
#define H_    16
#define DH_   64
#define QS_   1024
#define T3_   3072
#define NCH_  32          // chunks of 64
#define EPS_  1.1920929e-07f

// ---------------- scratch (device globals; no allocation allowed) ----------------
__device__ float g_qkv[L_ * T3_];          // (L, 3072)
__device__ float g_q[H_ * L_ * DH_];       // (H, L, DH)
__device__ float g_k[H_ * L_ * DH_];
__device__ float g_v[H_ * L_ * DH_];       // pre-scaled by dt
__device__ float g_dt[H_ * L_];
__device__ float g_Adec[H_ * L_];
__device__ float g_ca[H_ * L_];            // cumsum of A per head
__device__ float g_attn[L_ * QS_];         // (L, H*DH) post-RMSNorm
__device__ float g_M[H_ * NCH_ * DH_ * DH_];      // per-chunk decayed outer products [e][d]
__device__ float g_state[H_ * NCH_ * DH_ * DH_];  // scanned states [e][d]

// =================================================================================
// tf32 mma.sync helpers
// =================================================================================
#define MMA_TF32(D, Ar, Br)                                                        \
    asm volatile("mma.sync.aligned.m16n8k8.row.col.f32.tf32.tf32.f32 "             \
                 "{%0,%1,%2,%3}, {%4,%5,%6,%7}, {%8,%9}, {%0,%1,%2,%3};"           \
                 : "+f"((D)[0]), "+f"((D)[1]), "+f"((D)[2]), "+f"((D)[3])          \
                 : "r"((Ar)[0]), "r"((Ar)[1]), "r"((Ar)[2]), "r"((Ar)[3]),         \
                   "r"((Br)[0]), "r"((Br)[1]))

__device__ __forceinline__ uint32_t f2tf32(float x) {
    uint32_t u;
    asm("cvt.rna.tf32.f32 %0, %1;" : "=r"(u) : "f"(x));
    return u;
}
__device__ __forceinline__ float f2tf32f(float x) { return __uint_as_float(f2tf32(x)); }

template <int STRIDE>
__device__ __forceinline__ void cvt_store(float* dst, int row, int cg, float4 x) {
    float4 y;
    y.x = f2tf32f(x.x);
    y.y = f2tf32f(x.y);
    y.z = f2tf32f(x.z);
    y.w = f2tf32f(x.w);
    *reinterpret_cast<float4*>(&dst[row * STRIDE + cg]) = y;
}

// =================================================================================
// TN GEMM on tensor pipe (unchanged from round 4)
// =================================================================================
template <int M, int N, int K>
__device__ __forceinline__ void mma_gemm_body(const float* __restrict__ A,
                                              const float* __restrict__ B,
                                              float* __restrict__ C)
{
    __shared__ __align__(16) float As[2][128 * 20];
    __shared__ __align__(16) float Bs[2][128 * 20];

    const int tid  = threadIdx.x;
    const int lane = tid & 31;
    const int wid  = tid >> 5;
    const int g    = lane >> 2;
    const int t4   = lane & 3;
    const int m0   = blockIdx.y * 128;
    const int n0   = blockIdx.x * 128;
    const int wm   = (wid >> 1) * 32;
    const int wn   = (wid & 1) * 64;

    const int r0 = tid >> 2,           c0 = (tid & 3) << 2;
    const int r1 = (tid + 256) >> 2,   c1 = ((tid + 256) & 3) << 2;

    float acc[2][8][4];
#pragma unroll
    for (int mt = 0; mt < 2; mt++)
#pragma unroll
        for (int nt = 0; nt < 8; nt++)
#pragma unroll
            for (int e = 0; e < 4; e++) acc[mt][nt][e] = 0.f;

    cvt_store<20>(As[0], r0, c0, *reinterpret_cast<const float4*>(&A[(size_t)(m0 + r0) * K + c0]));
    cvt_store<20>(As[0], r1, c1, *reinterpret_cast<const float4*>(&A[(size_t)(m0 + r1) * K + c1]));
    cvt_store<20>(Bs[0], r0, c0, *reinterpret_cast<const float4*>(&B[(size_t)(n0 + r0) * K + c0]));
    cvt_store<20>(Bs[0], r1, c1, *reinterpret_cast<const float4*>(&B[(size_t)(n0 + r1) * K + c1]));
    __syncthreads();

    int buf = 0;
    for (int k0 = 0; k0 < K; k0 += 16) {
        const bool has_next = (k0 + 16) < K;
        float4 pa0, pa1, pb0, pb1;
        if (has_next) {
            const int kn = k0 + 16;
            pa0 = *reinterpret_cast<const float4*>(&A[(size_t)(m0 + r0) * K + kn + c0]);
            pa1 = *reinterpret_cast<const float4*>(&A[(size_t)(m0 + r1) * K + kn + c1]);
            pb0 = *reinterpret_cast<const float4*>(&B[(size_t)(n0 + r0) * K + kn + c0]);
            pb1 = *reinterpret_cast<const float4*>(&B[(size_t)(n0 + r1) * K + kn + c1]);
        }

        const uint32_t* Au = reinterpret_cast<const uint32_t*>(As[buf]);
        const uint32_t* Bu = reinterpret_cast<const uint32_t*>(Bs[buf]);
#pragma unroll
        for (int ks = 0; ks < 16; ks += 8) {
            uint32_t a[2][4], b[8][2];
#pragma unroll
            for (int mt = 0; mt < 2; mt++) {
                const int r = wm + mt * 16 + g;
                a[mt][0] = Au[r * 20 + ks + t4];
                a[mt][1] = Au[(r + 8) * 20 + ks + t4];
                a[mt][2] = Au[r * 20 + ks + t4 + 4];
                a[mt][3] = Au[(r + 8) * 20 + ks + t4 + 4];
            }
#pragma unroll
            for (int nt = 0; nt < 8; nt++) {
                const int r = wn + nt * 8 + g;
                b[nt][0] = Bu[r * 20 + ks + t4];
                b[nt][1] = Bu[r * 20 + ks + t4 + 4];
            }
#pragma unroll
            for (int mt = 0; mt < 2; mt++)
#pragma unroll
                for (int nt = 0; nt < 8; nt++)
                    MMA_TF32(acc[mt][nt], a[mt], b[nt]);
        }

        if (has_next) {
            cvt_store<20>(As[buf ^ 1], r0, c0, pa0);
            cvt_store<20>(As[buf ^ 1], r1, c1, pa1);
            cvt_store<20>(Bs[buf ^ 1], r0, c0, pb0);
            cvt_store<20>(Bs[buf ^ 1], r1, c1, pb1);
            __syncthreads();
            buf ^= 1;
        }
    }

#pragma unroll
    for (int mt = 0; mt < 2; mt++) {
#pragma unroll
        for (int nt = 0; nt < 8; nt++) {
            const int row = m0 + wm + mt * 16 + g;
            const int col = n0 + wn + nt * 8 + t4 * 2;
            *reinterpret_cast<float2*>(&C[(size_t)row * N + col]) =
                make_float2(acc[mt][nt][0], acc[mt][nt][1]);
            *reinterpret_cast<float2*>(&C[(size_t)(row + 8) * N + col]) =
                make_float2(acc[mt][nt][2], acc[mt][nt][3]);
        }
    }
}

__global__ __launch_bounds__(256) void mma_qkv_kernel(const float* __restrict__ X,
                                                      const float* __restrict__ W)
{
    mma_gemm_body<L_, T3_, HID_>(X, W, g_qkv);
}

__global__ __launch_bounds__(256) void mma_o_kernel(const float* __restrict__ W,
                                                    float* __restrict__ out)
{
    mma_gemm_body<L_, HID_, QS_>(g_attn, W, out);
}

// ---------------- dt = softplus(X @ Wdt^T + b + dt_bias); A = -exp(A_log)*dt -----
__global__ __launch_bounds__(512) void dt_kernel(const float* __restrict__ X,
                                                 const float* __restrict__ W,
                                                 const float* __restrict__ b,
                                                 const float* __restrict__ dt_bias,
                                                 const float* __restrict__ A_log)
{
    const int l = blockIdx.x;
    const int warp = threadIdx.x >> 5;
    const int lane = threadIdx.x & 31;
    const float* x = X + (size_t)l * HID_;
    const float* w = W + (size_t)warp * HID_;
    float s = 0.f;
#pragma unroll 8
    for (int k = lane; k < HID_; k += 32) s = fmaf(x[k], w[k], s);
#pragma unroll
    for (int o = 16; o; o >>= 1) s += __shfl_xor_sync(0xffffffffu, s, o);
    if (lane == 0) {
        float xv = s + b[warp] + dt_bias[warp];
        float dt = (xv > 20.f) ? xv : log1pf(expf(xv));
        g_dt[warp * L_ + l]   = dt;
        g_Adec[warp * L_ + l] = -expf(A_log[warp]) * dt;
    }
}

// ---------------- per-head inclusive cumsum over L -------------------------------
__global__ __launch_bounds__(256) void cumsum_kernel()
{
    const int h = blockIdx.x;
    __shared__ float wsum[8];
    __shared__ float carry_s;
    const int tid = threadIdx.x, lane = tid & 31, warp = tid >> 5;
    if (tid == 0) carry_s = 0.f;
    __syncthreads();
    for (int base = 0; base < L_; base += 256) {
        float x = g_Adec[h * L_ + base + tid];
#pragma unroll
        for (int o = 1; o < 32; o <<= 1) {
            float t = __shfl_up_sync(0xffffffffu, x, o);
            if (lane >= o) x += t;
        }
        if (lane == 31) wsum[warp] = x;
        __syncthreads();
        if (tid < 8) {
            float w = wsum[tid];
#pragma unroll
            for (int o = 1; o < 8; o <<= 1) {
                float t = __shfl_up_sync(0xffu, w, o);
                if (tid >= o) w += t;
            }
            wsum[tid] = w;
        }
        __syncthreads();
        float pre = (warp > 0 ? wsum[warp - 1] : 0.f) + carry_s;
        float outv = x + pre;
        g_ca[h * L_ + base + tid] = outv;
        __syncthreads();
        if (tid == 255) carry_s = outv;
        __syncthreads();
    }
}

// ---------------- causal depthwise conv (K=2) + head split + v*dt ----------------
__global__ __launch_bounds__(256) void conv_kernel(const float* __restrict__ qcw,
                                                   const float* __restrict__ qcb,
                                                   const float* __restrict__ kcw,
                                                   const float* __restrict__ kcb,
                                                   const float* __restrict__ vcw,
                                                   const float* __restrict__ vcb)
{
    const int idx = blockIdx.x * 256 + threadIdx.x;
    const int l = idx >> 10;
    const int c = idx & 1023;
    const int h = c >> 6;
    const int d = c & 63;
    const float* row  = g_qkv + (size_t)l * T3_;
    const float* prow = g_qkv + (size_t)(l - 1) * T3_;
    const bool hasp = (l > 0);
    float qc = row[c];            float qp = hasp ? prow[c] : 0.f;
    float kc = row[QS_ + c];      float kp = hasp ? prow[QS_ + c] : 0.f;
    float vc = row[2 * QS_ + c];  float vp = hasp ? prow[2 * QS_ + c] : 0.f;
    float qv = fmaf(qc, qcw[2 * c + 1], fmaf(qp, qcw[2 * c], qcb[c]));
    float kv = fmaf(kc, kcw[2 * c + 1], fmaf(kp, kcw[2 * c], kcb[c]));
    float vv = fmaf(vc, vcw[2 * c + 1], fmaf(vp, vcw[2 * c], vcb[c]));
    vv *= g_dt[h * L_ + l];
    const size_t o = ((size_t)h * L_ + l) * DH_ + d;
    g_q[o] = qv;
    g_k[o] = kv;
    g_v[o] = vv;
}

// =================================================================================
// Chunked linear attention (exact factorization of the decay weights)
// =================================================================================
#define AT_NW 68

// ---- Phase A: per-chunk decayed outer product M'[e][d] = sum_m v[m,e]*k'[m,d] ----
// k'[m,d] = k[m,d] * exp(ca[(c+1)*64] - ca[m]).  grid (31, H), 128 threads.
__global__ __launch_bounds__(128) void kv_outer_kernel()
{
    __shared__ __align__(16) float Kt[64 * AT_NW];   // [d][m]
    __shared__ __align__(16) float Vt2[64 * AT_NW];  // [e][m]

    const int c = blockIdx.x, h = blockIdx.y;
    const int m0 = c * 64;
    const int tid = threadIdx.x, lane = tid & 31, w = tid >> 5;
    const int g = lane >> 2, t4 = lane & 3;
    const int wl = w * 16;
    const float* ca = g_ca + h * L_;
    const float* kh = g_k + (size_t)h * L_ * DH_;
    const float* vh = g_v + (size_t)h * L_ * DH_;
    const float bnext = ca[(c + 1) * 64];

    const int d0 = w * 16;
    int m = lane;
#pragma unroll
    for (int half = 0; half < 2; half++, m += 32) {
        const float wm = __expf(bnext - ca[m0 + m]);
#pragma unroll
        for (int i = 0; i < 4; i++) {
            float4 kx = *reinterpret_cast<const float4*>(&kh[(size_t)(m0 + m) * DH_ + d0 + i * 4]);
            Kt[(d0 + i * 4 + 0) * AT_NW + m] = f2tf32f(kx.x * wm);
            Kt[(d0 + i * 4 + 1) * AT_NW + m] = f2tf32f(kx.y * wm);
            Kt[(d0 + i * 4 + 2) * AT_NW + m] = f2tf32f(kx.z * wm);
            Kt[(d0 + i * 4 + 3) * AT_NW + m] = f2tf32f(kx.w * wm);
            float4 vx = *reinterpret_cast<const float4*>(&vh[(size_t)(m0 + m) * DH_ + d0 + i * 4]);
            Vt2[(d0 + i * 4 + 0) * AT_NW + m] = f2tf32f(vx.x);
            Vt2[(d0 + i * 4 + 1) * AT_NW + m] = f2tf32f(vx.y);
            Vt2[(d0 + i * 4 + 2) * AT_NW + m] = f2tf32f(vx.z);
            Vt2[(d0 + i * 4 + 3) * AT_NW + m] = f2tf32f(vx.w);
        }
    }
    __syncthreads();

    float acc[8][4];
#pragma unroll
    for (int nt = 0; nt < 8; nt++)
#pragma unroll
        for (int e = 0; e < 4; e++) acc[nt][e] = 0.f;

    const uint32_t* Vu = reinterpret_cast<const uint32_t*>(Vt2);
    const uint32_t* Ku = reinterpret_cast<const uint32_t*>(Kt);
#pragma unroll
    for (int ko = 0; ko < 8; ko++) {
        uint32_t a[4];
        a[0] = Vu[(wl + g) * AT_NW + ko * 8 + t4];
        a[1] = Vu[(wl + g + 8) * AT_NW + ko * 8 + t4];
        a[2] = Vu[(wl + g) * AT_NW + ko * 8 + t4 + 4];
        a[3] = Vu[(wl + g + 8) * AT_NW + ko * 8 + t4 + 4];
#pragma unroll
        for (int nt = 0; nt < 8; nt++) {
            uint32_t b[2];
            b[0] = Ku[(nt * 8 + g) * AT_NW + ko * 8 + t4];
            b[1] = Ku[(nt * 8 + g) * AT_NW + ko * 8 + t4 + 4];
            MMA_TF32(acc[nt], a, b);
        }
    }

    float* Md = g_M + ((size_t)(h * NCH_ + c) << 12);
#pragma unroll
    for (int nt = 0; nt < 8; nt++) {
        const int dc = nt * 8 + 2 * t4;
        *reinterpret_cast<float2*>(&Md[(wl + g) * 64 + dc])     = make_float2(acc[nt][0], acc[nt][1]);
        *reinterpret_cast<float2*>(&Md[(wl + g + 8) * 64 + dc]) = make_float2(acc[nt][2], acc[nt][3]);
    }
}

// ---- Phase B: per-head sequential state scan (fp32 exact). grid H, 256 thr ------
__global__ __launch_bounds__(256) void state_scan_kernel()
{
    const int h = blockIdx.x, t = threadIdx.x;
    const float* ca = g_ca + h * L_;
    float st[16];
#pragma unroll
    for (int j = 0; j < 16; j++) st[j] = 0.f;

    for (int c = 0; c < NCH_; c++) {
        float* Sd = g_state + ((size_t)(h * NCH_ + c) << 12);
#pragma unroll
        for (int j = 0; j < 16; j++) Sd[t + 256 * j] = st[j];
        if (c < NCH_ - 1) {
            const float dec = __expf(ca[(c + 1) * 64] - ca[c * 64]);
            const float* Md = g_M + ((size_t)(h * NCH_ + c) << 12);
#pragma unroll
            for (int j = 0; j < 16; j++) st[j] = fmaf(st[j], dec, Md[t + 256 * j]);
        }
    }
}

// ---- Phase C: diagonal tile (intra) + q.State (inter), fused RMSNorm ------------
__global__ __launch_bounds__(128) void attn_mma_kernel(const float* __restrict__ norm_w,
                                                       const float* __restrict__ order_coeff)
{
    __shared__ __align__(16) float KSs[64 * AT_NW];   // Q staging -> K -> weighted S
    __shared__ __align__(16) float Vt[64 * AT_NW];    // State' -> V^T

    const int h    = blockIdx.y;
    const int lt   = blockIdx.x;
    const int l0   = lt * 64;
    const int tid  = threadIdx.x;
    const int lane = tid & 31;
    const int w    = tid >> 5;
    const int g    = lane >> 2;
    const int t4   = lane & 3;
    const int wl   = w * 16;

    const float* qh = g_q + (size_t)h * L_ * DH_;
    const float* kh = g_k + (size_t)h * L_ * DH_;
    const float* vh = g_v + (size_t)h * L_ * DH_;
    const float* ca = g_ca + h * L_;
    const float lc  = __logf(1.f / order_coeff[h]);

    // stage Q (tf32) into KSs and State' into Vt
    const float* Sg = g_state + ((size_t)(h * NCH_ + lt) << 12);
    for (int f = tid; f < 1024; f += 128) {
        int row = f >> 4, c4 = (f & 15) << 2;
        cvt_store<AT_NW>(KSs, row, c4,
            *reinterpret_cast<const float4*>(&qh[(size_t)(l0 + row) * DH_ + c4]));
        cvt_store<AT_NW>(Vt, row, c4,
            *reinterpret_cast<const float4*>(&Sg[row * 64 + c4]));
    }
    __syncthreads();

    uint32_t qa[8][4];
    {
        const uint32_t* Qu = reinterpret_cast<const uint32_t*>(KSs);
#pragma unroll
        for (int ko = 0; ko < 8; ko++) {
            qa[ko][0] = Qu[(wl + g) * AT_NW + ko * 8 + t4];
            qa[ko][1] = Qu[(wl + g + 8) * AT_NW + ko * 8 + t4];
            qa[ko][2] = Qu[(wl + g) * AT_NW + ko * 8 + t4 + 4];
            qa[ko][3] = Qu[(wl + g + 8) * AT_NW + ko * 8 + t4 + 4];
        }
    }
    const float cl0 = ca[l0 + wl + g] + lc;
    const float cl1 = ca[l0 + wl + g + 8] + lc;
    const float bc  = ca[l0];
    const float iw0 = __expf(cl0 - bc);   // inter row weights (include 1/oc)
    const float iw1 = __expf(cl1 - bc);

    // inter: P = Q . State'^T  (C[l,e] = sum_d q[l,d]*State'[e,d])
    float accO[8][4];
#pragma unroll
    for (int nt = 0; nt < 8; nt++)
#pragma unroll
        for (int e = 0; e < 4; e++) accO[nt][e] = 0.f;

    {
        const uint32_t* Su = reinterpret_cast<const uint32_t*>(Vt);
#pragma unroll
        for (int ko = 0; ko < 8; ko++) {
            uint32_t b[8][2];
#pragma unroll
            for (int nt = 0; nt < 8; nt++) {
                b[nt][0] = Su[(nt * 8 + g) * AT_NW + ko * 8 + t4];
                b[nt][1] = Su[(nt * 8 + g) * AT_NW + ko * 8 + t4 + 4];
            }
#pragma unroll
            for (int nt = 0; nt < 8; nt++)
                MMA_TF32(accO[nt], qa[ko], b[nt]);
        }
#pragma unroll
        for (int nt = 0; nt < 8; nt++) {
            accO[nt][0] *= iw0;
            accO[nt][1] *= iw0;
            accO[nt][2] *= iw1;
            accO[nt][3] *= iw1;
        }
    }
    __syncthreads();   // done reading KSs(Q) and Vt(State)

    // load K into KSs, V transposed into Vt
    for (int f = tid; f < 1024; f += 128) {
        int row = f >> 4, c4 = (f & 15) << 2;
        cvt_store<AT_NW>(KSs, row, c4,
            *reinterpret_cast<const float4*>(&kh[(size_t)(l0 + row) * DH_ + c4]));
    }
    {
        const int d0 = w * 16;
        int m = lane;
#pragma unroll
        for (int half = 0; half < 2; half++, m += 32) {
#pragma unroll
            for (int i = 0; i < 4; i++) {
                float4 x = *reinterpret_cast<const float4*>(
                    &vh[(size_t)(l0 + m) * DH_ + d0 + i * 4]);
                Vt[(d0 + i * 4 + 0) * AT_NW + m] = f2tf32f(x.x);
                Vt[(d0 + i * 4 + 1) * AT_NW + m] = f2tf32f(x.y);
                Vt[(d0 + i * 4 + 2) * AT_NW + m] = f2tf32f(x.z);
                Vt[(d0 + i * 4 + 3) * AT_NW + m] = f2tf32f(x.w);
            }
        }
    }
    __syncthreads();

    // S-phase: sfr = Q(16x64) . K^T(64x64)
    float sfr[8][4];
#pragma unroll
    for (int nt = 0; nt < 8; nt++)
#pragma unroll
        for (int e = 0; e < 4; e++) sfr[nt][e] = 0.f;

    {
        const uint32_t* Ku = reinterpret_cast<const uint32_t*>(KSs);
#pragma unroll
        for (int ko = 0; ko < 8; ko++) {
            uint32_t b[8][2];
#pragma unroll
            for (int nt = 0; nt < 8; nt++) {
                b[nt][0] = Ku[(nt * 8 + g) * AT_NW + ko * 8 + t4];
                b[nt][1] = Ku[(nt * 8 + g) * AT_NW + ko * 8 + t4 + 4];
            }
#pragma unroll
            for (int nt = 0; nt < 8; nt++)
                MMA_TF32(sfr[nt], qa[ko], b[nt]);
        }
    }

    // intra decay weighting + causal mask
    const int gl0 = l0 + wl + g, gl1 = gl0 + 8;
#pragma unroll
    for (int nt = 0; nt < 8; nt++) {
        const int gm0 = l0 + nt * 8 + 2 * t4;
        const int gm1 = gm0 + 1;
        const float cm0 = ca[gm0], cm1 = ca[gm1];
        sfr[nt][0] *= (gm0 <= gl0) ? __expf(cl0 - cm0) : 0.f;
        sfr[nt][1] *= (gm1 <= gl0) ? __expf(cl0 - cm1) : 0.f;
        sfr[nt][2] *= (gm0 <= gl1) ? __expf(cl1 - cm0) : 0.f;
        sfr[nt][3] *= (gm1 <= gl1) ? __expf(cl1 - cm1) : 0.f;
    }
    __syncthreads();   // all warps done reading K

    // store weighted S (tf32) into warp-private KSs rows
#pragma unroll
    for (int nt = 0; nt < 8; nt++) {
        const int cc = nt * 8 + 2 * t4;
        *reinterpret_cast<float2*>(&KSs[(wl + g) * AT_NW + cc]) =
            make_float2(f2tf32f(sfr[nt][0]), f2tf32f(sfr[nt][1]));
        *reinterpret_cast<float2*>(&KSs[(wl + g + 8) * AT_NW + cc]) =
            make_float2(f2tf32f(sfr[nt][2]), f2tf32f(sfr[nt][3]));
    }
    __syncwarp();

    // O-phase: accO += S(16x64) . V(64x64)
    {
        const uint32_t* Su = reinterpret_cast<const uint32_t*>(KSs);
        const uint32_t* Vu = reinterpret_cast<const uint32_t*>(Vt);
#pragma unroll
        for (int ko = 0; ko < 8; ko++) {
            uint32_t a[4];
            a[0] = Su[(wl + g) * AT_NW + ko * 8 + t4];
            a[1] = Su[(wl + g + 8) * AT_NW + ko * 8 + t4];
            a[2] = Su[(wl + g) * AT_NW + ko * 8 + t4 + 4];
            a[3] = Su[(wl + g + 8) * AT_NW + ko * 8 + t4 + 4];
#pragma unroll
            for (int nt = 0; nt < 8; nt++) {
                uint32_t b[2];
                b[0] = Vu[(nt * 8 + g) * AT_NW + ko * 8 + t4];
                b[1] = Vu[(nt * 8 + g) * AT_NW + ko * 8 + t4 + 4];
                MMA_TF32(accO[nt], a, b);
            }
        }
    }

    // fused RMSNorm epilogue
    float ss0 = 0.f, ss1 = 0.f;
#pragma unroll
    for (int nt = 0; nt < 8; nt++) {
        ss0 = fmaf(accO[nt][0], accO[nt][0], ss0);
        ss0 = fmaf(accO[nt][1], accO[nt][1], ss0);
        ss1 = fmaf(accO[nt][2], accO[nt][2], ss1);
        ss1 = fmaf(accO[nt][3], accO[nt][3], ss1);
    }
    ss0 += __shfl_xor_sync(0xffffffffu, ss0, 1);
    ss0 += __shfl_xor_sync(0xffffffffu, ss0, 2);
    ss1 += __shfl_xor_sync(0xffffffffu, ss1, 1);
    ss1 += __shfl_xor_sync(0xffffffffu, ss1, 2);
    const float r0 = rsqrtf(ss0 * (1.f / 64.f) + EPS_);
    const float r1 = rsqrtf(ss1 * (1.f / 64.f) + EPS_);

#pragma unroll
    for (int nt = 0; nt < 8; nt++) {
        const int dc = nt * 8 + 2 * t4;
        const float2 nw = *reinterpret_cast<const float2*>(&norm_w[dc]);
        const int col = h * DH_ + dc;
        *reinterpret_cast<float2*>(&g_attn[(size_t)(l0 + wl + g) * QS_ + col]) =
            make_float2(accO[nt][0] * r0 * nw.x, accO[nt][1] * r0 * nw.y);
        *reinterpret_cast<float2*>(&g_attn[(size_t)(l0 + wl + g + 8) * QS_ + col]) =
            make_float2(accO[nt][2] * r1 * nw.x, accO[nt][3] * r1 * nw.y);
    }
}

// ---------------- launch ---------------------------------------------------------
extern "C" void kernel_launch(void* const* d_in, const int* in_sizes, int n_in,
                              void* d_out, int out_size)
{
    const float* hidden    = (const float*)d_in[0];
    // d_in[1] = attention_mask (causal triu) — structurally known, unused
    const float* qkv_w     = (const float*)d_in[2];
    const float* q_conv_w  = (const float*)d_in[3];
    const float* q_conv_b  = (const float*)d_in[4];
    const float* k_conv_w  = (const float*)d_in[5];
    const float* k_conv_b  = (const float*)d_in[6];
    const float* v_conv_w  = (const float*)d_in[7];
    const float* v_conv_b  = (const float*)d_in[8];
    const float* norm_w    = (const float*)d_in[9];
    const float* A_log     = (const float*)d_in[10];
    const float* dt_bias   = (const float*)d_in[11];
    const float* dt_proj_w = (const float*)d_in[12];
    const float* dt_proj_b = (const float*)d_in[13];
    const float* o_w       = (const float*)d_in[14];
    const float* order_c   = (const float*)d_in[15];
    float* out = (float*)d_out;

    mma_qkv_kernel<<<dim3(T3_ / 128, L_ / 128), 256>>>(hidden, qkv_w);
    dt_kernel<<<L_, 512>>>(hidden, dt_proj_w, dt_proj_b, dt_bias, A_log);
    cumsum_kernel<<<H_, 256>>>();
    conv_kernel<<<(L_ * QS_) / 256, 256>>>(q_conv_w, q_conv_b, k_conv_w, k_conv_b,
                                           v_conv_w, v_conv_b);
    kv_outer_kernel<<<dim3(NCH_ - 1, H_), 128>>>();
    state_scan_kernel<<<H_, 256>>>();
    attn_mma_kernel<<<dim3(NCH_, H_), 128>>>(norm_w, order_c);
    mma_o_kernel<<<dim3(HID_ / 128, L_ / 128), 256>>>(o_w, out);
}

// round 6
// speedup vs baseline: 3.1725x; 1.1324x over previous
#include <cuda_runtime.h>
#include <stdint.h>
#include <math.h>

#define L_    2048
#define HID_  1024
#define H_    16
#define DH_   64
#define QS_   1024
#define T3_   3072
#define NCH_  32          // chunks of 64
#define EPS_  1.1920929e-07f

// ---------------- scratch (device globals; no allocation allowed) ----------------
__device__ float g_qkv[L_ * T3_];          // (L, 3072)
__device__ float g_q[H_ * L_ * DH_];       // (H, L, DH)
__device__ float g_k[H_ * L_ * DH_];
__device__ float g_v[H_ * L_ * DH_];       // pre-scaled by dt
__device__ float g_dt[H_ * L_];
__device__ float g_Adec[H_ * L_];
__device__ float g_ca[H_ * L_];            // cumsum of A per head
__device__ float g_attn[L_ * QS_];         // (L, H*DH) post-RMSNorm
__device__ float g_M[H_ * NCH_ * DH_ * DH_];      // per-chunk decayed outer products [e][d]
__device__ float g_state[H_ * NCH_ * DH_ * DH_];  // scanned states [e][d]

// =================================================================================
// tf32 mma.sync helpers
// =================================================================================
#define MMA_TF32(D, Ar, Br)                                                        \
    asm volatile("mma.sync.aligned.m16n8k8.row.col.f32.tf32.tf32.f32 "             \
                 "{%0,%1,%2,%3}, {%4,%5,%6,%7}, {%8,%9}, {%0,%1,%2,%3};"           \
                 : "+f"((D)[0]), "+f"((D)[1]), "+f"((D)[2]), "+f"((D)[3])          \
                 : "r"((Ar)[0]), "r"((Ar)[1]), "r"((Ar)[2]), "r"((Ar)[3]),         \
                   "r"((Br)[0]), "r"((Br)[1]))

__device__ __forceinline__ uint32_t f2tf32(float x) {
    uint32_t u;
    asm("cvt.rna.tf32.f32 %0, %1;" : "=r"(u) : "f"(x));
    return u;
}
__device__ __forceinline__ float f2tf32f(float x) { return __uint_as_float(f2tf32(x)); }

template <int STRIDE>
__device__ __forceinline__ void cvt_store(float* dst, int row, int cg, float4 x) {
    float4 y;
    y.x = f2tf32f(x.x);
    y.y = f2tf32f(x.y);
    y.z = f2tf32f(x.z);
    y.w = f2tf32f(x.w);
    *reinterpret_cast<float4*>(&dst[row * STRIDE + cg]) = y;
}

// =================================================================================
// TN GEMM on tensor pipe: K-step 32, double-buffered dynamic smem (72KB)
// CTA tile 128x128, 256 threads = 8 warps (4m x 2n), warp tile 32x64.
// Smem stride 36: frag banks (4g + t4) mod 32 all distinct -> conflict-free.
// =================================================================================
#define GS_ (128 * 36)     // floats per operand per buffer

template <int M, int N, int K>
__device__ __forceinline__ void mma_gemm_body(const float* __restrict__ A,
                                              const float* __restrict__ B,
                                              float* __restrict__ C)
{
    extern __shared__ __align__(16) float smem_g[];
    float* As[2] = { smem_g,            smem_g + 2 * GS_ };
    float* Bs[2] = { smem_g + GS_,      smem_g + 3 * GS_ };

    const int tid  = threadIdx.x;
    const int lane = tid & 31;
    const int wid  = tid >> 5;
    const int g    = lane >> 2;
    const int t4   = lane & 3;
    const int m0   = blockIdx.y * 128;
    const int n0   = blockIdx.x * 128;
    const int wm   = (wid >> 1) * 32;
    const int wn   = (wid & 1) * 64;

    // loader coords: 1024 float4 per operand stage, 4 per thread
    int lr[4], lc[4];
#pragma unroll
    for (int r = 0; r < 4; r++) {
        const int v = tid + 256 * r;
        lr[r] = v >> 3;
        lc[r] = (v & 7) << 2;
    }

    float acc[2][8][4];
#pragma unroll
    for (int mt = 0; mt < 2; mt++)
#pragma unroll
        for (int nt = 0; nt < 8; nt++)
#pragma unroll
            for (int e = 0; e < 4; e++) acc[mt][nt][e] = 0.f;

    // prologue: fill buffer 0
#pragma unroll
    for (int r = 0; r < 4; r++) {
        cvt_store<36>(As[0], lr[r], lc[r],
            *reinterpret_cast<const float4*>(&A[(size_t)(m0 + lr[r]) * K + lc[r]]));
        cvt_store<36>(Bs[0], lr[r], lc[r],
            *reinterpret_cast<const float4*>(&B[(size_t)(n0 + lr[r]) * K + lc[r]]));
    }
    __syncthreads();

    int buf = 0;
    for (int k0 = 0; k0 < K; k0 += 32) {
        const bool has_next = (k0 + 32) < K;
        float4 pa[4], pb[4];
        if (has_next) {
            const int kn = k0 + 32;
#pragma unroll
            for (int r = 0; r < 4; r++) {
                pa[r] = *reinterpret_cast<const float4*>(&A[(size_t)(m0 + lr[r]) * K + kn + lc[r]]);
                pb[r] = *reinterpret_cast<const float4*>(&B[(size_t)(n0 + lr[r]) * K + kn + lc[r]]);
            }
        }

        const uint32_t* Au = reinterpret_cast<const uint32_t*>(As[buf]);
        const uint32_t* Bu = reinterpret_cast<const uint32_t*>(Bs[buf]);
#pragma unroll
        for (int ks = 0; ks < 32; ks += 8) {
            uint32_t a[2][4], b[8][2];
#pragma unroll
            for (int mt = 0; mt < 2; mt++) {
                const int r = wm + mt * 16 + g;
                a[mt][0] = Au[r * 36 + ks + t4];
                a[mt][1] = Au[(r + 8) * 36 + ks + t4];
                a[mt][2] = Au[r * 36 + ks + t4 + 4];
                a[mt][3] = Au[(r + 8) * 36 + ks + t4 + 4];
            }
#pragma unroll
            for (int nt = 0; nt < 8; nt++) {
                const int r = wn + nt * 8 + g;
                b[nt][0] = Bu[r * 36 + ks + t4];
                b[nt][1] = Bu[r * 36 + ks + t4 + 4];
            }
#pragma unroll
            for (int mt = 0; mt < 2; mt++)
#pragma unroll
                for (int nt = 0; nt < 8; nt++)
                    MMA_TF32(acc[mt][nt], a[mt], b[nt]);
        }

        if (has_next) {
#pragma unroll
            for (int r = 0; r < 4; r++) {
                cvt_store<36>(As[buf ^ 1], lr[r], lc[r], pa[r]);
                cvt_store<36>(Bs[buf ^ 1], lr[r], lc[r], pb[r]);
            }
            __syncthreads();
            buf ^= 1;
        }
    }

#pragma unroll
    for (int mt = 0; mt < 2; mt++) {
#pragma unroll
        for (int nt = 0; nt < 8; nt++) {
            const int row = m0 + wm + mt * 16 + g;
            const int col = n0 + wn + nt * 8 + t4 * 2;
            *reinterpret_cast<float2*>(&C[(size_t)row * N + col]) =
                make_float2(acc[mt][nt][0], acc[mt][nt][1]);
            *reinterpret_cast<float2*>(&C[(size_t)(row + 8) * N + col]) =
                make_float2(acc[mt][nt][2], acc[mt][nt][3]);
        }
    }
}

__global__ __launch_bounds__(256) void mma_qkv_kernel(const float* __restrict__ X,
                                                      const float* __restrict__ W)
{
    mma_gemm_body<L_, T3_, HID_>(X, W, g_qkv);
}

__global__ __launch_bounds__(256) void mma_o_kernel(const float* __restrict__ W,
                                                    float* __restrict__ out)
{
    mma_gemm_body<L_, HID_, QS_>(g_attn, W, out);
}

// ---------------- dt = softplus(X @ Wdt^T + b + dt_bias); A = -exp(A_log)*dt -----
__global__ __launch_bounds__(512) void dt_kernel(const float* __restrict__ X,
                                                 const float* __restrict__ W,
                                                 const float* __restrict__ b,
                                                 const float* __restrict__ dt_bias,
                                                 const float* __restrict__ A_log)
{
    const int l = blockIdx.x;
    const int warp = threadIdx.x >> 5;
    const int lane = threadIdx.x & 31;
    const float* x = X + (size_t)l * HID_;
    const float* w = W + (size_t)warp * HID_;
    float s = 0.f;
#pragma unroll 8
    for (int k = lane; k < HID_; k += 32) s = fmaf(x[k], w[k], s);
#pragma unroll
    for (int o = 16; o; o >>= 1) s += __shfl_xor_sync(0xffffffffu, s, o);
    if (lane == 0) {
        float xv = s + b[warp] + dt_bias[warp];
        float dt = (xv > 20.f) ? xv : log1pf(expf(xv));
        g_dt[warp * L_ + l]   = dt;
        g_Adec[warp * L_ + l] = -expf(A_log[warp]) * dt;
    }
}

// ---------------- per-head inclusive cumsum over L -------------------------------
__global__ __launch_bounds__(256) void cumsum_kernel()
{
    const int h = blockIdx.x;
    __shared__ float wsum[8];
    __shared__ float carry_s;
    const int tid = threadIdx.x, lane = tid & 31, warp = tid >> 5;
    if (tid == 0) carry_s = 0.f;
    __syncthreads();
    for (int base = 0; base < L_; base += 256) {
        float x = g_Adec[h * L_ + base + tid];
#pragma unroll
        for (int o = 1; o < 32; o <<= 1) {
            float t = __shfl_up_sync(0xffffffffu, x, o);
            if (lane >= o) x += t;
        }
        if (lane == 31) wsum[warp] = x;
        __syncthreads();
        if (tid < 8) {
            float w = wsum[tid];
#pragma unroll
            for (int o = 1; o < 8; o <<= 1) {
                float t = __shfl_up_sync(0xffu, w, o);
                if (tid >= o) w += t;
            }
            wsum[tid] = w;
        }
        __syncthreads();
        float pre = (warp > 0 ? wsum[warp - 1] : 0.f) + carry_s;
        float outv = x + pre;
        g_ca[h * L_ + base + tid] = outv;
        __syncthreads();
        if (tid == 255) carry_s = outv;
        __syncthreads();
    }
}

// ---------------- causal depthwise conv (K=2) + head split + v*dt ----------------
__global__ __launch_bounds__(256) void conv_kernel(const float* __restrict__ qcw,
                                                   const float* __restrict__ qcb,
                                                   const float* __restrict__ kcw,
                                                   const float* __restrict__ kcb,
                                                   const float* __restrict__ vcw,
                                                   const float* __restrict__ vcb)
{
    const int idx = blockIdx.x * 256 + threadIdx.x;
    const int l = idx >> 10;
    const int c = idx & 1023;
    const int h = c >> 6;
    const int d = c & 63;
    const float* row  = g_qkv + (size_t)l * T3_;
    const float* prow = g_qkv + (size_t)(l - 1) * T3_;
    const bool hasp = (l > 0);
    float qc = row[c];            float qp = hasp ? prow[c] : 0.f;
    float kc = row[QS_ + c];      float kp = hasp ? prow[QS_ + c] : 0.f;
    float vc = row[2 * QS_ + c];  float vp = hasp ? prow[2 * QS_ + c] : 0.f;
    float qv = fmaf(qc, qcw[2 * c + 1], fmaf(qp, qcw[2 * c], qcb[c]));
    float kv = fmaf(kc, kcw[2 * c + 1], fmaf(kp, kcw[2 * c], kcb[c]));
    float vv = fmaf(vc, vcw[2 * c + 1], fmaf(vp, vcw[2 * c], vcb[c]));
    vv *= g_dt[h * L_ + l];
    const size_t o = ((size_t)h * L_ + l) * DH_ + d;
    g_q[o] = qv;
    g_k[o] = kv;
    g_v[o] = vv;
}

// =================================================================================
// Chunked linear attention (exact factorization of the decay weights)
// =================================================================================
#define AT_NW 68

// ---- Phase A: per-chunk decayed outer product M'[e][d] = sum_m v[m,e]*k'[m,d] ----
__global__ __launch_bounds__(128) void kv_outer_kernel()
{
    __shared__ __align__(16) float Kt[64 * AT_NW];   // [d][m]
    __shared__ __align__(16) float Vt2[64 * AT_NW];  // [e][m]

    const int c = blockIdx.x, h = blockIdx.y;
    const int m0 = c * 64;
    const int tid = threadIdx.x, lane = tid & 31, w = tid >> 5;
    const int g = lane >> 2, t4 = lane & 3;
    const int wl = w * 16;
    const float* ca = g_ca + h * L_;
    const float* kh = g_k + (size_t)h * L_ * DH_;
    const float* vh = g_v + (size_t)h * L_ * DH_;
    const float bnext = ca[(c + 1) * 64];

    const int d0 = w * 16;
    int m = lane;
#pragma unroll
    for (int half = 0; half < 2; half++, m += 32) {
        const float wm = __expf(bnext - ca[m0 + m]);
#pragma unroll
        for (int i = 0; i < 4; i++) {
            float4 kx = *reinterpret_cast<const float4*>(&kh[(size_t)(m0 + m) * DH_ + d0 + i * 4]);
            Kt[(d0 + i * 4 + 0) * AT_NW + m] = f2tf32f(kx.x * wm);
            Kt[(d0 + i * 4 + 1) * AT_NW + m] = f2tf32f(kx.y * wm);
            Kt[(d0 + i * 4 + 2) * AT_NW + m] = f2tf32f(kx.z * wm);
            Kt[(d0 + i * 4 + 3) * AT_NW + m] = f2tf32f(kx.w * wm);
            float4 vx = *reinterpret_cast<const float4*>(&vh[(size_t)(m0 + m) * DH_ + d0 + i * 4]);
            Vt2[(d0 + i * 4 + 0) * AT_NW + m] = f2tf32f(vx.x);
            Vt2[(d0 + i * 4 + 1) * AT_NW + m] = f2tf32f(vx.y);
            Vt2[(d0 + i * 4 + 2) * AT_NW + m] = f2tf32f(vx.z);
            Vt2[(d0 + i * 4 + 3) * AT_NW + m] = f2tf32f(vx.w);
        }
    }
    __syncthreads();

    float acc[8][4];
#pragma unroll
    for (int nt = 0; nt < 8; nt++)
#pragma unroll
        for (int e = 0; e < 4; e++) acc[nt][e] = 0.f;

    const uint32_t* Vu = reinterpret_cast<const uint32_t*>(Vt2);
    const uint32_t* Ku = reinterpret_cast<const uint32_t*>(Kt);
#pragma unroll
    for (int ko = 0; ko < 8; ko++) {
        uint32_t a[4];
        a[0] = Vu[(wl + g) * AT_NW + ko * 8 + t4];
        a[1] = Vu[(wl + g + 8) * AT_NW + ko * 8 + t4];
        a[2] = Vu[(wl + g) * AT_NW + ko * 8 + t4 + 4];
        a[3] = Vu[(wl + g + 8) * AT_NW + ko * 8 + t4 + 4];
#pragma unroll
        for (int nt = 0; nt < 8; nt++) {
            uint32_t b[2];
            b[0] = Ku[(nt * 8 + g) * AT_NW + ko * 8 + t4];
            b[1] = Ku[(nt * 8 + g) * AT_NW + ko * 8 + t4 + 4];
            MMA_TF32(acc[nt], a, b);
        }
    }

    float* Md = g_M + ((size_t)(h * NCH_ + c) << 12);
#pragma unroll
    for (int nt = 0; nt < 8; nt++) {
        const int dc = nt * 8 + 2 * t4;
        *reinterpret_cast<float2*>(&Md[(wl + g) * 64 + dc])     = make_float2(acc[nt][0], acc[nt][1]);
        *reinterpret_cast<float2*>(&Md[(wl + g + 8) * 64 + dc]) = make_float2(acc[nt][2], acc[nt][3]);
    }
}

// ---- Phase B: per-head state scan, depth-2 register prefetch. grid H, 1024 thr --
__global__ __launch_bounds__(1024) void state_scan_kernel()
{
    const int h = blockIdx.x, t = threadIdx.x;
    __shared__ float decs[NCH_];
    if (t < NCH_) {
        const float* ca = g_ca + h * L_;
        decs[t] = (t < NCH_ - 1) ? __expf(ca[(t + 1) * 64] - ca[t * 64]) : 0.f;
    }
    __syncthreads();

    const float* Mbase = g_M + ((size_t)h * NCH_ << 12);
    float* Sbase = g_state + ((size_t)h * NCH_ << 12);
    const int off = t * 4;

    float4 st = make_float4(0.f, 0.f, 0.f, 0.f);
    float4 mbuf0 = *reinterpret_cast<const float4*>(&Mbase[off]);                 // M[0]
    float4 mbuf1 = *reinterpret_cast<const float4*>(&Mbase[(1 << 12) + off]);     // M[1]

    for (int c = 0; c < NCH_; c++) {
        *reinterpret_cast<float4*>(&Sbase[((size_t)c << 12) + off]) = st;
        if (c < NCH_ - 1) {
            const float dec = decs[c];
            st.x = fmaf(st.x, dec, mbuf0.x);
            st.y = fmaf(st.y, dec, mbuf0.y);
            st.z = fmaf(st.z, dec, mbuf0.z);
            st.w = fmaf(st.w, dec, mbuf0.w);
            mbuf0 = mbuf1;
            if (c + 2 < NCH_ - 1 + 1)   // need M[c+2] only when c+2 <= NCH_-2 used later; safe read c+2 < NCH_
                if (c + 2 < NCH_)
                    mbuf1 = *reinterpret_cast<const float4*>(&Mbase[((size_t)(c + 2) << 12) + off]);
        }
    }
}

// ---- Phase C: diagonal tile (intra) + q.State (inter), fused RMSNorm ------------
__global__ __launch_bounds__(128) void attn_mma_kernel(const float* __restrict__ norm_w,
                                                       const float* __restrict__ order_coeff)
{
    __shared__ __align__(16) float KSs[64 * AT_NW];   // Q staging -> K -> weighted S
    __shared__ __align__(16) float Vt[64 * AT_NW];    // State' -> V^T

    const int h    = blockIdx.y;
    const int lt   = blockIdx.x;
    const int l0   = lt * 64;
    const int tid  = threadIdx.x;
    const int lane = tid & 31;
    const int w    = tid >> 5;
    const int g    = lane >> 2;
    const int t4   = lane & 3;
    const int wl   = w * 16;

    const float* qh = g_q + (size_t)h * L_ * DH_;
    const float* kh = g_k + (size_t)h * L_ * DH_;
    const float* vh = g_v + (size_t)h * L_ * DH_;
    const float* ca = g_ca + h * L_;
    const float lc  = __logf(1.f / order_coeff[h]);

    const float* Sg = g_state + ((size_t)(h * NCH_ + lt) << 12);
    for (int f = tid; f < 1024; f += 128) {
        int row = f >> 4, c4 = (f & 15) << 2;
        cvt_store<AT_NW>(KSs, row, c4,
            *reinterpret_cast<const float4*>(&qh[(size_t)(l0 + row) * DH_ + c4]));
        cvt_store<AT_NW>(Vt, row, c4,
            *reinterpret_cast<const float4*>(&Sg[row * 64 + c4]));
    }
    __syncthreads();

    uint32_t qa[8][4];
    {
        const uint32_t* Qu = reinterpret_cast<const uint32_t*>(KSs);
#pragma unroll
        for (int ko = 0; ko < 8; ko++) {
            qa[ko][0] = Qu[(wl + g) * AT_NW + ko * 8 + t4];
            qa[ko][1] = Qu[(wl + g + 8) * AT_NW + ko * 8 + t4];
            qa[ko][2] = Qu[(wl + g) * AT_NW + ko * 8 + t4 + 4];
            qa[ko][3] = Qu[(wl + g + 8) * AT_NW + ko * 8 + t4 + 4];
        }
    }
    const float cl0 = ca[l0 + wl + g] + lc;
    const float cl1 = ca[l0 + wl + g + 8] + lc;
    const float bc  = ca[l0];
    const float iw0 = __expf(cl0 - bc);
    const float iw1 = __expf(cl1 - bc);

    float accO[8][4];
#pragma unroll
    for (int nt = 0; nt < 8; nt++)
#pragma unroll
        for (int e = 0; e < 4; e++) accO[nt][e] = 0.f;

    {
        const uint32_t* Su = reinterpret_cast<const uint32_t*>(Vt);
#pragma unroll
        for (int ko = 0; ko < 8; ko++) {
            uint32_t b[8][2];
#pragma unroll
            for (int nt = 0; nt < 8; nt++) {
                b[nt][0] = Su[(nt * 8 + g) * AT_NW + ko * 8 + t4];
                b[nt][1] = Su[(nt * 8 + g) * AT_NW + ko * 8 + t4 + 4];
            }
#pragma unroll
            for (int nt = 0; nt < 8; nt++)
                MMA_TF32(accO[nt], qa[ko], b[nt]);
        }
#pragma unroll
        for (int nt = 0; nt < 8; nt++) {
            accO[nt][0] *= iw0;
            accO[nt][1] *= iw0;
            accO[nt][2] *= iw1;
            accO[nt][3] *= iw1;
        }
    }
    __syncthreads();

    for (int f = tid; f < 1024; f += 128) {
        int row = f >> 4, c4 = (f & 15) << 2;
        cvt_store<AT_NW>(KSs, row, c4,
            *reinterpret_cast<const float4*>(&kh[(size_t)(l0 + row) * DH_ + c4]));
    }
    {
        const int d0 = w * 16;
        int m = lane;
#pragma unroll
        for (int half = 0; half < 2; half++, m += 32) {
#pragma unroll
            for (int i = 0; i < 4; i++) {
                float4 x = *reinterpret_cast<const float4*>(
                    &vh[(size_t)(l0 + m) * DH_ + d0 + i * 4]);
                Vt[(d0 + i * 4 + 0) * AT_NW + m] = f2tf32f(x.x);
                Vt[(d0 + i * 4 + 1) * AT_NW + m] = f2tf32f(x.y);
                Vt[(d0 + i * 4 + 2) * AT_NW + m] = f2tf32f(x.z);
                Vt[(d0 + i * 4 + 3) * AT_NW + m] = f2tf32f(x.w);
            }
        }
    }
    __syncthreads();

    float sfr[8][4];
#pragma unroll
    for (int nt = 0; nt < 8; nt++)
#pragma unroll
        for (int e = 0; e < 4; e++) sfr[nt][e] = 0.f;

    {
        const uint32_t* Ku = reinterpret_cast<const uint32_t*>(KSs);
#pragma unroll
        for (int ko = 0; ko < 8; ko++) {
            uint32_t b[8][2];
#pragma unroll
            for (int nt = 0; nt < 8; nt++) {
                b[nt][0] = Ku[(nt * 8 + g) * AT_NW + ko * 8 + t4];
                b[nt][1] = Ku[(nt * 8 + g) * AT_NW + ko * 8 + t4 + 4];
            }
#pragma unroll
            for (int nt = 0; nt < 8; nt++)
                MMA_TF32(sfr[nt], qa[ko], b[nt]);
        }
    }

    const int gl0 = l0 + wl + g, gl1 = gl0 + 8;
#pragma unroll
    for (int nt = 0; nt < 8; nt++) {
        const int gm0 = l0 + nt * 8 + 2 * t4;
        const int gm1 = gm0 + 1;
        const float cm0 = ca[gm0], cm1 = ca[gm1];
        sfr[nt][0] *= (gm0 <= gl0) ? __expf(cl0 - cm0) : 0.f;
        sfr[nt][1] *= (gm1 <= gl0) ? __expf(cl0 - cm1) : 0.f;
        sfr[nt][2] *= (gm0 <= gl1) ? __expf(cl1 - cm0) : 0.f;
        sfr[nt][3] *= (gm1 <= gl1) ? __expf(cl1 - cm1) : 0.f;
    }
    __syncthreads();

#pragma unroll
    for (int nt = 0; nt < 8; nt++) {
        const int cc = nt * 8 + 2 * t4;
        *reinterpret_cast<float2*>(&KSs[(wl + g) * AT_NW + cc]) =
            make_float2(f2tf32f(sfr[nt][0]), f2tf32f(sfr[nt][1]));
        *reinterpret_cast<float2*>(&KSs[(wl + g + 8) * AT_NW + cc]) =
            make_float2(f2tf32f(sfr[nt][2]), f2tf32f(sfr[nt][3]));
    }
    __syncwarp();

    {
        const uint32_t* Su = reinterpret_cast<const uint32_t*>(KSs);
        const uint32_t* Vu = reinterpret_cast<const uint32_t*>(Vt);
#pragma unroll
        for (int ko = 0; ko < 8; ko++) {
            uint32_t a[4];
            a[0] = Su[(wl + g) * AT_NW + ko * 8 + t4];
            a[1] = Su[(wl + g + 8) * AT_NW + ko * 8 + t4];
            a[2] = Su[(wl + g) * AT_NW + ko * 8 + t4 + 4];
            a[3] = Su[(wl + g + 8) * AT_NW + ko * 8 + t4 + 4];
#pragma unroll
            for (int nt = 0; nt < 8; nt++) {
                uint32_t b[2];
                b[0] = Vu[(nt * 8 + g) * AT_NW + ko * 8 + t4];
                b[1] = Vu[(nt * 8 + g) * AT_NW + ko * 8 + t4 + 4];
                MMA_TF32(accO[nt], a, b);
            }
        }
    }

    float ss0 = 0.f, ss1 = 0.f;
#pragma unroll
    for (int nt = 0; nt < 8; nt++) {
        ss0 = fmaf(accO[nt][0], accO[nt][0], ss0);
        ss0 = fmaf(accO[nt][1], accO[nt][1], ss0);
        ss1 = fmaf(accO[nt][2], accO[nt][2], ss1);
        ss1 = fmaf(accO[nt][3], accO[nt][3], ss1);
    }
    ss0 += __shfl_xor_sync(0xffffffffu, ss0, 1);
    ss0 += __shfl_xor_sync(0xffffffffu, ss0, 2);
    ss1 += __shfl_xor_sync(0xffffffffu, ss1, 1);
    ss1 += __shfl_xor_sync(0xffffffffu, ss1, 2);
    const float r0 = rsqrtf(ss0 * (1.f / 64.f) + EPS_);
    const float r1 = rsqrtf(ss1 * (1.f / 64.f) + EPS_);

#pragma unroll
    for (int nt = 0; nt < 8; nt++) {
        const int dc = nt * 8 + 2 * t4;
        const float2 nw = *reinterpret_cast<const float2*>(&norm_w[dc]);
        const int col = h * DH_ + dc;
        *reinterpret_cast<float2*>(&g_attn[(size_t)(l0 + wl + g) * QS_ + col]) =
            make_float2(accO[nt][0] * r0 * nw.x, accO[nt][1] * r0 * nw.y);
        *reinterpret_cast<float2*>(&g_attn[(size_t)(l0 + wl + g + 8) * QS_ + col]) =
            make_float2(accO[nt][2] * r1 * nw.x, accO[nt][3] * r1 * nw.y);
    }
}

// ---------------- launch ---------------------------------------------------------
#define GEMM_SMEM (4 * GS_ * (int)sizeof(float))   // 73728 bytes

extern "C" void kernel_launch(void* const* d_in, const int* in_sizes, int n_in,
                              void* d_out, int out_size)
{
    const float* hidden    = (const float*)d_in[0];
    // d_in[1] = attention_mask (causal triu) — structurally known, unused
    const float* qkv_w     = (const float*)d_in[2];
    const float* q_conv_w  = (const float*)d_in[3];
    const float* q_conv_b  = (const float*)d_in[4];
    const float* k_conv_w  = (const float*)d_in[5];
    const float* k_conv_b  = (const float*)d_in[6];
    const float* v_conv_w  = (const float*)d_in[7];
    const float* v_conv_b  = (const float*)d_in[8];
    const float* norm_w    = (const float*)d_in[9];
    const float* A_log     = (const float*)d_in[10];
    const float* dt_bias   = (const float*)d_in[11];
    const float* dt_proj_w = (const float*)d_in[12];
    const float* dt_proj_b = (const float*)d_in[13];
    const float* o_w       = (const float*)d_in[14];
    const float* order_c   = (const float*)d_in[15];
    float* out = (float*)d_out;

    static int attr_done = 0;
    if (!attr_done) {
        cudaFuncSetAttribute(mma_qkv_kernel, cudaFuncAttributeMaxDynamicSharedMemorySize, GEMM_SMEM);
        cudaFuncSetAttribute(mma_o_kernel,   cudaFuncAttributeMaxDynamicSharedMemorySize, GEMM_SMEM);
        attr_done = 1;
    }

    mma_qkv_kernel<<<dim3(T3_ / 128, L_ / 128), 256, GEMM_SMEM>>>(hidden, qkv_w);
    dt_kernel<<<L_, 512>>>(hidden, dt_proj_w, dt_proj_b, dt_bias, A_log);
    cumsum_kernel<<<H_, 256>>>();
    conv_kernel<<<(L_ * QS_) / 256, 256>>>(q_conv_w, q_conv_b, k_conv_w, k_conv_b,
                                           v_conv_w, v_conv_b);
    kv_outer_kernel<<<dim3(NCH_ - 1, H_), 128>>>();
    state_scan_kernel<<<H_, 1024>>>();
    attn_mma_kernel<<<dim3(NCH_, H_), 128>>>(norm_w, order_c);
    mma_o_kernel<<<dim3(HID_ / 128, L_ / 128), 256, GEMM_SMEM>>>(o_w, out);
}

// round 7
// speedup vs baseline: 3.3434x; 1.0539x over previous
#include <cuda_runtime.h>
#include <stdint.h>
#include <math.h>

#define L_    2048
#define HID_  1024
#define H_    16
#define DH_   64
#define QS_   1024
#define T3_   3072
#define NCH_  32          // chunks of 64
#define EPS_  1.1920929e-07f

// ---------------- scratch (device globals; no allocation allowed) ----------------
__device__ float g_qkv[L_ * T3_];          // (L, 3072)
__device__ float g_q[H_ * L_ * DH_];       // (H, L, DH)
__device__ float g_k[H_ * L_ * DH_];
__device__ float g_v[H_ * L_ * DH_];       // pre-scaled by dt
__device__ float g_dt[H_ * L_];
__device__ float g_Adec[H_ * L_];
__device__ float g_ca[H_ * L_];            // cumsum of A per head
__device__ float g_attn[L_ * QS_];         // (L, H*DH) post-RMSNorm
__device__ float g_M[H_ * NCH_ * DH_ * DH_];      // per-chunk decayed outer products [e][d]
__device__ float g_state[H_ * NCH_ * DH_ * DH_];  // scanned states [e][d]

// =================================================================================
// tf32 mma.sync helpers
// =================================================================================
#define MMA_TF32(D, Ar, Br)                                                        \
    asm volatile("mma.sync.aligned.m16n8k8.row.col.f32.tf32.tf32.f32 "             \
                 "{%0,%1,%2,%3}, {%4,%5,%6,%7}, {%8,%9}, {%0,%1,%2,%3};"           \
                 : "+f"((D)[0]), "+f"((D)[1]), "+f"((D)[2]), "+f"((D)[3])          \
                 : "r"((Ar)[0]), "r"((Ar)[1]), "r"((Ar)[2]), "r"((Ar)[3]),         \
                   "r"((Br)[0]), "r"((Br)[1]))

__device__ __forceinline__ uint32_t f2tf32(float x) {
    uint32_t u;
    asm("cvt.rna.tf32.f32 %0, %1;" : "=r"(u) : "f"(x));
    return u;
}
__device__ __forceinline__ float f2tf32f(float x) { return __uint_as_float(f2tf32(x)); }

template <int STRIDE>
__device__ __forceinline__ void cvt_store(float* dst, int row, int cg, float4 x) {
    float4 y;
    y.x = f2tf32f(x.x);
    y.y = f2tf32f(x.y);
    y.z = f2tf32f(x.z);
    y.w = f2tf32f(x.w);
    *reinterpret_cast<float4*>(&dst[row * STRIDE + cg]) = y;
}

// =================================================================================
// TN GEMM on tensor pipe: K-step 32, double-buffered dynamic smem (72KB)
// CTA tile 128x128, 256 threads = 8 warps (4m x 2n), warp tile 32x64.
// Interleaved half-prefetch keeps only 16 regs in flight -> 2 CTAs/SM.
// =================================================================================
#define GS_ (128 * 36)     // floats per operand per buffer

template <int M, int N, int K>
__device__ __forceinline__ void mma_gemm_body(const float* __restrict__ A,
                                              const float* __restrict__ B,
                                              float* __restrict__ C)
{
    extern __shared__ __align__(16) float smem_g[];
    float* As[2] = { smem_g,            smem_g + 2 * GS_ };
    float* Bs[2] = { smem_g + GS_,      smem_g + 3 * GS_ };

    const int tid  = threadIdx.x;
    const int lane = tid & 31;
    const int wid  = tid >> 5;
    const int g    = lane >> 2;
    const int t4   = lane & 3;
    const int m0   = blockIdx.y * 128;
    const int n0   = blockIdx.x * 128;
    const int wm   = (wid >> 1) * 32;
    const int wn   = (wid & 1) * 64;

    // loader coords: 1024 float4 per operand stage, 4 per thread (2 per half)
    int lr[4], lc[4];
#pragma unroll
    for (int r = 0; r < 4; r++) {
        const int v = tid + 256 * r;
        lr[r] = v >> 3;
        lc[r] = (v & 7) << 2;
    }

    float acc[2][8][4];
#pragma unroll
    for (int mt = 0; mt < 2; mt++)
#pragma unroll
        for (int nt = 0; nt < 8; nt++)
#pragma unroll
            for (int e = 0; e < 4; e++) acc[mt][nt][e] = 0.f;

    // prologue: fill buffer 0
#pragma unroll
    for (int r = 0; r < 4; r++) {
        cvt_store<36>(As[0], lr[r], lc[r],
            *reinterpret_cast<const float4*>(&A[(size_t)(m0 + lr[r]) * K + lc[r]]));
        cvt_store<36>(Bs[0], lr[r], lc[r],
            *reinterpret_cast<const float4*>(&B[(size_t)(n0 + lr[r]) * K + lc[r]]));
    }
    __syncthreads();

    int buf = 0;
    for (int k0 = 0; k0 < K; k0 += 32) {
        const bool has_next = (k0 + 32) < K;
        const int kn = k0 + 32;
        const uint32_t* Au = reinterpret_cast<const uint32_t*>(As[buf]);
        const uint32_t* Bu = reinterpret_cast<const uint32_t*>(Bs[buf]);

#pragma unroll
        for (int half = 0; half < 2; half++) {
            // prefetch this half of the next stage (2 float4 per operand)
            float4 pa0, pa1, pb0, pb1;
            if (has_next) {
                const int i0 = half * 2, i1 = half * 2 + 1;
                pa0 = *reinterpret_cast<const float4*>(&A[(size_t)(m0 + lr[i0]) * K + kn + lc[i0]]);
                pa1 = *reinterpret_cast<const float4*>(&A[(size_t)(m0 + lr[i1]) * K + kn + lc[i1]]);
                pb0 = *reinterpret_cast<const float4*>(&B[(size_t)(n0 + lr[i0]) * K + kn + lc[i0]]);
                pb1 = *reinterpret_cast<const float4*>(&B[(size_t)(n0 + lr[i1]) * K + kn + lc[i1]]);
            }

            // compute 2 of the 4 ks sub-steps on the current buffer
#pragma unroll
            for (int s = 0; s < 2; s++) {
                const int ks = half * 16 + s * 8;
                uint32_t a[2][4];
#pragma unroll
                for (int mt = 0; mt < 2; mt++) {
                    const int r = wm + mt * 16 + g;
                    a[mt][0] = Au[r * 36 + ks + t4];
                    a[mt][1] = Au[(r + 8) * 36 + ks + t4];
                    a[mt][2] = Au[r * 36 + ks + t4 + 4];
                    a[mt][3] = Au[(r + 8) * 36 + ks + t4 + 4];
                }
                // nt in two groups of 4 to cap b-frag registers
#pragma unroll
                for (int grp = 0; grp < 2; grp++) {
                    uint32_t b[4][2];
#pragma unroll
                    for (int q = 0; q < 4; q++) {
                        const int r = wn + (grp * 4 + q) * 8 + g;
                        b[q][0] = Bu[r * 36 + ks + t4];
                        b[q][1] = Bu[r * 36 + ks + t4 + 4];
                    }
#pragma unroll
                    for (int mt = 0; mt < 2; mt++)
#pragma unroll
                        for (int q = 0; q < 4; q++)
                            MMA_TF32(acc[mt][grp * 4 + q], a[mt], b[q]);
                }
            }

            // store this half's prefetch into the other buffer
            if (has_next) {
                const int i0 = half * 2, i1 = half * 2 + 1;
                cvt_store<36>(As[buf ^ 1], lr[i0], lc[i0], pa0);
                cvt_store<36>(As[buf ^ 1], lr[i1], lc[i1], pa1);
                cvt_store<36>(Bs[buf ^ 1], lr[i0], lc[i0], pb0);
                cvt_store<36>(Bs[buf ^ 1], lr[i1], lc[i1], pb1);
            }
        }

        if (has_next) {
            __syncthreads();
            buf ^= 1;
        }
    }

#pragma unroll
    for (int mt = 0; mt < 2; mt++) {
#pragma unroll
        for (int nt = 0; nt < 8; nt++) {
            const int row = m0 + wm + mt * 16 + g;
            const int col = n0 + wn + nt * 8 + t4 * 2;
            *reinterpret_cast<float2*>(&C[(size_t)row * N + col]) =
                make_float2(acc[mt][nt][0], acc[mt][nt][1]);
            *reinterpret_cast<float2*>(&C[(size_t)(row + 8) * N + col]) =
                make_float2(acc[mt][nt][2], acc[mt][nt][3]);
        }
    }
}

__global__ __launch_bounds__(256, 2) void mma_qkv_kernel(const float* __restrict__ X,
                                                         const float* __restrict__ W)
{
    mma_gemm_body<L_, T3_, HID_>(X, W, g_qkv);
}

__global__ __launch_bounds__(256, 2) void mma_o_kernel(const float* __restrict__ W,
                                                       float* __restrict__ out)
{
    mma_gemm_body<L_, HID_, QS_>(g_attn, W, out);
}

// ---------------- dt = softplus(X @ Wdt^T + b + dt_bias); A = -exp(A_log)*dt -----
__global__ __launch_bounds__(512) void dt_kernel(const float* __restrict__ X,
                                                 const float* __restrict__ W,
                                                 const float* __restrict__ b,
                                                 const float* __restrict__ dt_bias,
                                                 const float* __restrict__ A_log)
{
    const int l = blockIdx.x;
    const int warp = threadIdx.x >> 5;
    const int lane = threadIdx.x & 31;
    const float* x = X + (size_t)l * HID_;
    const float* w = W + (size_t)warp * HID_;
    float s = 0.f;
#pragma unroll 8
    for (int k = lane; k < HID_; k += 32) s = fmaf(x[k], w[k], s);
#pragma unroll
    for (int o = 16; o; o >>= 1) s += __shfl_xor_sync(0xffffffffu, s, o);
    if (lane == 0) {
        float xv = s + b[warp] + dt_bias[warp];
        float dt = (xv > 20.f) ? xv : log1pf(expf(xv));
        g_dt[warp * L_ + l]   = dt;
        g_Adec[warp * L_ + l] = -expf(A_log[warp]) * dt;
    }
}

// ---------------- per-head inclusive cumsum over L -------------------------------
__global__ __launch_bounds__(256) void cumsum_kernel()
{
    const int h = blockIdx.x;
    __shared__ float wsum[8];
    __shared__ float carry_s;
    const int tid = threadIdx.x, lane = tid & 31, warp = tid >> 5;
    if (tid == 0) carry_s = 0.f;
    __syncthreads();
    for (int base = 0; base < L_; base += 256) {
        float x = g_Adec[h * L_ + base + tid];
#pragma unroll
        for (int o = 1; o < 32; o <<= 1) {
            float t = __shfl_up_sync(0xffffffffu, x, o);
            if (lane >= o) x += t;
        }
        if (lane == 31) wsum[warp] = x;
        __syncthreads();
        if (tid < 8) {
            float w = wsum[tid];
#pragma unroll
            for (int o = 1; o < 8; o <<= 1) {
                float t = __shfl_up_sync(0xffu, w, o);
                if (tid >= o) w += t;
            }
            wsum[tid] = w;
        }
        __syncthreads();
        float pre = (warp > 0 ? wsum[warp - 1] : 0.f) + carry_s;
        float outv = x + pre;
        g_ca[h * L_ + base + tid] = outv;
        __syncthreads();
        if (tid == 255) carry_s = outv;
        __syncthreads();
    }
}

// ---------------- causal depthwise conv (K=2) + head split + v*dt (float4) -------
__global__ __launch_bounds__(256) void conv_kernel(const float* __restrict__ qcw,
                                                   const float* __restrict__ qcb,
                                                   const float* __restrict__ kcw,
                                                   const float* __restrict__ kcb,
                                                   const float* __restrict__ vcw,
                                                   const float* __restrict__ vcb)
{
    const int idx = blockIdx.x * 256 + threadIdx.x;   // L_*256 total
    const int l  = idx >> 8;
    const int c4 = (idx & 255) << 2;                  // channel group (4 consecutive)
    const int h  = c4 >> 6;
    const int d  = c4 & 63;
    const float* row  = g_qkv + (size_t)l * T3_;
    const float* prow = g_qkv + (size_t)(l - 1) * T3_;
    const bool hasp = (l > 0);
    const float4 z = make_float4(0.f, 0.f, 0.f, 0.f);

    float4 qc = *reinterpret_cast<const float4*>(&row[c4]);
    float4 kc = *reinterpret_cast<const float4*>(&row[QS_ + c4]);
    float4 vc = *reinterpret_cast<const float4*>(&row[2 * QS_ + c4]);
    float4 qp = hasp ? *reinterpret_cast<const float4*>(&prow[c4]) : z;
    float4 kp = hasp ? *reinterpret_cast<const float4*>(&prow[QS_ + c4]) : z;
    float4 vp = hasp ? *reinterpret_cast<const float4*>(&prow[2 * QS_ + c4]) : z;

    // weights: [channel][2] layout -> per 4 channels, 8 floats
    float4 qw0 = *reinterpret_cast<const float4*>(&qcw[2 * c4]);       // ch0:{w0,w1} ch1:{w0,w1}
    float4 qw1 = *reinterpret_cast<const float4*>(&qcw[2 * c4 + 4]);
    float4 kw0 = *reinterpret_cast<const float4*>(&kcw[2 * c4]);
    float4 kw1 = *reinterpret_cast<const float4*>(&kcw[2 * c4 + 4]);
    float4 vw0 = *reinterpret_cast<const float4*>(&vcw[2 * c4]);
    float4 vw1 = *reinterpret_cast<const float4*>(&vcw[2 * c4 + 4]);
    float4 qb = *reinterpret_cast<const float4*>(&qcb[c4]);
    float4 kb = *reinterpret_cast<const float4*>(&kcb[c4]);
    float4 vb = *reinterpret_cast<const float4*>(&vcb[c4]);

    const float dtv = g_dt[h * L_ + l];

    float4 qo, ko, vo;
    qo.x = fmaf(qc.x, qw0.y, fmaf(qp.x, qw0.x, qb.x));
    qo.y = fmaf(qc.y, qw0.w, fmaf(qp.y, qw0.z, qb.y));
    qo.z = fmaf(qc.z, qw1.y, fmaf(qp.z, qw1.x, qb.z));
    qo.w = fmaf(qc.w, qw1.w, fmaf(qp.w, qw1.z, qb.w));
    ko.x = fmaf(kc.x, kw0.y, fmaf(kp.x, kw0.x, kb.x));
    ko.y = fmaf(kc.y, kw0.w, fmaf(kp.y, kw0.z, kb.y));
    ko.z = fmaf(kc.z, kw1.y, fmaf(kp.z, kw1.x, kb.z));
    ko.w = fmaf(kc.w, kw1.w, fmaf(kp.w, kw1.z, kb.w));
    vo.x = fmaf(vc.x, vw0.y, fmaf(vp.x, vw0.x, vb.x)) * dtv;
    vo.y = fmaf(vc.y, vw0.w, fmaf(vp.y, vw0.z, vb.y)) * dtv;
    vo.z = fmaf(vc.z, vw1.y, fmaf(vp.z, vw1.x, vb.z)) * dtv;
    vo.w = fmaf(vc.w, vw1.w, fmaf(vp.w, vw1.z, vb.w)) * dtv;

    const size_t o = ((size_t)h * L_ + l) * DH_ + d;
    *reinterpret_cast<float4*>(&g_q[o]) = qo;
    *reinterpret_cast<float4*>(&g_k[o]) = ko;
    *reinterpret_cast<float4*>(&g_v[o]) = vo;
}

// =================================================================================
// Chunked linear attention (exact factorization of the decay weights)
// =================================================================================
#define AT_NW 68

// ---- Phase A: per-chunk decayed outer product M'[e][d] = sum_m v[m,e]*k'[m,d] ----
__global__ __launch_bounds__(128) void kv_outer_kernel()
{
    __shared__ __align__(16) float Kt[64 * AT_NW];   // [d][m]
    __shared__ __align__(16) float Vt2[64 * AT_NW];  // [e][m]

    const int c = blockIdx.x, h = blockIdx.y;
    const int m0 = c * 64;
    const int tid = threadIdx.x, lane = tid & 31, w = tid >> 5;
    const int g = lane >> 2, t4 = lane & 3;
    const int wl = w * 16;
    const float* ca = g_ca + h * L_;
    const float* kh = g_k + (size_t)h * L_ * DH_;
    const float* vh = g_v + (size_t)h * L_ * DH_;
    const float bnext = ca[(c + 1) * 64];

    const int d0 = w * 16;
    int m = lane;
#pragma unroll
    for (int half = 0; half < 2; half++, m += 32) {
        const float wm = __expf(bnext - ca[m0 + m]);
#pragma unroll
        for (int i = 0; i < 4; i++) {
            float4 kx = *reinterpret_cast<const float4*>(&kh[(size_t)(m0 + m) * DH_ + d0 + i * 4]);
            Kt[(d0 + i * 4 + 0) * AT_NW + m] = f2tf32f(kx.x * wm);
            Kt[(d0 + i * 4 + 1) * AT_NW + m] = f2tf32f(kx.y * wm);
            Kt[(d0 + i * 4 + 2) * AT_NW + m] = f2tf32f(kx.z * wm);
            Kt[(d0 + i * 4 + 3) * AT_NW + m] = f2tf32f(kx.w * wm);
            float4 vx = *reinterpret_cast<const float4*>(&vh[(size_t)(m0 + m) * DH_ + d0 + i * 4]);
            Vt2[(d0 + i * 4 + 0) * AT_NW + m] = f2tf32f(vx.x);
            Vt2[(d0 + i * 4 + 1) * AT_NW + m] = f2tf32f(vx.y);
            Vt2[(d0 + i * 4 + 2) * AT_NW + m] = f2tf32f(vx.z);
            Vt2[(d0 + i * 4 + 3) * AT_NW + m] = f2tf32f(vx.w);
        }
    }
    __syncthreads();

    float acc[8][4];
#pragma unroll
    for (int nt = 0; nt < 8; nt++)
#pragma unroll
        for (int e = 0; e < 4; e++) acc[nt][e] = 0.f;

    const uint32_t* Vu = reinterpret_cast<const uint32_t*>(Vt2);
    const uint32_t* Ku = reinterpret_cast<const uint32_t*>(Kt);
#pragma unroll
    for (int ko = 0; ko < 8; ko++) {
        uint32_t a[4];
        a[0] = Vu[(wl + g) * AT_NW + ko * 8 + t4];
        a[1] = Vu[(wl + g + 8) * AT_NW + ko * 8 + t4];
        a[2] = Vu[(wl + g) * AT_NW + ko * 8 + t4 + 4];
        a[3] = Vu[(wl + g + 8) * AT_NW + ko * 8 + t4 + 4];
#pragma unroll
        for (int nt = 0; nt < 8; nt++) {
            uint32_t b[2];
            b[0] = Ku[(nt * 8 + g) * AT_NW + ko * 8 + t4];
            b[1] = Ku[(nt * 8 + g) * AT_NW + ko * 8 + t4 + 4];
            MMA_TF32(acc[nt], a, b);
        }
    }

    float* Md = g_M + ((size_t)(h * NCH_ + c) << 12);
#pragma unroll
    for (int nt = 0; nt < 8; nt++) {
        const int dc = nt * 8 + 2 * t4;
        *reinterpret_cast<float2*>(&Md[(wl + g) * 64 + dc])     = make_float2(acc[nt][0], acc[nt][1]);
        *reinterpret_cast<float2*>(&Md[(wl + g + 8) * 64 + dc]) = make_float2(acc[nt][2], acc[nt][3]);
    }
}

// ---- Phase B: per-head state scan, depth-2 register prefetch. grid H, 1024 thr --
__global__ __launch_bounds__(1024) void state_scan_kernel()
{
    const int h = blockIdx.x, t = threadIdx.x;
    __shared__ float decs[NCH_];
    if (t < NCH_) {
        const float* ca = g_ca + h * L_;
        decs[t] = (t < NCH_ - 1) ? __expf(ca[(t + 1) * 64] - ca[t * 64]) : 0.f;
    }
    __syncthreads();

    const float* Mbase = g_M + ((size_t)h * NCH_ << 12);
    float* Sbase = g_state + ((size_t)h * NCH_ << 12);
    const int off = t * 4;

    float4 st = make_float4(0.f, 0.f, 0.f, 0.f);
    float4 mbuf0 = *reinterpret_cast<const float4*>(&Mbase[off]);
    float4 mbuf1 = *reinterpret_cast<const float4*>(&Mbase[(1 << 12) + off]);

    for (int c = 0; c < NCH_; c++) {
        *reinterpret_cast<float4*>(&Sbase[((size_t)c << 12) + off]) = st;
        if (c < NCH_ - 1) {
            const float dec = decs[c];
            st.x = fmaf(st.x, dec, mbuf0.x);
            st.y = fmaf(st.y, dec, mbuf0.y);
            st.z = fmaf(st.z, dec, mbuf0.z);
            st.w = fmaf(st.w, dec, mbuf0.w);
            mbuf0 = mbuf1;
            if (c + 2 < NCH_)
                mbuf1 = *reinterpret_cast<const float4*>(&Mbase[((size_t)(c + 2) << 12) + off]);
        }
    }
}

// ---- Phase C: diagonal tile (intra) + q.State (inter), fused RMSNorm ------------
__global__ __launch_bounds__(128) void attn_mma_kernel(const float* __restrict__ norm_w,
                                                       const float* __restrict__ order_coeff)
{
    __shared__ __align__(16) float KSs[64 * AT_NW];   // Q staging -> K -> weighted S
    __shared__ __align__(16) float Vt[64 * AT_NW];    // State' -> V^T

    const int h    = blockIdx.y;
    const int lt   = blockIdx.x;
    const int l0   = lt * 64;
    const int tid  = threadIdx.x;
    const int lane = tid & 31;
    const int w    = tid >> 5;
    const int g    = lane >> 2;
    const int t4   = lane & 3;
    const int wl   = w * 16;

    const float* qh = g_q + (size_t)h * L_ * DH_;
    const float* kh = g_k + (size_t)h * L_ * DH_;
    const float* vh = g_v + (size_t)h * L_ * DH_;
    const float* ca = g_ca + h * L_;
    const float lc  = __logf(1.f / order_coeff[h]);

    const float* Sg = g_state + ((size_t)(h * NCH_ + lt) << 12);
    for (int f = tid; f < 1024; f += 128) {
        int row = f >> 4, c4 = (f & 15) << 2;
        cvt_store<AT_NW>(KSs, row, c4,
            *reinterpret_cast<const float4*>(&qh[(size_t)(l0 + row) * DH_ + c4]));
        cvt_store<AT_NW>(Vt, row, c4,
            *reinterpret_cast<const float4*>(&Sg[row * 64 + c4]));
    }
    __syncthreads();

    uint32_t qa[8][4];
    {
        const uint32_t* Qu = reinterpret_cast<const uint32_t*>(KSs);
#pragma unroll
        for (int ko = 0; ko < 8; ko++) {
            qa[ko][0] = Qu[(wl + g) * AT_NW + ko * 8 + t4];
            qa[ko][1] = Qu[(wl + g + 8) * AT_NW + ko * 8 + t4];
            qa[ko][2] = Qu[(wl + g) * AT_NW + ko * 8 + t4 + 4];
            qa[ko][3] = Qu[(wl + g + 8) * AT_NW + ko * 8 + t4 + 4];
        }
    }
    const float cl0 = ca[l0 + wl + g] + lc;
    const float cl1 = ca[l0 + wl + g + 8] + lc;
    const float bc  = ca[l0];
    const float iw0 = __expf(cl0 - bc);
    const float iw1 = __expf(cl1 - bc);

    float accO[8][4];
#pragma unroll
    for (int nt = 0; nt < 8; nt++)
#pragma unroll
        for (int e = 0; e < 4; e++) accO[nt][e] = 0.f;

    {
        const uint32_t* Su = reinterpret_cast<const uint32_t*>(Vt);
#pragma unroll
        for (int ko = 0; ko < 8; ko++) {
            uint32_t b[8][2];
#pragma unroll
            for (int nt = 0; nt < 8; nt++) {
                b[nt][0] = Su[(nt * 8 + g) * AT_NW + ko * 8 + t4];
                b[nt][1] = Su[(nt * 8 + g) * AT_NW + ko * 8 + t4 + 4];
            }
#pragma unroll
            for (int nt = 0; nt < 8; nt++)
                MMA_TF32(accO[nt], qa[ko], b[nt]);
        }
#pragma unroll
        for (int nt = 0; nt < 8; nt++) {
            accO[nt][0] *= iw0;
            accO[nt][1] *= iw0;
            accO[nt][2] *= iw1;
            accO[nt][3] *= iw1;
        }
    }
    __syncthreads();

    for (int f = tid; f < 1024; f += 128) {
        int row = f >> 4, c4 = (f & 15) << 2;
        cvt_store<AT_NW>(KSs, row, c4,
            *reinterpret_cast<const float4*>(&kh[(size_t)(l0 + row) * DH_ + c4]));
    }
    {
        const int d0 = w * 16;
        int m = lane;
#pragma unroll
        for (int half = 0; half < 2; half++, m += 32) {
#pragma unroll
            for (int i = 0; i < 4; i++) {
                float4 x = *reinterpret_cast<const float4*>(
                    &vh[(size_t)(l0 + m) * DH_ + d0 + i * 4]);
                Vt[(d0 + i * 4 + 0) * AT_NW + m] = f2tf32f(x.x);
                Vt[(d0 + i * 4 + 1) * AT_NW + m] = f2tf32f(x.y);
                Vt[(d0 + i * 4 + 2) * AT_NW + m] = f2tf32f(x.z);
                Vt[(d0 + i * 4 + 3) * AT_NW + m] = f2tf32f(x.w);
            }
        }
    }
    __syncthreads();

    float sfr[8][4];
#pragma unroll
    for (int nt = 0; nt < 8; nt++)
#pragma unroll
        for (int e = 0; e < 4; e++) sfr[nt][e] = 0.f;

    {
        const uint32_t* Ku = reinterpret_cast<const uint32_t*>(KSs);
#pragma unroll
        for (int ko = 0; ko < 8; ko++) {
            uint32_t b[8][2];
#pragma unroll
            for (int nt = 0; nt < 8; nt++) {
                b[nt][0] = Ku[(nt * 8 + g) * AT_NW + ko * 8 + t4];
                b[nt][1] = Ku[(nt * 8 + g) * AT_NW + ko * 8 + t4 + 4];
            }
#pragma unroll
            for (int nt = 0; nt < 8; nt++)
                MMA_TF32(sfr[nt], qa[ko], b[nt]);
        }
    }

    const int gl0 = l0 + wl + g, gl1 = gl0 + 8;
#pragma unroll
    for (int nt = 0; nt < 8; nt++) {
        const int gm0 = l0 + nt * 8 + 2 * t4;
        const int gm1 = gm0 + 1;
        const float cm0 = ca[gm0], cm1 = ca[gm1];
        sfr[nt][0] *= (gm0 <= gl0) ? __expf(cl0 - cm0) : 0.f;
        sfr[nt][1] *= (gm1 <= gl0) ? __expf(cl0 - cm1) : 0.f;
        sfr[nt][2] *= (gm0 <= gl1) ? __expf(cl1 - cm0) : 0.f;
        sfr[nt][3] *= (gm1 <= gl1) ? __expf(cl1 - cm1) : 0.f;
    }
    __syncthreads();

#pragma unroll
    for (int nt = 0; nt < 8; nt++) {
        const int cc = nt * 8 + 2 * t4;
        *reinterpret_cast<float2*>(&KSs[(wl + g) * AT_NW + cc]) =
            make_float2(f2tf32f(sfr[nt][0]), f2tf32f(sfr[nt][1]));
        *reinterpret_cast<float2*>(&KSs[(wl + g + 8) * AT_NW + cc]) =
            make_float2(f2tf32f(sfr[nt][2]), f2tf32f(sfr[nt][3]));
    }
    __syncwarp();

    {
        const uint32_t* Su = reinterpret_cast<const uint32_t*>(KSs);
        const uint32_t* Vu = reinterpret_cast<const uint32_t*>(Vt);
#pragma unroll
        for (int ko = 0; ko < 8; ko++) {
            uint32_t a[4];
            a[0] = Su[(wl + g) * AT_NW + ko * 8 + t4];
            a[1] = Su[(wl + g + 8) * AT_NW + ko * 8 + t4];
            a[2] = Su[(wl + g) * AT_NW + ko * 8 + t4 + 4];
            a[3] = Su[(wl + g + 8) * AT_NW + ko * 8 + t4 + 4];
#pragma unroll
            for (int nt = 0; nt < 8; nt++) {
                uint32_t b[2];
                b[0] = Vu[(nt * 8 + g) * AT_NW + ko * 8 + t4];
                b[1] = Vu[(nt * 8 + g) * AT_NW + ko * 8 + t4 + 4];
                MMA_TF32(accO[nt], a, b);
            }
        }
    }

    float ss0 = 0.f, ss1 = 0.f;
#pragma unroll
    for (int nt = 0; nt < 8; nt++) {
        ss0 = fmaf(accO[nt][0], accO[nt][0], ss0);
        ss0 = fmaf(accO[nt][1], accO[nt][1], ss0);
        ss1 = fmaf(accO[nt][2], accO[nt][2], ss1);
        ss1 = fmaf(accO[nt][3], accO[nt][3], ss1);
    }
    ss0 += __shfl_xor_sync(0xffffffffu, ss0, 1);
    ss0 += __shfl_xor_sync(0xffffffffu, ss0, 2);
    ss1 += __shfl_xor_sync(0xffffffffu, ss1, 1);
    ss1 += __shfl_xor_sync(0xffffffffu, ss1, 2);
    const float r0 = rsqrtf(ss0 * (1.f / 64.f) + EPS_);
    const float r1 = rsqrtf(ss1 * (1.f / 64.f) + EPS_);

#pragma unroll
    for (int nt = 0; nt < 8; nt++) {
        const int dc = nt * 8 + 2 * t4;
        const float2 nw = *reinterpret_cast<const float2*>(&norm_w[dc]);
        const int col = h * DH_ + dc;
        *reinterpret_cast<float2*>(&g_attn[(size_t)(l0 + wl + g) * QS_ + col]) =
            make_float2(accO[nt][0] * r0 * nw.x, accO[nt][1] * r0 * nw.y);
        *reinterpret_cast<float2*>(&g_attn[(size_t)(l0 + wl + g + 8) * QS_ + col]) =
            make_float2(accO[nt][2] * r1 * nw.x, accO[nt][3] * r1 * nw.y);
    }
}

// ---------------- launch ---------------------------------------------------------
#define GEMM_SMEM (4 * GS_ * (int)sizeof(float))   // 73728 bytes

extern "C" void kernel_launch(void* const* d_in, const int* in_sizes, int n_in,
                              void* d_out, int out_size)
{
    const float* hidden    = (const float*)d_in[0];
    // d_in[1] = attention_mask (causal triu) — structurally known, unused
    const float* qkv_w     = (const float*)d_in[2];
    const float* q_conv_w  = (const float*)d_in[3];
    const float* q_conv_b  = (const float*)d_in[4];
    const float* k_conv_w  = (const float*)d_in[5];
    const float* k_conv_b  = (const float*)d_in[6];
    const float* v_conv_w  = (const float*)d_in[7];
    const float* v_conv_b  = (const float*)d_in[8];
    const float* norm_w    = (const float*)d_in[9];
    const float* A_log     = (const float*)d_in[10];
    const float* dt_bias   = (const float*)d_in[11];
    const float* dt_proj_w = (const float*)d_in[12];
    const float* dt_proj_b = (const float*)d_in[13];
    const float* o_w       = (const float*)d_in[14];
    const float* order_c   = (const float*)d_in[15];
    float* out = (float*)d_out;

    static int attr_done = 0;
    if (!attr_done) {
        cudaFuncSetAttribute(mma_qkv_kernel, cudaFuncAttributeMaxDynamicSharedMemorySize, GEMM_SMEM);
        cudaFuncSetAttribute(mma_o_kernel,   cudaFuncAttributeMaxDynamicSharedMemorySize, GEMM_SMEM);
        attr_done = 1;
    }

    mma_qkv_kernel<<<dim3(T3_ / 128, L_ / 128), 256, GEMM_SMEM>>>(hidden, qkv_w);
    dt_kernel<<<L_, 512>>>(hidden, dt_proj_w, dt_proj_b, dt_bias, A_log);
    cumsum_kernel<<<H_, 256>>>();
    conv_kernel<<<(L_ * 256) / 256, 256>>>(q_conv_w, q_conv_b, k_conv_w, k_conv_b,
                                           v_conv_w, v_conv_b);
    kv_outer_kernel<<<dim3(NCH_ - 1, H_), 128>>>();
    state_scan_kernel<<<H_, 1024>>>();
    attn_mma_kernel<<<dim3(NCH_, H_), 128>>>(norm_w, order_c);
    mma_o_kernel<<<dim3(HID_ / 128, L_ / 128), 256, GEMM_SMEM>>>(o_w, out);
}

// round 8
// speedup vs baseline: 3.6299x; 1.0857x over previous
#include <cuda_runtime.h>
#include <stdint.h>
#include <math.h>

#define L_    2048
#define HID_  1024
#define H_    16
#define DH_   64
#define QS_   1024
#define T3_   3072
#define NCH_  32          // chunks of 64
#define EPS_  1.1920929e-07f

// ---------------- scratch (device globals; no allocation allowed) ----------------
__device__ float g_qkv[L_ * T3_];          // (L, 3072)
__device__ float g_q[H_ * L_ * DH_];       // (H, L, DH)
__device__ float g_k[H_ * L_ * DH_];
__device__ float g_v[H_ * L_ * DH_];       // pre-scaled by dt
__device__ float g_dt[H_ * L_];
__device__ float g_Adec[H_ * L_];
__device__ float g_ca[H_ * L_];            // cumsum of A per head
__device__ float g_attn[L_ * QS_];         // (L, H*DH) post-RMSNorm
__device__ float g_M[H_ * NCH_ * DH_ * DH_];      // per-chunk decayed outer products [e][d]
__device__ float g_state[H_ * NCH_ * DH_ * DH_];  // scanned states [e][d]

// =================================================================================
// tf32 mma.sync helpers
// =================================================================================
#define MMA_TF32(D, Ar, Br)                                                        \
    asm volatile("mma.sync.aligned.m16n8k8.row.col.f32.tf32.tf32.f32 "             \
                 "{%0,%1,%2,%3}, {%4,%5,%6,%7}, {%8,%9}, {%0,%1,%2,%3};"           \
                 : "+f"((D)[0]), "+f"((D)[1]), "+f"((D)[2]), "+f"((D)[3])          \
                 : "r"((Ar)[0]), "r"((Ar)[1]), "r"((Ar)[2]), "r"((Ar)[3]),         \
                   "r"((Br)[0]), "r"((Br)[1]))

__device__ __forceinline__ uint32_t f2tf32(float x) {
    uint32_t u;
    asm("cvt.rna.tf32.f32 %0, %1;" : "=r"(u) : "f"(x));
    return u;
}
__device__ __forceinline__ float f2tf32f(float x) { return __uint_as_float(f2tf32(x)); }

template <int STRIDE>
__device__ __forceinline__ void cvt_store(float* dst, int row, int cg, float4 x) {
    float4 y;
    y.x = f2tf32f(x.x);
    y.y = f2tf32f(x.y);
    y.z = f2tf32f(x.z);
    y.w = f2tf32f(x.w);
    *reinterpret_cast<float4*>(&dst[row * STRIDE + cg]) = y;
}

// =================================================================================
// TN GEMM on tensor pipe: CTA tile 128 x NT, K-step 32, double-buffered dyn smem.
// 256 threads = 8 warps (4m x 2n), warp tile 32 x NT/2. NT in {64, 96, 128}.
// Interleaved half-prefetch keeps register pressure low -> 2 CTAs/SM.
// =================================================================================
template <int M, int N, int K, int NT>
__device__ __forceinline__ void mma_gemm_body(const float* __restrict__ A,
                                              const float* __restrict__ B,
                                              float* __restrict__ C)
{
    constexpr int NTN = NT / 16;       // nt tiles per warp
    constexpr int BNV = NT / 32;       // B float4 loads per thread per stage
    constexpr int GSA = 128 * 36;
    constexpr int GSB = NT * 36;
    constexpr int SS  = GSA + GSB;

    extern __shared__ __align__(16) float smem_g[];

    const int tid  = threadIdx.x;
    const int lane = tid & 31;
    const int wid  = tid >> 5;
    const int g    = lane >> 2;
    const int t4   = lane & 3;
    const int m0   = blockIdx.y * 128;
    const int n0   = blockIdx.x * NT;
    const int wm   = (wid >> 1) * 32;
    const int wn   = (wid & 1) * (NT / 2);

    // loader coords
    int ar[4], ac[4];
#pragma unroll
    for (int r = 0; r < 4; r++) {
        const int v = tid + 256 * r;
        ar[r] = v >> 3;
        ac[r] = (v & 7) << 2;
    }
    int br_[BNV], bc_[BNV];
#pragma unroll
    for (int r = 0; r < BNV; r++) {
        const int v = tid + 256 * r;
        br_[r] = v >> 3;
        bc_[r] = (v & 7) << 2;
    }

    float acc[2][NTN][4];
#pragma unroll
    for (int mt = 0; mt < 2; mt++)
#pragma unroll
        for (int nt = 0; nt < NTN; nt++)
#pragma unroll
            for (int e = 0; e < 4; e++) acc[mt][nt][e] = 0.f;

    // prologue: fill buffer 0
#pragma unroll
    for (int r = 0; r < 4; r++)
        cvt_store<36>(smem_g, ar[r], ac[r],
            *reinterpret_cast<const float4*>(&A[(size_t)(m0 + ar[r]) * K + ac[r]]));
#pragma unroll
    for (int r = 0; r < BNV; r++)
        cvt_store<36>(smem_g + GSA, br_[r], bc_[r],
            *reinterpret_cast<const float4*>(&B[(size_t)(n0 + br_[r]) * K + bc_[r]]));
    __syncthreads();

    int buf = 0;
    for (int k0 = 0; k0 < K; k0 += 32) {
        const bool has_next = (k0 + 32) < K;
        const int kn = k0 + 32;
        const uint32_t* Au = reinterpret_cast<const uint32_t*>(smem_g + buf * SS);
        const uint32_t* Bu = reinterpret_cast<const uint32_t*>(smem_g + buf * SS + GSA);
        float* Asn = smem_g + (buf ^ 1) * SS;
        float* Bsn = smem_g + (buf ^ 1) * SS + GSA;

#pragma unroll
        for (int half = 0; half < 2; half++) {
            const int b_lo = (BNV * half) / 2;
            const int b_hi = (BNV * (half + 1)) / 2;

            float4 pa[2], pb[2];
            if (has_next) {
#pragma unroll
                for (int r = 0; r < 2; r++) {
                    const int i = half * 2 + r;
                    pa[r] = *reinterpret_cast<const float4*>(&A[(size_t)(m0 + ar[i]) * K + kn + ac[i]]);
                }
#pragma unroll
                for (int r = b_lo; r < b_hi; r++)
                    pb[r - b_lo] = *reinterpret_cast<const float4*>(&B[(size_t)(n0 + br_[r]) * K + kn + bc_[r]]);
            }

#pragma unroll
            for (int s = 0; s < 2; s++) {
                const int ks = half * 16 + s * 8;
                uint32_t a[2][4];
#pragma unroll
                for (int mt = 0; mt < 2; mt++) {
                    const int r = wm + mt * 16 + g;
                    a[mt][0] = Au[r * 36 + ks + t4];
                    a[mt][1] = Au[(r + 8) * 36 + ks + t4];
                    a[mt][2] = Au[r * 36 + ks + t4 + 4];
                    a[mt][3] = Au[(r + 8) * 36 + ks + t4 + 4];
                }
#pragma unroll
                for (int grp = 0; grp < NTN / 2; grp++) {
                    uint32_t b[2][2];
#pragma unroll
                    for (int q = 0; q < 2; q++) {
                        const int r = wn + (grp * 2 + q) * 8 + g;
                        b[q][0] = Bu[r * 36 + ks + t4];
                        b[q][1] = Bu[r * 36 + ks + t4 + 4];
                    }
#pragma unroll
                    for (int mt = 0; mt < 2; mt++)
#pragma unroll
                        for (int q = 0; q < 2; q++)
                            MMA_TF32(acc[mt][grp * 2 + q], a[mt], b[q]);
                }
            }

            if (has_next) {
#pragma unroll
                for (int r = 0; r < 2; r++) {
                    const int i = half * 2 + r;
                    cvt_store<36>(Asn, ar[i], ac[i], pa[r]);
                }
#pragma unroll
                for (int r = b_lo; r < b_hi; r++)
                    cvt_store<36>(Bsn, br_[r], bc_[r], pb[r - b_lo]);
            }
        }

        if (has_next) {
            __syncthreads();
            buf ^= 1;
        }
    }

#pragma unroll
    for (int mt = 0; mt < 2; mt++) {
#pragma unroll
        for (int nt = 0; nt < NTN; nt++) {
            const int row = m0 + wm + mt * 16 + g;
            const int col = n0 + wn + nt * 8 + t4 * 2;
            *reinterpret_cast<float2*>(&C[(size_t)row * N + col]) =
                make_float2(acc[mt][nt][0], acc[mt][nt][1]);
            *reinterpret_cast<float2*>(&C[(size_t)(row + 8) * N + col]) =
                make_float2(acc[mt][nt][2], acc[mt][nt][3]);
        }
    }
}

__global__ __launch_bounds__(256, 2) void mma_qkv_kernel(const float* __restrict__ X,
                                                         const float* __restrict__ W)
{
    mma_gemm_body<L_, T3_, HID_, 96>(X, W, g_qkv);
}

__global__ __launch_bounds__(256, 2) void mma_o_kernel(const float* __restrict__ W,
                                                       float* __restrict__ out)
{
    mma_gemm_body<L_, HID_, QS_, 64>(g_attn, W, out);
}

// ---------------- dt = softplus(X @ Wdt^T + b + dt_bias); A = -exp(A_log)*dt -----
// 8 rows per block; W rows held in registers (one warp per head).
__global__ __launch_bounds__(512) void dt_kernel(const float* __restrict__ X,
                                                 const float* __restrict__ W,
                                                 const float* __restrict__ b,
                                                 const float* __restrict__ dt_bias,
                                                 const float* __restrict__ A_log)
{
    const int l0 = blockIdx.x * 8;
    const int warp = threadIdx.x >> 5;   // head
    const int lane = threadIdx.x & 31;
    const float* w = W + (size_t)warp * HID_;

    float wreg[32];
#pragma unroll
    for (int j = 0; j < 32; j++) wreg[j] = w[lane + 32 * j];

    const float bb = b[warp] + dt_bias[warp];
    const float nA = -expf(A_log[warp]);

    for (int r = 0; r < 8; r++) {
        const int l = l0 + r;
        const float* x = X + (size_t)l * HID_;
        float s = 0.f;
#pragma unroll
        for (int j = 0; j < 32; j++) s = fmaf(x[lane + 32 * j], wreg[j], s);
#pragma unroll
        for (int o = 16; o; o >>= 1) s += __shfl_xor_sync(0xffffffffu, s, o);
        if (lane == 0) {
            float xv = s + bb;
            float dt = (xv > 20.f) ? xv : log1pf(expf(xv));
            g_dt[warp * L_ + l]   = dt;
            g_Adec[warp * L_ + l] = nA * dt;
        }
    }
}

// ---------------- per-head inclusive cumsum over L -------------------------------
__global__ __launch_bounds__(256) void cumsum_kernel()
{
    const int h = blockIdx.x;
    __shared__ float wsum[8];
    __shared__ float carry_s;
    const int tid = threadIdx.x, lane = tid & 31, warp = tid >> 5;
    if (tid == 0) carry_s = 0.f;
    __syncthreads();
    for (int base = 0; base < L_; base += 256) {
        float x = g_Adec[h * L_ + base + tid];
#pragma unroll
        for (int o = 1; o < 32; o <<= 1) {
            float t = __shfl_up_sync(0xffffffffu, x, o);
            if (lane >= o) x += t;
        }
        if (lane == 31) wsum[warp] = x;
        __syncthreads();
        if (tid < 8) {
            float w = wsum[tid];
#pragma unroll
            for (int o = 1; o < 8; o <<= 1) {
                float t = __shfl_up_sync(0xffu, w, o);
                if (tid >= o) w += t;
            }
            wsum[tid] = w;
        }
        __syncthreads();
        float pre = (warp > 0 ? wsum[warp - 1] : 0.f) + carry_s;
        float outv = x + pre;
        g_ca[h * L_ + base + tid] = outv;
        __syncthreads();
        if (tid == 255) carry_s = outv;
        __syncthreads();
    }
}

// ---------------- causal depthwise conv (K=2) + head split + v*dt (float4) -------
__global__ __launch_bounds__(256) void conv_kernel(const float* __restrict__ qcw,
                                                   const float* __restrict__ qcb,
                                                   const float* __restrict__ kcw,
                                                   const float* __restrict__ kcb,
                                                   const float* __restrict__ vcw,
                                                   const float* __restrict__ vcb)
{
    const int idx = blockIdx.x * 256 + threadIdx.x;   // L_*256 total
    const int l  = idx >> 8;
    const int c4 = (idx & 255) << 2;
    const int h  = c4 >> 6;
    const int d  = c4 & 63;
    const float* row  = g_qkv + (size_t)l * T3_;
    const float* prow = g_qkv + (size_t)(l - 1) * T3_;
    const bool hasp = (l > 0);
    const float4 z = make_float4(0.f, 0.f, 0.f, 0.f);

    float4 qc = *reinterpret_cast<const float4*>(&row[c4]);
    float4 kc = *reinterpret_cast<const float4*>(&row[QS_ + c4]);
    float4 vc = *reinterpret_cast<const float4*>(&row[2 * QS_ + c4]);
    float4 qp = hasp ? *reinterpret_cast<const float4*>(&prow[c4]) : z;
    float4 kp = hasp ? *reinterpret_cast<const float4*>(&prow[QS_ + c4]) : z;
    float4 vp = hasp ? *reinterpret_cast<const float4*>(&prow[2 * QS_ + c4]) : z;

    float4 qw0 = *reinterpret_cast<const float4*>(&qcw[2 * c4]);
    float4 qw1 = *reinterpret_cast<const float4*>(&qcw[2 * c4 + 4]);
    float4 kw0 = *reinterpret_cast<const float4*>(&kcw[2 * c4]);
    float4 kw1 = *reinterpret_cast<const float4*>(&kcw[2 * c4 + 4]);
    float4 vw0 = *reinterpret_cast<const float4*>(&vcw[2 * c4]);
    float4 vw1 = *reinterpret_cast<const float4*>(&vcw[2 * c4 + 4]);
    float4 qb = *reinterpret_cast<const float4*>(&qcb[c4]);
    float4 kb = *reinterpret_cast<const float4*>(&kcb[c4]);
    float4 vb = *reinterpret_cast<const float4*>(&vcb[c4]);

    const float dtv = g_dt[h * L_ + l];

    float4 qo, ko, vo;
    qo.x = fmaf(qc.x, qw0.y, fmaf(qp.x, qw0.x, qb.x));
    qo.y = fmaf(qc.y, qw0.w, fmaf(qp.y, qw0.z, qb.y));
    qo.z = fmaf(qc.z, qw1.y, fmaf(qp.z, qw1.x, qb.z));
    qo.w = fmaf(qc.w, qw1.w, fmaf(qp.w, qw1.z, qb.w));
    ko.x = fmaf(kc.x, kw0.y, fmaf(kp.x, kw0.x, kb.x));
    ko.y = fmaf(kc.y, kw0.w, fmaf(kp.y, kw0.z, kb.y));
    ko.z = fmaf(kc.z, kw1.y, fmaf(kp.z, kw1.x, kb.z));
    ko.w = fmaf(kc.w, kw1.w, fmaf(kp.w, kw1.z, kb.w));
    vo.x = fmaf(vc.x, vw0.y, fmaf(vp.x, vw0.x, vb.x)) * dtv;
    vo.y = fmaf(vc.y, vw0.w, fmaf(vp.y, vw0.z, vb.y)) * dtv;
    vo.z = fmaf(vc.z, vw1.y, fmaf(vp.z, vw1.x, vb.z)) * dtv;
    vo.w = fmaf(vc.w, vw1.w, fmaf(vp.w, vw1.z, vb.w)) * dtv;

    const size_t o = ((size_t)h * L_ + l) * DH_ + d;
    *reinterpret_cast<float4*>(&g_q[o]) = qo;
    *reinterpret_cast<float4*>(&g_k[o]) = ko;
    *reinterpret_cast<float4*>(&g_v[o]) = vo;
}

// =================================================================================
// Chunked linear attention (exact factorization of the decay weights)
// =================================================================================
#define AT_NW 68

// ---- Phase A: per-chunk decayed outer product M'[e][d] = sum_m v[m,e]*k'[m,d] ----
__global__ __launch_bounds__(128) void kv_outer_kernel()
{
    __shared__ __align__(16) float Kt[64 * AT_NW];   // [d][m]
    __shared__ __align__(16) float Vt2[64 * AT_NW];  // [e][m]

    const int c = blockIdx.x, h = blockIdx.y;
    const int m0 = c * 64;
    const int tid = threadIdx.x, lane = tid & 31, w = tid >> 5;
    const int g = lane >> 2, t4 = lane & 3;
    const int wl = w * 16;
    const float* ca = g_ca + h * L_;
    const float* kh = g_k + (size_t)h * L_ * DH_;
    const float* vh = g_v + (size_t)h * L_ * DH_;
    const float bnext = ca[(c + 1) * 64];

    const int d0 = w * 16;
    int m = lane;
#pragma unroll
    for (int half = 0; half < 2; half++, m += 32) {
        const float wm = __expf(bnext - ca[m0 + m]);
#pragma unroll
        for (int i = 0; i < 4; i++) {
            float4 kx = *reinterpret_cast<const float4*>(&kh[(size_t)(m0 + m) * DH_ + d0 + i * 4]);
            Kt[(d0 + i * 4 + 0) * AT_NW + m] = f2tf32f(kx.x * wm);
            Kt[(d0 + i * 4 + 1) * AT_NW + m] = f2tf32f(kx.y * wm);
            Kt[(d0 + i * 4 + 2) * AT_NW + m] = f2tf32f(kx.z * wm);
            Kt[(d0 + i * 4 + 3) * AT_NW + m] = f2tf32f(kx.w * wm);
            float4 vx = *reinterpret_cast<const float4*>(&vh[(size_t)(m0 + m) * DH_ + d0 + i * 4]);
            Vt2[(d0 + i * 4 + 0) * AT_NW + m] = f2tf32f(vx.x);
            Vt2[(d0 + i * 4 + 1) * AT_NW + m] = f2tf32f(vx.y);
            Vt2[(d0 + i * 4 + 2) * AT_NW + m] = f2tf32f(vx.z);
            Vt2[(d0 + i * 4 + 3) * AT_NW + m] = f2tf32f(vx.w);
        }
    }
    __syncthreads();

    float acc[8][4];
#pragma unroll
    for (int nt = 0; nt < 8; nt++)
#pragma unroll
        for (int e = 0; e < 4; e++) acc[nt][e] = 0.f;

    const uint32_t* Vu = reinterpret_cast<const uint32_t*>(Vt2);
    const uint32_t* Ku = reinterpret_cast<const uint32_t*>(Kt);
#pragma unroll
    for (int ko = 0; ko < 8; ko++) {
        uint32_t a[4];
        a[0] = Vu[(wl + g) * AT_NW + ko * 8 + t4];
        a[1] = Vu[(wl + g + 8) * AT_NW + ko * 8 + t4];
        a[2] = Vu[(wl + g) * AT_NW + ko * 8 + t4 + 4];
        a[3] = Vu[(wl + g + 8) * AT_NW + ko * 8 + t4 + 4];
#pragma unroll
        for (int nt = 0; nt < 8; nt++) {
            uint32_t b[2];
            b[0] = Ku[(nt * 8 + g) * AT_NW + ko * 8 + t4];
            b[1] = Ku[(nt * 8 + g) * AT_NW + ko * 8 + t4 + 4];
            MMA_TF32(acc[nt], a, b);
        }
    }

    float* Md = g_M + ((size_t)(h * NCH_ + c) << 12);
#pragma unroll
    for (int nt = 0; nt < 8; nt++) {
        const int dc = nt * 8 + 2 * t4;
        *reinterpret_cast<float2*>(&Md[(wl + g) * 64 + dc])     = make_float2(acc[nt][0], acc[nt][1]);
        *reinterpret_cast<float2*>(&Md[(wl + g + 8) * 64 + dc]) = make_float2(acc[nt][2], acc[nt][3]);
    }
}

// ---- Phase B: per-head state scan, depth-2 register prefetch. grid H, 1024 thr --
__global__ __launch_bounds__(1024) void state_scan_kernel()
{
    const int h = blockIdx.x, t = threadIdx.x;
    __shared__ float decs[NCH_];
    if (t < NCH_) {
        const float* ca = g_ca + h * L_;
        decs[t] = (t < NCH_ - 1) ? __expf(ca[(t + 1) * 64] - ca[t * 64]) : 0.f;
    }
    __syncthreads();

    const float* Mbase = g_M + ((size_t)h * NCH_ << 12);
    float* Sbase = g_state + ((size_t)h * NCH_ << 12);
    const int off = t * 4;

    float4 st = make_float4(0.f, 0.f, 0.f, 0.f);
    float4 mbuf0 = *reinterpret_cast<const float4*>(&Mbase[off]);
    float4 mbuf1 = *reinterpret_cast<const float4*>(&Mbase[(1 << 12) + off]);

    for (int c = 0; c < NCH_; c++) {
        *reinterpret_cast<float4*>(&Sbase[((size_t)c << 12) + off]) = st;
        if (c < NCH_ - 1) {
            const float dec = decs[c];
            st.x = fmaf(st.x, dec, mbuf0.x);
            st.y = fmaf(st.y, dec, mbuf0.y);
            st.z = fmaf(st.z, dec, mbuf0.z);
            st.w = fmaf(st.w, dec, mbuf0.w);
            mbuf0 = mbuf1;
            if (c + 2 < NCH_)
                mbuf1 = *reinterpret_cast<const float4*>(&Mbase[((size_t)(c + 2) << 12) + off]);
        }
    }
}

// ---- Phase C: diagonal tile (intra) + q.State (inter), fused RMSNorm ------------
__global__ __launch_bounds__(128) void attn_mma_kernel(const float* __restrict__ norm_w,
                                                       const float* __restrict__ order_coeff)
{
    __shared__ __align__(16) float KSs[64 * AT_NW];   // Q staging -> K -> weighted S
    __shared__ __align__(16) float Vt[64 * AT_NW];    // State' -> V^T

    const int h    = blockIdx.y;
    const int lt   = blockIdx.x;
    const int l0   = lt * 64;
    const int tid  = threadIdx.x;
    const int lane = tid & 31;
    const int w    = tid >> 5;
    const int g    = lane >> 2;
    const int t4   = lane & 3;
    const int wl   = w * 16;

    const float* qh = g_q + (size_t)h * L_ * DH_;
    const float* kh = g_k + (size_t)h * L_ * DH_;
    const float* vh = g_v + (size_t)h * L_ * DH_;
    const float* ca = g_ca + h * L_;
    const float lc  = __logf(1.f / order_coeff[h]);

    const float* Sg = g_state + ((size_t)(h * NCH_ + lt) << 12);
    for (int f = tid; f < 1024; f += 128) {
        int row = f >> 4, c4 = (f & 15) << 2;
        cvt_store<AT_NW>(KSs, row, c4,
            *reinterpret_cast<const float4*>(&qh[(size_t)(l0 + row) * DH_ + c4]));
        cvt_store<AT_NW>(Vt, row, c4,
            *reinterpret_cast<const float4*>(&Sg[row * 64 + c4]));
    }
    __syncthreads();

    uint32_t qa[8][4];
    {
        const uint32_t* Qu = reinterpret_cast<const uint32_t*>(KSs);
#pragma unroll
        for (int ko = 0; ko < 8; ko++) {
            qa[ko][0] = Qu[(wl + g) * AT_NW + ko * 8 + t4];
            qa[ko][1] = Qu[(wl + g + 8) * AT_NW + ko * 8 + t4];
            qa[ko][2] = Qu[(wl + g) * AT_NW + ko * 8 + t4 + 4];
            qa[ko][3] = Qu[(wl + g + 8) * AT_NW + ko * 8 + t4 + 4];
        }
    }
    const float cl0 = ca[l0 + wl + g] + lc;
    const float cl1 = ca[l0 + wl + g + 8] + lc;
    const float bc  = ca[l0];
    const float iw0 = __expf(cl0 - bc);
    const float iw1 = __expf(cl1 - bc);

    float accO[8][4];
#pragma unroll
    for (int nt = 0; nt < 8; nt++)
#pragma unroll
        for (int e = 0; e < 4; e++) accO[nt][e] = 0.f;

    {
        const uint32_t* Su = reinterpret_cast<const uint32_t*>(Vt);
#pragma unroll
        for (int ko = 0; ko < 8; ko++) {
            uint32_t b[8][2];
#pragma unroll
            for (int nt = 0; nt < 8; nt++) {
                b[nt][0] = Su[(nt * 8 + g) * AT_NW + ko * 8 + t4];
                b[nt][1] = Su[(nt * 8 + g) * AT_NW + ko * 8 + t4 + 4];
            }
#pragma unroll
            for (int nt = 0; nt < 8; nt++)
                MMA_TF32(accO[nt], qa[ko], b[nt]);
        }
#pragma unroll
        for (int nt = 0; nt < 8; nt++) {
            accO[nt][0] *= iw0;
            accO[nt][1] *= iw0;
            accO[nt][2] *= iw1;
            accO[nt][3] *= iw1;
        }
    }
    __syncthreads();

    for (int f = tid; f < 1024; f += 128) {
        int row = f >> 4, c4 = (f & 15) << 2;
        cvt_store<AT_NW>(KSs, row, c4,
            *reinterpret_cast<const float4*>(&kh[(size_t)(l0 + row) * DH_ + c4]));
    }
    {
        const int d0 = w * 16;
        int m = lane;
#pragma unroll
        for (int half = 0; half < 2; half++, m += 32) {
#pragma unroll
            for (int i = 0; i < 4; i++) {
                float4 x = *reinterpret_cast<const float4*>(
                    &vh[(size_t)(l0 + m) * DH_ + d0 + i * 4]);
                Vt[(d0 + i * 4 + 0) * AT_NW + m] = f2tf32f(x.x);
                Vt[(d0 + i * 4 + 1) * AT_NW + m] = f2tf32f(x.y);
                Vt[(d0 + i * 4 + 2) * AT_NW + m] = f2tf32f(x.z);
                Vt[(d0 + i * 4 + 3) * AT_NW + m] = f2tf32f(x.w);
            }
        }
    }
    __syncthreads();

    float sfr[8][4];
#pragma unroll
    for (int nt = 0; nt < 8; nt++)
#pragma unroll
        for (int e = 0; e < 4; e++) sfr[nt][e] = 0.f;

    {
        const uint32_t* Ku = reinterpret_cast<const uint32_t*>(KSs);
#pragma unroll
        for (int ko = 0; ko < 8; ko++) {
            uint32_t b[8][2];
#pragma unroll
            for (int nt = 0; nt < 8; nt++) {
                b[nt][0] = Ku[(nt * 8 + g) * AT_NW + ko * 8 + t4];
                b[nt][1] = Ku[(nt * 8 + g) * AT_NW + ko * 8 + t4 + 4];
            }
#pragma unroll
            for (int nt = 0; nt < 8; nt++)
                MMA_TF32(sfr[nt], qa[ko], b[nt]);
        }
    }

    const int gl0 = l0 + wl + g, gl1 = gl0 + 8;
#pragma unroll
    for (int nt = 0; nt < 8; nt++) {
        const int gm0 = l0 + nt * 8 + 2 * t4;
        const int gm1 = gm0 + 1;
        const float cm0 = ca[gm0], cm1 = ca[gm1];
        sfr[nt][0] *= (gm0 <= gl0) ? __expf(cl0 - cm0) : 0.f;
        sfr[nt][1] *= (gm1 <= gl0) ? __expf(cl0 - cm1) : 0.f;
        sfr[nt][2] *= (gm0 <= gl1) ? __expf(cl1 - cm0) : 0.f;
        sfr[nt][3] *= (gm1 <= gl1) ? __expf(cl1 - cm1) : 0.f;
    }
    __syncthreads();

#pragma unroll
    for (int nt = 0; nt < 8; nt++) {
        const int cc = nt * 8 + 2 * t4;
        *reinterpret_cast<float2*>(&KSs[(wl + g) * AT_NW + cc]) =
            make_float2(f2tf32f(sfr[nt][0]), f2tf32f(sfr[nt][1]));
        *reinterpret_cast<float2*>(&KSs[(wl + g + 8) * AT_NW + cc]) =
            make_float2(f2tf32f(sfr[nt][2]), f2tf32f(sfr[nt][3]));
    }
    __syncwarp();

    {
        const uint32_t* Su = reinterpret_cast<const uint32_t*>(KSs);
        const uint32_t* Vu = reinterpret_cast<const uint32_t*>(Vt);
#pragma unroll
        for (int ko = 0; ko < 8; ko++) {
            uint32_t a[4];
            a[0] = Su[(wl + g) * AT_NW + ko * 8 + t4];
            a[1] = Su[(wl + g + 8) * AT_NW + ko * 8 + t4];
            a[2] = Su[(wl + g) * AT_NW + ko * 8 + t4 + 4];
            a[3] = Su[(wl + g + 8) * AT_NW + ko * 8 + t4 + 4];
#pragma unroll
            for (int nt = 0; nt < 8; nt++) {
                uint32_t b[2];
                b[0] = Vu[(nt * 8 + g) * AT_NW + ko * 8 + t4];
                b[1] = Vu[(nt * 8 + g) * AT_NW + ko * 8 + t4 + 4];
                MMA_TF32(accO[nt], a, b);
            }
        }
    }

    float ss0 = 0.f, ss1 = 0.f;
#pragma unroll
    for (int nt = 0; nt < 8; nt++) {
        ss0 = fmaf(accO[nt][0], accO[nt][0], ss0);
        ss0 = fmaf(accO[nt][1], accO[nt][1], ss0);
        ss1 = fmaf(accO[nt][2], accO[nt][2], ss1);
        ss1 = fmaf(accO[nt][3], accO[nt][3], ss1);
    }
    ss0 += __shfl_xor_sync(0xffffffffu, ss0, 1);
    ss0 += __shfl_xor_sync(0xffffffffu, ss0, 2);
    ss1 += __shfl_xor_sync(0xffffffffu, ss1, 1);
    ss1 += __shfl_xor_sync(0xffffffffu, ss1, 2);
    const float r0 = rsqrtf(ss0 * (1.f / 64.f) + EPS_);
    const float r1 = rsqrtf(ss1 * (1.f / 64.f) + EPS_);

#pragma unroll
    for (int nt = 0; nt < 8; nt++) {
        const int dc = nt * 8 + 2 * t4;
        const float2 nw = *reinterpret_cast<const float2*>(&norm_w[dc]);
        const int col = h * DH_ + dc;
        *reinterpret_cast<float2*>(&g_attn[(size_t)(l0 + wl + g) * QS_ + col]) =
            make_float2(accO[nt][0] * r0 * nw.x, accO[nt][1] * r0 * nw.y);
        *reinterpret_cast<float2*>(&g_attn[(size_t)(l0 + wl + g + 8) * QS_ + col]) =
            make_float2(accO[nt][2] * r1 * nw.x, accO[nt][3] * r1 * nw.y);
    }
}

// ---------------- launch ---------------------------------------------------------
#define GEMM_SMEM_QKV ((128 + 96) * 36 * 2 * (int)sizeof(float))   // 64512 bytes
#define GEMM_SMEM_O   ((128 + 64) * 36 * 2 * (int)sizeof(float))   // 55296 bytes

extern "C" void kernel_launch(void* const* d_in, const int* in_sizes, int n_in,
                              void* d_out, int out_size)
{
    const float* hidden    = (const float*)d_in[0];
    // d_in[1] = attention_mask (causal triu) — structurally known, unused
    const float* qkv_w     = (const float*)d_in[2];
    const float* q_conv_w  = (const float*)d_in[3];
    const float* q_conv_b  = (const float*)d_in[4];
    const float* k_conv_w  = (const float*)d_in[5];
    const float* k_conv_b  = (const float*)d_in[6];
    const float* v_conv_w  = (const float*)d_in[7];
    const float* v_conv_b  = (const float*)d_in[8];
    const float* norm_w    = (const float*)d_in[9];
    const float* A_log     = (const float*)d_in[10];
    const float* dt_bias   = (const float*)d_in[11];
    const float* dt_proj_w = (const float*)d_in[12];
    const float* dt_proj_b = (const float*)d_in[13];
    const float* o_w       = (const float*)d_in[14];
    const float* order_c   = (const float*)d_in[15];
    float* out = (float*)d_out;

    static int attr_done = 0;
    if (!attr_done) {
        cudaFuncSetAttribute(mma_qkv_kernel, cudaFuncAttributeMaxDynamicSharedMemorySize, GEMM_SMEM_QKV);
        cudaFuncSetAttribute(mma_o_kernel,   cudaFuncAttributeMaxDynamicSharedMemorySize, GEMM_SMEM_O);
        attr_done = 1;
    }

    mma_qkv_kernel<<<dim3(T3_ / 96, L_ / 128), 256, GEMM_SMEM_QKV>>>(hidden, qkv_w);
    dt_kernel<<<L_ / 8, 512>>>(hidden, dt_proj_w, dt_proj_b, dt_bias, A_log);
    cumsum_kernel<<<H_, 256>>>();
    conv_kernel<<<(L_ * 256) / 256, 256>>>(q_conv_w, q_conv_b, k_conv_w, k_conv_b,
                                           v_conv_w, v_conv_b);
    kv_outer_kernel<<<dim3(NCH_ - 1, H_), 128>>>();
    state_scan_kernel<<<H_, 1024>>>();
    attn_mma_kernel<<<dim3(NCH_, H_), 128>>>(norm_w, order_c);
    mma_o_kernel<<<dim3(HID_ / 64, L_ / 128), 256, GEMM_SMEM_O>>>(o_w, out);
}

// round 10
// speedup vs baseline: 3.7343x; 1.0288x over previous
#include <cuda_runtime.h>
#include <stdint.h>
#include <math.h>

#define L_    2048
#define HID_  1024
#define H_    16
#define DH_   64
#define QS_   1024
#define T3_   3072
#define NCH_  32          // chunks of 64
#define EPS_  1.1920929e-07f

// ---------------- scratch (device globals; no allocation allowed) ----------------
__device__ float g_qkv[L_ * T3_];          // (L, 3072)
__device__ float g_dt[H_ * L_];
__device__ float g_Adec[H_ * L_];
__device__ float g_ca[H_ * L_];            // cumsum of A per head
__device__ float g_attn[L_ * QS_];         // (L, H*DH) post-RMSNorm
__device__ float g_M[H_ * NCH_ * DH_ * DH_];      // per-chunk decayed outer products [e][d]
__device__ float g_state[H_ * NCH_ * DH_ * DH_];  // scanned states [e][d]

// =================================================================================
// tf32 mma.sync helpers
// =================================================================================
#define MMA_TF32(D, Ar, Br)                                                        \
    asm volatile("mma.sync.aligned.m16n8k8.row.col.f32.tf32.tf32.f32 "             \
                 "{%0,%1,%2,%3}, {%4,%5,%6,%7}, {%8,%9}, {%0,%1,%2,%3};"           \
                 : "+f"((D)[0]), "+f"((D)[1]), "+f"((D)[2]), "+f"((D)[3])          \
                 : "r"((Ar)[0]), "r"((Ar)[1]), "r"((Ar)[2]), "r"((Ar)[3]),         \
                   "r"((Br)[0]), "r"((Br)[1]))

__device__ __forceinline__ uint32_t f2tf32(float x) {
    uint32_t u;
    asm("cvt.rna.tf32.f32 %0, %1;" : "=r"(u) : "f"(x));
    return u;
}
__device__ __forceinline__ float f2tf32f(float x) { return __uint_as_float(f2tf32(x)); }

template <int STRIDE>
__device__ __forceinline__ void cvt_store(float* dst, int row, int cg, float4 x) {
    float4 y;
    y.x = f2tf32f(x.x);
    y.y = f2tf32f(x.y);
    y.z = f2tf32f(x.z);
    y.w = f2tf32f(x.w);
    *reinterpret_cast<float4*>(&dst[row * STRIDE + cg]) = y;
}

// K=2 causal depthwise conv on a float4 channel group: prev*w0 + cur*w1 + b
__device__ __forceinline__ float4 conv4(float4 cur, float4 prev,
                                        float4 wa, float4 wb, float4 bb) {
    float4 o;
    o.x = fmaf(cur.x, wa.y, fmaf(prev.x, wa.x, bb.x));
    o.y = fmaf(cur.y, wa.w, fmaf(prev.y, wa.z, bb.y));
    o.z = fmaf(cur.z, wb.y, fmaf(prev.z, wb.x, bb.z));
    o.w = fmaf(cur.w, wb.w, fmaf(prev.w, wb.z, bb.w));
    return o;
}

// =================================================================================
// TN GEMM on tensor pipe: CTA tile 128 x NT, K-step 32, double-buffered dyn smem.
// 256 threads = 8 warps (4m x 2n), warp tile 32 x NT/2.
// =================================================================================
template <int M, int N, int K, int NT>
__device__ __forceinline__ void mma_gemm_body(const float* __restrict__ A,
                                              const float* __restrict__ B,
                                              float* __restrict__ C)
{
    constexpr int NTN = NT / 16;
    constexpr int BNV = NT / 32;
    constexpr int GSA = 128 * 36;
    constexpr int GSB = NT * 36;
    constexpr int SS  = GSA + GSB;

    extern __shared__ __align__(16) float smem_g[];

    const int tid  = threadIdx.x;
    const int lane = tid & 31;
    const int wid  = tid >> 5;
    const int g    = lane >> 2;
    const int t4   = lane & 3;
    const int m0   = blockIdx.y * 128;
    const int n0   = blockIdx.x * NT;
    const int wm   = (wid >> 1) * 32;
    const int wn   = (wid & 1) * (NT / 2);

    int ar[4], ac[4];
#pragma unroll
    for (int r = 0; r < 4; r++) {
        const int v = tid + 256 * r;
        ar[r] = v >> 3;
        ac[r] = (v & 7) << 2;
    }
    int br_[BNV], bc_[BNV];
#pragma unroll
    for (int r = 0; r < BNV; r++) {
        const int v = tid + 256 * r;
        br_[r] = v >> 3;
        bc_[r] = (v & 7) << 2;
    }

    float acc[2][NTN][4];
#pragma unroll
    for (int mt = 0; mt < 2; mt++)
#pragma unroll
        for (int nt = 0; nt < NTN; nt++)
#pragma unroll
            for (int e = 0; e < 4; e++) acc[mt][nt][e] = 0.f;

#pragma unroll
    for (int r = 0; r < 4; r++)
        cvt_store<36>(smem_g, ar[r], ac[r],
            *reinterpret_cast<const float4*>(&A[(size_t)(m0 + ar[r]) * K + ac[r]]));
#pragma unroll
    for (int r = 0; r < BNV; r++)
        cvt_store<36>(smem_g + GSA, br_[r], bc_[r],
            *reinterpret_cast<const float4*>(&B[(size_t)(n0 + br_[r]) * K + bc_[r]]));
    __syncthreads();

    int buf = 0;
    for (int k0 = 0; k0 < K; k0 += 32) {
        const bool has_next = (k0 + 32) < K;
        const int kn = k0 + 32;
        const uint32_t* Au = reinterpret_cast<const uint32_t*>(smem_g + buf * SS);
        const uint32_t* Bu = reinterpret_cast<const uint32_t*>(smem_g + buf * SS + GSA);
        float* Asn = smem_g + (buf ^ 1) * SS;
        float* Bsn = smem_g + (buf ^ 1) * SS + GSA;

#pragma unroll
        for (int half = 0; half < 2; half++) {
            const int b_lo = (BNV * half) / 2;
            const int b_hi = (BNV * (half + 1)) / 2;

            float4 pa[2], pb[2];
            if (has_next) {
#pragma unroll
                for (int r = 0; r < 2; r++) {
                    const int i = half * 2 + r;
                    pa[r] = *reinterpret_cast<const float4*>(&A[(size_t)(m0 + ar[i]) * K + kn + ac[i]]);
                }
#pragma unroll
                for (int r = b_lo; r < b_hi; r++)
                    pb[r - b_lo] = *reinterpret_cast<const float4*>(&B[(size_t)(n0 + br_[r]) * K + kn + bc_[r]]);
            }

#pragma unroll
            for (int s = 0; s < 2; s++) {
                const int ks = half * 16 + s * 8;
                uint32_t a[2][4];
#pragma unroll
                for (int mt = 0; mt < 2; mt++) {
                    const int r = wm + mt * 16 + g;
                    a[mt][0] = Au[r * 36 + ks + t4];
                    a[mt][1] = Au[(r + 8) * 36 + ks + t4];
                    a[mt][2] = Au[r * 36 + ks + t4 + 4];
                    a[mt][3] = Au[(r + 8) * 36 + ks + t4 + 4];
                }
#pragma unroll
                for (int grp = 0; grp < NTN / 2; grp++) {
                    uint32_t b[2][2];
#pragma unroll
                    for (int q = 0; q < 2; q++) {
                        const int r = wn + (grp * 2 + q) * 8 + g;
                        b[q][0] = Bu[r * 36 + ks + t4];
                        b[q][1] = Bu[r * 36 + ks + t4 + 4];
                    }
#pragma unroll
                    for (int mt = 0; mt < 2; mt++)
#pragma unroll
                        for (int q = 0; q < 2; q++)
                            MMA_TF32(acc[mt][grp * 2 + q], a[mt], b[q]);
                }
            }

            if (has_next) {
#pragma unroll
                for (int r = 0; r < 2; r++) {
                    const int i = half * 2 + r;
                    cvt_store<36>(Asn, ar[i], ac[i], pa[r]);
                }
#pragma unroll
                for (int r = b_lo; r < b_hi; r++)
                    cvt_store<36>(Bsn, br_[r], bc_[r], pb[r - b_lo]);
            }
        }

        if (has_next) {
            __syncthreads();
            buf ^= 1;
        }
    }

#pragma unroll
    for (int mt = 0; mt < 2; mt++) {
#pragma unroll
        for (int nt = 0; nt < NTN; nt++) {
            const int row = m0 + wm + mt * 16 + g;
            const int col = n0 + wn + nt * 8 + t4 * 2;
            *reinterpret_cast<float2*>(&C[(size_t)row * N + col]) =
                make_float2(acc[mt][nt][0], acc[mt][nt][1]);
            *reinterpret_cast<float2*>(&C[(size_t)(row + 8) * N + col]) =
                make_float2(acc[mt][nt][2], acc[mt][nt][3]);
        }
    }
}

__global__ __launch_bounds__(256, 2) void mma_qkv_kernel(const float* __restrict__ X,
                                                         const float* __restrict__ W)
{
    mma_gemm_body<L_, T3_, HID_, 96>(X, W, g_qkv);
}

__global__ __launch_bounds__(256, 2) void mma_o_kernel(const float* __restrict__ W,
                                                       float* __restrict__ out)
{
    mma_gemm_body<L_, HID_, QS_, 64>(g_attn, W, out);
}

// ---------------- dt = softplus(X @ Wdt^T + b + dt_bias); A = -exp(A_log)*dt -----
__global__ __launch_bounds__(512) void dt_kernel(const float* __restrict__ X,
                                                 const float* __restrict__ W,
                                                 const float* __restrict__ b,
                                                 const float* __restrict__ dt_bias,
                                                 const float* __restrict__ A_log)
{
    const int l0 = blockIdx.x * 8;
    const int warp = threadIdx.x >> 5;   // head
    const int lane = threadIdx.x & 31;
    const float* w = W + (size_t)warp * HID_;

    float wreg[32];
#pragma unroll
    for (int j = 0; j < 32; j++) wreg[j] = w[lane + 32 * j];

    const float bb = b[warp] + dt_bias[warp];
    const float nA = -expf(A_log[warp]);

    for (int r = 0; r < 8; r++) {
        const int l = l0 + r;
        const float* x = X + (size_t)l * HID_;
        float s = 0.f;
#pragma unroll
        for (int j = 0; j < 32; j++) s = fmaf(x[lane + 32 * j], wreg[j], s);
#pragma unroll
        for (int o = 16; o; o >>= 1) s += __shfl_xor_sync(0xffffffffu, s, o);
        if (lane == 0) {
            float xv = s + bb;
            float dt = (xv > 20.f) ? xv : log1pf(expf(xv));
            g_dt[warp * L_ + l]   = dt;
            g_Adec[warp * L_ + l] = nA * dt;
        }
    }
}

// ---------------- per-head inclusive cumsum over L -------------------------------
__global__ __launch_bounds__(256) void cumsum_kernel()
{
    const int h = blockIdx.x;
    __shared__ float wsum[8];
    __shared__ float carry_s;
    const int tid = threadIdx.x, lane = tid & 31, warp = tid >> 5;
    if (tid == 0) carry_s = 0.f;
    __syncthreads();
    for (int base = 0; base < L_; base += 256) {
        float x = g_Adec[h * L_ + base + tid];
#pragma unroll
        for (int o = 1; o < 32; o <<= 1) {
            float t = __shfl_up_sync(0xffffffffu, x, o);
            if (lane >= o) x += t;
        }
        if (lane == 31) wsum[warp] = x;
        __syncthreads();
        if (tid < 8) {
            float w = wsum[tid];
#pragma unroll
            for (int o = 1; o < 8; o <<= 1) {
                float t = __shfl_up_sync(0xffu, w, o);
                if (tid >= o) w += t;
            }
            wsum[tid] = w;
        }
        __syncthreads();
        float pre = (warp > 0 ? wsum[warp - 1] : 0.f) + carry_s;
        float outv = x + pre;
        g_ca[h * L_ + base + tid] = outv;
        __syncthreads();
        if (tid == 255) carry_s = outv;
        __syncthreads();
    }
}

// =================================================================================
// Chunked linear attention — conv fused into consumers (no g_q/g_k/g_v round-trip)
// =================================================================================
#define AT_NW 68

// ---- Phase A: M'[e][d] = sum_m v[m,e]*k'[m,d], conv applied inline --------------
__global__ __launch_bounds__(128) void kv_outer_kernel(const float* __restrict__ kcw,
                                                       const float* __restrict__ kcb,
                                                       const float* __restrict__ vcw,
                                                       const float* __restrict__ vcb)
{
    __shared__ __align__(16) float Kt[64 * AT_NW];   // [d][m]
    __shared__ __align__(16) float Vt2[64 * AT_NW];  // [e][m]

    const int c = blockIdx.x, h = blockIdx.y;
    const int m0 = c * 64;
    const int tid = threadIdx.x, lane = tid & 31, w = tid >> 5;
    const int g = lane >> 2, t4 = lane & 3;
    const int wl = w * 16;
    const float* ca = g_ca + h * L_;
    const float bnext = ca[(c + 1) * 64];
    const int d0 = w * 16;
    const float4 z = make_float4(0.f, 0.f, 0.f, 0.f);

#pragma unroll
    for (int i = 0; i < 4; i++) {
        const int ch = h * 64 + d0 + i * 4;            // global channel in [0,1024)
        const float4 kwa = *reinterpret_cast<const float4*>(&kcw[2 * ch]);
        const float4 kwb = *reinterpret_cast<const float4*>(&kcw[2 * ch + 4]);
        const float4 kbb = *reinterpret_cast<const float4*>(&kcb[ch]);
        const float4 vwa = *reinterpret_cast<const float4*>(&vcw[2 * ch]);
        const float4 vwb = *reinterpret_cast<const float4*>(&vcw[2 * ch + 4]);
        const float4 vbb = *reinterpret_cast<const float4*>(&vcb[ch]);

        int m = lane;
#pragma unroll
        for (int half = 0; half < 2; half++, m += 32) {
            const int gm = m0 + m;
            const float wm = __expf(bnext - ca[gm]);
            const float dtv = g_dt[h * L_ + gm];
            const float* rowp  = g_qkv + (size_t)gm * T3_;
            const float* prowp = g_qkv + (size_t)(gm - 1) * T3_;
            const bool hasp = (gm > 0);

            float4 kc4 = *reinterpret_cast<const float4*>(&rowp[QS_ + ch]);
            float4 kp4 = hasp ? *reinterpret_cast<const float4*>(&prowp[QS_ + ch]) : z;
            float4 vc4 = *reinterpret_cast<const float4*>(&rowp[2 * QS_ + ch]);
            float4 vp4 = hasp ? *reinterpret_cast<const float4*>(&prowp[2 * QS_ + ch]) : z;

            float4 kx = conv4(kc4, kp4, kwa, kwb, kbb);
            float4 vx = conv4(vc4, vp4, vwa, vwb, vbb);
            vx.x *= dtv; vx.y *= dtv; vx.z *= dtv; vx.w *= dtv;

            Kt[(d0 + i * 4 + 0) * AT_NW + m] = f2tf32f(kx.x * wm);
            Kt[(d0 + i * 4 + 1) * AT_NW + m] = f2tf32f(kx.y * wm);
            Kt[(d0 + i * 4 + 2) * AT_NW + m] = f2tf32f(kx.z * wm);
            Kt[(d0 + i * 4 + 3) * AT_NW + m] = f2tf32f(kx.w * wm);
            Vt2[(d0 + i * 4 + 0) * AT_NW + m] = f2tf32f(vx.x);
            Vt2[(d0 + i * 4 + 1) * AT_NW + m] = f2tf32f(vx.y);
            Vt2[(d0 + i * 4 + 2) * AT_NW + m] = f2tf32f(vx.z);
            Vt2[(d0 + i * 4 + 3) * AT_NW + m] = f2tf32f(vx.w);
        }
    }
    __syncthreads();

    float acc[8][4];
#pragma unroll
    for (int nt = 0; nt < 8; nt++)
#pragma unroll
        for (int e = 0; e < 4; e++) acc[nt][e] = 0.f;

    const uint32_t* Vu = reinterpret_cast<const uint32_t*>(Vt2);
    const uint32_t* Ku = reinterpret_cast<const uint32_t*>(Kt);
#pragma unroll
    for (int ko = 0; ko < 8; ko++) {
        uint32_t a[4];
        a[0] = Vu[(wl + g) * AT_NW + ko * 8 + t4];
        a[1] = Vu[(wl + g + 8) * AT_NW + ko * 8 + t4];
        a[2] = Vu[(wl + g) * AT_NW + ko * 8 + t4 + 4];
        a[3] = Vu[(wl + g + 8) * AT_NW + ko * 8 + t4 + 4];
#pragma unroll
        for (int nt = 0; nt < 8; nt++) {
            uint32_t b[2];
            b[0] = Ku[(nt * 8 + g) * AT_NW + ko * 8 + t4];
            b[1] = Ku[(nt * 8 + g) * AT_NW + ko * 8 + t4 + 4];
            MMA_TF32(acc[nt], a, b);
        }
    }

    float* Md = g_M + ((size_t)(h * NCH_ + c) << 12);
#pragma unroll
    for (int nt = 0; nt < 8; nt++) {
        const int dc = nt * 8 + 2 * t4;
        *reinterpret_cast<float2*>(&Md[(wl + g) * 64 + dc])     = make_float2(acc[nt][0], acc[nt][1]);
        *reinterpret_cast<float2*>(&Md[(wl + g + 8) * 64 + dc]) = make_float2(acc[nt][2], acc[nt][3]);
    }
}

// ---- Phase B: per-head state scan, depth-2 register prefetch. grid H, 1024 thr --
__global__ __launch_bounds__(1024) void state_scan_kernel()
{
    const int h = blockIdx.x, t = threadIdx.x;
    __shared__ float decs[NCH_];
    if (t < NCH_) {
        const float* ca = g_ca + h * L_;
        decs[t] = (t < NCH_ - 1) ? __expf(ca[(t + 1) * 64] - ca[t * 64]) : 0.f;
    }
    __syncthreads();

    const float* Mbase = g_M + ((size_t)h * NCH_ << 12);
    float* Sbase = g_state + ((size_t)h * NCH_ << 12);
    const int off = t * 4;

    float4 st = make_float4(0.f, 0.f, 0.f, 0.f);
    float4 mbuf0 = *reinterpret_cast<const float4*>(&Mbase[off]);
    float4 mbuf1 = *reinterpret_cast<const float4*>(&Mbase[(1 << 12) + off]);

    for (int c = 0; c < NCH_; c++) {
        *reinterpret_cast<float4*>(&Sbase[((size_t)c << 12) + off]) = st;
        if (c < NCH_ - 1) {
            const float dec = decs[c];
            st.x = fmaf(st.x, dec, mbuf0.x);
            st.y = fmaf(st.y, dec, mbuf0.y);
            st.z = fmaf(st.z, dec, mbuf0.z);
            st.w = fmaf(st.w, dec, mbuf0.w);
            mbuf0 = mbuf1;
            if (c + 2 < NCH_)
                mbuf1 = *reinterpret_cast<const float4*>(&Mbase[((size_t)(c + 2) << 12) + off]);
        }
    }
}

// ---- Phase C: diagonal tile (intra) + q.State (inter), conv fused, RMSNorm ------
__global__ __launch_bounds__(128) void attn_mma_kernel(const float* __restrict__ norm_w,
                                                       const float* __restrict__ order_coeff,
                                                       const float* __restrict__ qcw,
                                                       const float* __restrict__ qcb,
                                                       const float* __restrict__ kcw,
                                                       const float* __restrict__ kcb,
                                                       const float* __restrict__ vcw,
                                                       const float* __restrict__ vcb)
{
    __shared__ __align__(16) float KSs[64 * AT_NW];   // Q staging -> K -> weighted S
    __shared__ __align__(16) float Vt[64 * AT_NW];    // State' -> V^T

    const int h    = blockIdx.y;
    const int lt   = blockIdx.x;
    const int l0   = lt * 64;
    const int tid  = threadIdx.x;
    const int lane = tid & 31;
    const int w    = tid >> 5;
    const int g    = lane >> 2;
    const int t4   = lane & 3;
    const int wl   = w * 16;

    const float* ca = g_ca + h * L_;
    const float lc  = __logf(1.f / order_coeff[h]);
    const float4 z = make_float4(0.f, 0.f, 0.f, 0.f);

    // per-thread constant column group for the row-major staging loops
    const int c4i = (tid & 15) << 2;
    const int chq = h * 64 + c4i;

    // ---- stage Q (conv fused, tf32) into KSs; State' into Vt ----
    {
        const float4 qwa = *reinterpret_cast<const float4*>(&qcw[2 * chq]);
        const float4 qwb = *reinterpret_cast<const float4*>(&qcw[2 * chq + 4]);
        const float4 qbb = *reinterpret_cast<const float4*>(&qcb[chq]);
        const float* Sg = g_state + ((size_t)(h * NCH_ + lt) << 12);
#pragma unroll
        for (int it = 0; it < 8; it++) {
            const int row = (tid >> 4) + it * 8;
            const int gl = l0 + row;
            float4 qc4 = *reinterpret_cast<const float4*>(&g_qkv[(size_t)gl * T3_ + chq]);
            float4 qp4 = (gl > 0) ? *reinterpret_cast<const float4*>(&g_qkv[(size_t)(gl - 1) * T3_ + chq]) : z;
            cvt_store<AT_NW>(KSs, row, c4i, conv4(qc4, qp4, qwa, qwb, qbb));
            cvt_store<AT_NW>(Vt, row, c4i,
                *reinterpret_cast<const float4*>(&Sg[row * 64 + c4i]));
        }
    }
    __syncthreads();

    uint32_t qa[8][4];
    {
        const uint32_t* Qu = reinterpret_cast<const uint32_t*>(KSs);
#pragma unroll
        for (int ko = 0; ko < 8; ko++) {
            qa[ko][0] = Qu[(wl + g) * AT_NW + ko * 8 + t4];
            qa[ko][1] = Qu[(wl + g + 8) * AT_NW + ko * 8 + t4];
            qa[ko][2] = Qu[(wl + g) * AT_NW + ko * 8 + t4 + 4];
            qa[ko][3] = Qu[(wl + g + 8) * AT_NW + ko * 8 + t4 + 4];
        }
    }
    const float cl0 = ca[l0 + wl + g] + lc;
    const float cl1 = ca[l0 + wl + g + 8] + lc;
    const float bc  = ca[l0];
    const float iw0 = __expf(cl0 - bc);
    const float iw1 = __expf(cl1 - bc);

    float accO[8][4];
#pragma unroll
    for (int nt = 0; nt < 8; nt++)
#pragma unroll
        for (int e = 0; e < 4; e++) accO[nt][e] = 0.f;

    // inter: P = Q . State'^T
    {
        const uint32_t* Su = reinterpret_cast<const uint32_t*>(Vt);
#pragma unroll
        for (int ko = 0; ko < 8; ko++) {
            uint32_t b[8][2];
#pragma unroll
            for (int nt = 0; nt < 8; nt++) {
                b[nt][0] = Su[(nt * 8 + g) * AT_NW + ko * 8 + t4];
                b[nt][1] = Su[(nt * 8 + g) * AT_NW + ko * 8 + t4 + 4];
            }
#pragma unroll
            for (int nt = 0; nt < 8; nt++)
                MMA_TF32(accO[nt], qa[ko], b[nt]);
        }
#pragma unroll
        for (int nt = 0; nt < 8; nt++) {
            accO[nt][0] *= iw0;
            accO[nt][1] *= iw0;
            accO[nt][2] *= iw1;
            accO[nt][3] *= iw1;
        }
    }
    __syncthreads();

    // ---- load K (conv fused) into KSs row-major; V (conv fused, *dt) into Vt^T ----
    {
        const float4 kwa = *reinterpret_cast<const float4*>(&kcw[2 * chq]);
        const float4 kwb = *reinterpret_cast<const float4*>(&kcw[2 * chq + 4]);
        const float4 kbb = *reinterpret_cast<const float4*>(&kcb[chq]);
#pragma unroll
        for (int it = 0; it < 8; it++) {
            const int row = (tid >> 4) + it * 8;
            const int gl = l0 + row;
            float4 kc4 = *reinterpret_cast<const float4*>(&g_qkv[(size_t)gl * T3_ + QS_ + chq]);
            float4 kp4 = (gl > 0) ? *reinterpret_cast<const float4*>(&g_qkv[(size_t)(gl - 1) * T3_ + QS_ + chq]) : z;
            cvt_store<AT_NW>(KSs, row, c4i, conv4(kc4, kp4, kwa, kwb, kbb));
        }
    }
    {
        const int d0 = w * 16;
#pragma unroll
        for (int i = 0; i < 4; i++) {
            const int ch = h * 64 + d0 + i * 4;
            const float4 vwa = *reinterpret_cast<const float4*>(&vcw[2 * ch]);
            const float4 vwb = *reinterpret_cast<const float4*>(&vcw[2 * ch + 4]);
            const float4 vbb = *reinterpret_cast<const float4*>(&vcb[ch]);
            int m = lane;
#pragma unroll
            for (int half = 0; half < 2; half++, m += 32) {
                const int gm = l0 + m;
                const float dtv = g_dt[h * L_ + gm];
                float4 vc4 = *reinterpret_cast<const float4*>(&g_qkv[(size_t)gm * T3_ + 2 * QS_ + ch]);
                float4 vp4 = (gm > 0) ? *reinterpret_cast<const float4*>(&g_qkv[(size_t)(gm - 1) * T3_ + 2 * QS_ + ch]) : z;
                float4 vx = conv4(vc4, vp4, vwa, vwb, vbb);
                Vt[(d0 + i * 4 + 0) * AT_NW + m] = f2tf32f(vx.x * dtv);
                Vt[(d0 + i * 4 + 1) * AT_NW + m] = f2tf32f(vx.y * dtv);
                Vt[(d0 + i * 4 + 2) * AT_NW + m] = f2tf32f(vx.z * dtv);
                Vt[(d0 + i * 4 + 3) * AT_NW + m] = f2tf32f(vx.w * dtv);
            }
        }
    }
    __syncthreads();

    // S-phase: sfr = Q(16x64) . K^T(64x64)
    float sfr[8][4];
#pragma unroll
    for (int nt = 0; nt < 8; nt++)
#pragma unroll
        for (int e = 0; e < 4; e++) sfr[nt][e] = 0.f;

    {
        const uint32_t* Ku = reinterpret_cast<const uint32_t*>(KSs);
#pragma unroll
        for (int ko = 0; ko < 8; ko++) {
            uint32_t b[8][2];
#pragma unroll
            for (int nt = 0; nt < 8; nt++) {
                b[nt][0] = Ku[(nt * 8 + g) * AT_NW + ko * 8 + t4];
                b[nt][1] = Ku[(nt * 8 + g) * AT_NW + ko * 8 + t4 + 4];
            }
#pragma unroll
            for (int nt = 0; nt < 8; nt++)
                MMA_TF32(sfr[nt], qa[ko], b[nt]);
        }
    }

    const int gl0 = l0 + wl + g, gl1 = gl0 + 8;
#pragma unroll
    for (int nt = 0; nt < 8; nt++) {
        const int gm0 = l0 + nt * 8 + 2 * t4;
        const int gm1 = gm0 + 1;
        const float cm0 = ca[gm0], cm1 = ca[gm1];
        sfr[nt][0] *= (gm0 <= gl0) ? __expf(cl0 - cm0) : 0.f;
        sfr[nt][1] *= (gm1 <= gl0) ? __expf(cl0 - cm1) : 0.f;
        sfr[nt][2] *= (gm0 <= gl1) ? __expf(cl1 - cm0) : 0.f;
        sfr[nt][3] *= (gm1 <= gl1) ? __expf(cl1 - cm1) : 0.f;
    }
    __syncthreads();

#pragma unroll
    for (int nt = 0; nt < 8; nt++) {
        const int cc = nt * 8 + 2 * t4;
        *reinterpret_cast<float2*>(&KSs[(wl + g) * AT_NW + cc]) =
            make_float2(f2tf32f(sfr[nt][0]), f2tf32f(sfr[nt][1]));
        *reinterpret_cast<float2*>(&KSs[(wl + g + 8) * AT_NW + cc]) =
            make_float2(f2tf32f(sfr[nt][2]), f2tf32f(sfr[nt][3]));
    }
    __syncwarp();

    {
        const uint32_t* Su = reinterpret_cast<const uint32_t*>(KSs);
        const uint32_t* Vu = reinterpret_cast<const uint32_t*>(Vt);
#pragma unroll
        for (int ko = 0; ko < 8; ko++) {
            uint32_t a[4];
            a[0] = Su[(wl + g) * AT_NW + ko * 8 + t4];
            a[1] = Su[(wl + g + 8) * AT_NW + ko * 8 + t4];
            a[2] = Su[(wl + g) * AT_NW + ko * 8 + t4 + 4];
            a[3] = Su[(wl + g + 8) * AT_NW + ko * 8 + t4 + 4];
#pragma unroll
            for (int nt = 0; nt < 8; nt++) {
                uint32_t b[2];
                b[0] = Vu[(nt * 8 + g) * AT_NW + ko * 8 + t4];
                b[1] = Vu[(nt * 8 + g) * AT_NW + ko * 8 + t4 + 4];
                MMA_TF32(accO[nt], a, b);
            }
        }
    }

    float ss0 = 0.f, ss1 = 0.f;
#pragma unroll
    for (int nt = 0; nt < 8; nt++) {
        ss0 = fmaf(accO[nt][0], accO[nt][0], ss0);
        ss0 = fmaf(accO[nt][1], accO[nt][1], ss0);
        ss1 = fmaf(accO[nt][2], accO[nt][2], ss1);
        ss1 = fmaf(accO[nt][3], accO[nt][3], ss1);
    }
    ss0 += __shfl_xor_sync(0xffffffffu, ss0, 1);
    ss0 += __shfl_xor_sync(0xffffffffu, ss0, 2);
    ss1 += __shfl_xor_sync(0xffffffffu, ss1, 1);
    ss1 += __shfl_xor_sync(0xffffffffu, ss1, 2);
    const float r0 = rsqrtf(ss0 * (1.f / 64.f) + EPS_);
    const float r1 = rsqrtf(ss1 * (1.f / 64.f) + EPS_);

#pragma unroll
    for (int nt = 0; nt < 8; nt++) {
        const int dc = nt * 8 + 2 * t4;
        const float2 nw = *reinterpret_cast<const float2*>(&norm_w[dc]);
        const int col = h * DH_ + dc;
        *reinterpret_cast<float2*>(&g_attn[(size_t)(l0 + wl + g) * QS_ + col]) =
            make_float2(accO[nt][0] * r0 * nw.x, accO[nt][1] * r0 * nw.y);
        *reinterpret_cast<float2*>(&g_attn[(size_t)(l0 + wl + g + 8) * QS_ + col]) =
            make_float2(accO[nt][2] * r1 * nw.x, accO[nt][3] * r1 * nw.y);
    }
}

// ---------------- launch ---------------------------------------------------------
#define GEMM_SMEM_QKV ((128 + 96) * 36 * 2 * (int)sizeof(float))   // 64512 bytes
#define GEMM_SMEM_O   ((128 + 64) * 36 * 2 * (int)sizeof(float))   // 55296 bytes

extern "C" void kernel_launch(void* const* d_in, const int* in_sizes, int n_in,
                              void* d_out, int out_size)
{
    const float* hidden    = (const float*)d_in[0];
    // d_in[1] = attention_mask (causal triu) — structurally known, unused
    const float* qkv_w     = (const float*)d_in[2];
    const float* q_conv_w  = (const float*)d_in[3];
    const float* q_conv_b  = (const float*)d_in[4];
    const float* k_conv_w  = (const float*)d_in[5];
    const float* k_conv_b  = (const float*)d_in[6];
    const float* v_conv_w  = (const float*)d_in[7];
    const float* v_conv_b  = (const float*)d_in[8];
    const float* norm_w    = (const float*)d_in[9];
    const float* A_log     = (const float*)d_in[10];
    const float* dt_bias   = (const float*)d_in[11];
    const float* dt_proj_w = (const float*)d_in[12];
    const float* dt_proj_b = (const float*)d_in[13];
    const float* o_w       = (const float*)d_in[14];
    const float* order_c   = (const float*)d_in[15];
    float* out = (float*)d_out;

    static int attr_done = 0;
    if (!attr_done) {
        cudaFuncSetAttribute(mma_qkv_kernel, cudaFuncAttributeMaxDynamicSharedMemorySize, GEMM_SMEM_QKV);
        cudaFuncSetAttribute(mma_o_kernel,   cudaFuncAttributeMaxDynamicSharedMemorySize, GEMM_SMEM_O);
        attr_done = 1;
    }

    mma_qkv_kernel<<<dim3(T3_ / 96, L_ / 128), 256, GEMM_SMEM_QKV>>>(hidden, qkv_w);
    dt_kernel<<<L_ / 8, 512>>>(hidden, dt_proj_w, dt_proj_b, dt_bias, A_log);
    cumsum_kernel<<<H_, 256>>>();
    kv_outer_kernel<<<dim3(NCH_ - 1, H_), 128>>>(k_conv_w, k_conv_b, v_conv_w, v_conv_b);
    state_scan_kernel<<<H_, 1024>>>();
    attn_mma_kernel<<<dim3(NCH_, H_), 128>>>(norm_w, order_c,
                                             q_conv_w, q_conv_b, k_conv_w, k_conv_b,
                                             v_conv_w, v_conv_b);
    mma_o_kernel<<<dim3(HID_ / 64, L_ / 128), 256, GEMM_SMEM_O>>>(o_w, out);
}